// round 2
// baseline (speedup 1.0000x reference)
#include <cuda_runtime.h>
#include <math.h>

#define NB    64
#define DIMX  4096
#define HEADS 32
#define HDIM  192
#define RDIM  64
#define QLRK  1536
#define OLRK  512
#define GRP   8
#define BS    64
#define MAXB  64
#define LMAX  4096
#define TOPKK 1024
#define EPSI  1e-6f
#define NEGF  -1e30f
#define QDIM  (HEADS*HDIM)   /* 6144 */
#define SCALE_F 0.07216878364870323f  /* 192^-0.5 */

/* ------------------------------------------------------------------ */
/* scratch (device globals: allocation-free per harness rules)        */
/* ------------------------------------------------------------------ */
__device__ float g_qa[NB*QLRK];
__device__ float g_kv[NB*HDIM];
__device__ float g_q[NB*QDIM];
__device__ float g_logits[(size_t)NB*HEADS*LMAX];       /* 32 MB */
__device__ float g_tau[NB*HEADS];
__device__ float g_mrow[NB*HEADS];
__device__ float g_invden[NB*HEADS];
__device__ float g_opart[(size_t)8*NB*HEADS*HDIM];      /* 12.6 MB */
__device__ float g_o[NB*QDIM];
__device__ float g_lat[NB*GRP*OLRK];

/* ------------------------------------------------------------------ */
/* generic fp32 GEMM:  C[m,n] = sum_k A[m,k] * W[n,k],  M == 64       */
/* tile 64x64, K-chunk 16, 256 threads, 4x4 register tile             */
/* ------------------------------------------------------------------ */
#define GTK 16
__global__ void __launch_bounds__(256) k_gemm(
    const float* __restrict__ A, int lda, long long aGrpStride,
    const float* __restrict__ W, int ldw, long long wGrpStride,
    float* __restrict__ C, int ldc, long long cGrpStride,
    int K)
{
    int n0 = blockIdx.x * 64;
    int g  = blockIdx.z;
    A += (size_t)g * aGrpStride;
    W += (size_t)g * wGrpStride + (size_t)n0 * ldw;
    C += (size_t)g * cGrpStride + n0;

    __shared__ float As[GTK][68];  /* transposed: As[kk][m], 68 keeps 16B align */
    __shared__ float Ws[GTK][68];

    int tid  = threadIdx.x;
    int la_m = tid >> 2;           /* 0..63 */
    int la_k = (tid & 3) * 4;      /* 0,4,8,12 */
    int tx   = tid & 15;
    int ty   = tid >> 4;

    float acc[4][4];
#pragma unroll
    for (int i = 0; i < 4; i++)
#pragma unroll
        for (int j = 0; j < 4; j++) acc[i][j] = 0.f;

    for (int k0 = 0; k0 < K; k0 += GTK) {
        float4 av = *(const float4*)(A + (size_t)la_m * lda + k0 + la_k);
        float4 wv = *(const float4*)(W + (size_t)la_m * ldw + k0 + la_k);
        As[la_k+0][la_m] = av.x; As[la_k+1][la_m] = av.y;
        As[la_k+2][la_m] = av.z; As[la_k+3][la_m] = av.w;
        Ws[la_k+0][la_m] = wv.x; Ws[la_k+1][la_m] = wv.y;
        Ws[la_k+2][la_m] = wv.z; Ws[la_k+3][la_m] = wv.w;
        __syncthreads();
#pragma unroll
        for (int kk = 0; kk < GTK; kk++) {
            float4 a = *(const float4*)(&As[kk][ty*4]);
            float4 w = *(const float4*)(&Ws[kk][tx*4]);
            acc[0][0] += a.x*w.x; acc[0][1] += a.x*w.y; acc[0][2] += a.x*w.z; acc[0][3] += a.x*w.w;
            acc[1][0] += a.y*w.x; acc[1][1] += a.y*w.y; acc[1][2] += a.y*w.z; acc[1][3] += a.y*w.w;
            acc[2][0] += a.z*w.x; acc[2][1] += a.z*w.y; acc[2][2] += a.z*w.z; acc[2][3] += a.z*w.w;
            acc[3][0] += a.w*w.x; acc[3][1] += a.w*w.y; acc[3][2] += a.w*w.z; acc[3][3] += a.w*w.w;
        }
        __syncthreads();
    }
#pragma unroll
    for (int i = 0; i < 4; i++)
#pragma unroll
        for (int j = 0; j < 4; j++)
            C[(size_t)(ty*4+i)*ldc + tx*4 + j] = acc[i][j];
}

/* ------------------------------------------------------------------ */
/* RMS norm in place over rows of g_qa (cols = 1536)                  */
/* ------------------------------------------------------------------ */
__global__ void __launch_bounds__(256) k_rms_qa(float* __restrict__ a,
                                                const float* __restrict__ wt)
{
    __shared__ float red[256];
    int n = blockIdx.x, tid = threadIdx.x;
    float v[6]; float s = 0.f;
#pragma unroll
    for (int i = 0; i < 6; i++) {
        v[i] = a[(size_t)n*QLRK + tid + i*256];
        s += v[i]*v[i];
    }
    red[tid] = s; __syncthreads();
    for (int k = 128; k > 0; k >>= 1) { if (tid < k) red[tid] += red[tid+k]; __syncthreads(); }
    float scale = rsqrtf(red[0] / (float)QLRK + EPSI);
#pragma unroll
    for (int i = 0; i < 6; i++) {
        int c = tid + i*256;
        a[(size_t)n*QLRK + c] = v[i] * scale * wt[c];
    }
}

/* rope cos/sin: inv computed via double for accuracy */
__device__ __forceinline__ void rope_cs(int i, float pos, float& c, float& s)
{
    float inv = (float)exp(-(double)i * 0.28782313662425574); /* ln(1e4)/32 */
    float ang = pos * inv;
    double ad = (double)ang;
    c = (float)cos(ad); s = (float)sin(ad);
}

/* ------------------------------------------------------------------ */
/* kv row: rms + rope in place on g_kv                                */
/* ------------------------------------------------------------------ */
__global__ void k_kv_finish(float* __restrict__ kv, const float* __restrict__ wt,
                            const int* __restrict__ ctxl)
{
    __shared__ float srow[HDIM];
    __shared__ float rs[64];
    int n = blockIdx.x, tid = threadIdx.x;  /* 64 threads */
    float s = 0.f;
#pragma unroll
    for (int j = 0; j < 3; j++) {
        float v = kv[(size_t)n*HDIM + tid + j*64];
        srow[tid + j*64] = v; s += v*v;
    }
    rs[tid] = s; __syncthreads();
    for (int k = 32; k > 0; k >>= 1) { if (tid < k) rs[tid] += rs[tid+k]; __syncthreads(); }
    float scale = rsqrtf(rs[0] / (float)HDIM + EPSI);
#pragma unroll
    for (int j = 0; j < 3; j++) { int i = tid + j*64; srow[i] = srow[i]*scale*wt[i]; }
    __syncthreads();
    float pos = (float)(ctxl[n] - 1);
    if (tid < 32) {
        int i = tid;
        float x0 = srow[HDIM-RDIM + 2*i], x1 = srow[HDIM-RDIM + 2*i + 1];
        float c, sn; rope_cs(i, pos, c, sn);
        srow[HDIM-RDIM + 2*i]     = x0*c - x1*sn;
        srow[HDIM-RDIM + 2*i + 1] = x0*sn + x1*c;
    }
    __syncthreads();
#pragma unroll
    for (int j = 0; j < 3; j++) { int i = tid + j*64; kv[(size_t)n*HDIM + i] = srow[i]; }
}

/* ------------------------------------------------------------------ */
/* rope on q (last 64 dims of each head)                              */
/* ------------------------------------------------------------------ */
__global__ void __launch_bounds__(256) k_rope_q(float* __restrict__ q,
                                                const int* __restrict__ ctxl)
{
    int n = blockIdx.x, tid = threadIdx.x;
    float pos = (float)(ctxl[n] - 1);
#pragma unroll
    for (int k = 0; k < 4; k++) {
        int pi = tid + k*256;       /* 0..1023 */
        int h = pi >> 5, i = pi & 31;
        float* base = q + (size_t)n*QDIM + h*HDIM + (HDIM-RDIM) + 2*i;
        float x0 = base[0], x1 = base[1];
        float c, s; rope_cs(i, pos, c, s);
        base[0] = x0*c - x1*s;
        base[1] = x0*s + x1*c;
    }
}

/* ------------------------------------------------------------------ */
/* logits: one CTA per (block b, batch n); writes full g_logits row   */
/* (NEG for invalid). Fresh-kv override at position ctx-1.            */
/* ------------------------------------------------------------------ */
__global__ void __launch_bounds__(256) k_logits(
    const float* __restrict__ kvc, const int* __restrict__ bt,
    const int* __restrict__ ctxl, const float* __restrict__ q,
    const float* __restrict__ kvnew, float* __restrict__ logits)
{
    extern __shared__ float sm1[];
    int n = blockIdx.y, b = blockIdx.x;
    int ctx = ctxl[n];
    int base = b * BS;
    int tid = threadIdx.x;
    int w = tid >> 5, lane = tid & 31;

    if (base >= ctx) {
#pragma unroll
        for (int j = 0; j < 4; j++) {
            int h = w + 8*j;
            float* dst = logits + ((size_t)(n*HEADS + h))*LMAX + base;
            dst[lane] = NEGF; dst[lane+32] = NEGF;
        }
        return;
    }
    float* Qs  = sm1;            /* 6144 floats: [h*192+d] */
    float* KVs = sm1 + QDIM;     /* 64*193 floats          */

    const float4* qsrc = (const float4*)(q + (size_t)n*QDIM);
#pragma unroll
    for (int i = 0; i < 6; i++) {
        int idx = tid + i*256;
        float4 v = qsrc[idx];
        Qs[idx*4+0]=v.x; Qs[idx*4+1]=v.y; Qs[idx*4+2]=v.z; Qs[idx*4+3]=v.w;
    }
    int blk = bt[n*MAXB + b];
    {
        int row = tid >> 2, qp = tid & 3;
        int lg = base + row;
        const float* src = (lg == ctx-1) ? (kvnew + (size_t)n*HDIM)
                                         : (kvc + ((size_t)blk*BS + row)*HDIM);
        const float4* s4 = (const float4*)src;
#pragma unroll
        for (int j = 0; j < 12; j++) {
            int d4 = qp*12 + j;
            float4 v = s4[d4];
            float* dst = KVs + row*193 + d4*4;
            dst[0]=v.x; dst[1]=v.y; dst[2]=v.z; dst[3]=v.w;
        }
    }
    __syncthreads();

    float acc[4][2];
#pragma unroll
    for (int j = 0; j < 4; j++) { acc[j][0]=0.f; acc[j][1]=0.f; }
#pragma unroll 4
    for (int d = 0; d < HDIM; d++) {
        float k0 = KVs[lane*193 + d];
        float k1 = KVs[(lane+32)*193 + d];
#pragma unroll
        for (int j = 0; j < 4; j++) {
            float qv = Qs[(w + 8*j)*HDIM + d];
            acc[j][0] += qv*k0;
            acc[j][1] += qv*k1;
        }
    }
    bool v0 = (base + lane)      < ctx;
    bool v1 = (base + lane + 32) < ctx;
#pragma unroll
    for (int j = 0; j < 4; j++) {
        int h = w + 8*j;
        float* dst = logits + ((size_t)(n*HEADS + h))*LMAX + base;
        dst[lane]    = v0 ? acc[j][0]*SCALE_F : NEGF;
        dst[lane+32] = v1 ? acc[j][1]*SCALE_F : NEGF;
    }
}

/* ------------------------------------------------------------------ */
/* exact top-k threshold via 4-pass radix select on orderable bits;   */
/* also computes m = max(rowmax, sink) and 1/denom                    */
/* ------------------------------------------------------------------ */
__device__ __forceinline__ unsigned f2ord(float f) {
    unsigned b = __float_as_uint(f);
    return (b & 0x80000000u) ? ~b : (b | 0x80000000u);
}
__device__ __forceinline__ float ord2f(unsigned u) {
    return (u & 0x80000000u) ? __uint_as_float(u ^ 0x80000000u)
                             : __uint_as_float(~u);
}

__global__ void __launch_bounds__(256) k_select(
    const float* __restrict__ logits, const float* __restrict__ sink,
    float* __restrict__ tau_o, float* __restrict__ m_o, float* __restrict__ iv_o)
{
    __shared__ unsigned keys[LMAX];
    __shared__ unsigned hist[256];
    __shared__ unsigned rmax[256];
    __shared__ float    red[256];
    __shared__ unsigned s_prefix;
    __shared__ int      s_k;

    int rowid = blockIdx.x;       /* n*32 + h */
    int h = rowid & 31;
    int tid = threadIdx.x;
    const float* src = logits + (size_t)rowid * LMAX;

    unsigned um = 0u;
#pragma unroll
    for (int i = 0; i < 16; i++) {
        int idx = tid + i*256;
        unsigned u = f2ord(src[idx]);
        keys[idx] = u;
        um = max(um, u);
    }
    rmax[tid] = um; __syncthreads();
    for (int k = 128; k > 0; k >>= 1) { if (tid < k) rmax[tid] = max(rmax[tid], rmax[tid+k]); __syncthreads(); }
    if (tid == 0) { s_prefix = 0u; s_k = TOPKK; }
    __syncthreads();

    for (int shift = 24; shift >= 0; shift -= 8) {
        hist[tid] = 0u;
        __syncthreads();
        unsigned pref = s_prefix;
        unsigned himask = (shift == 24) ? 0u : (0xFFFFFFFFu << (shift + 8));
#pragma unroll
        for (int i = 0; i < 16; i++) {
            unsigned u = keys[tid + i*256];
            if ((u & himask) == pref) atomicAdd(&hist[(u >> shift) & 255u], 1u);
        }
        __syncthreads();
        if (tid == 0) {
            int kk = s_k; unsigned cum = 0u; int bin = 255;
            for (; bin > 0; bin--) {
                unsigned c = hist[bin];
                if (cum + c >= (unsigned)kk) break;
                cum += c;
            }
            s_prefix = pref | ((unsigned)bin << shift);
            s_k = kk - (int)cum;
        }
        __syncthreads();
    }
    unsigned tu = s_prefix;
    float tauf = ord2f(tu);
    float maxf = ord2f(rmax[0]);
    float snk  = sink[h];
    float m    = fmaxf(maxf, snk);

    float local = 0.f;
#pragma unroll
    for (int i = 0; i < 16; i++) {
        unsigned u = keys[tid + i*256];
        if (u >= tu) local += expf(ord2f(u) - m);
    }
    red[tid] = local; __syncthreads();
    for (int k = 128; k > 0; k >>= 1) { if (tid < k) red[tid] += red[tid+k]; __syncthreads(); }
    if (tid == 0) {
        float denom = red[0] + expf(snk - m);
        tau_o[rowid] = tauf; m_o[rowid] = m; iv_o[rowid] = 1.f / denom;
    }
}

/* ------------------------------------------------------------------ */
/* o accumulation: CTA per (chunk of 8 blocks, n); partials to gmem   */
/* ------------------------------------------------------------------ */
__global__ void __launch_bounds__(256) k_accum(
    const float* __restrict__ kvc, const int* __restrict__ bt,
    const int* __restrict__ ctxl, const float* __restrict__ kvnew,
    const float* __restrict__ logits, const float* __restrict__ tau_i,
    const float* __restrict__ m_i, const float* __restrict__ iv_i,
    float* __restrict__ opart)
{
    extern __shared__ float sm2[];
    float* KVs = sm2;                 /* 64*192 */
    float* ps  = sm2 + BS*HDIM;       /* 32*64  */

    int chunk = blockIdx.x, n = blockIdx.y;
    int ctx = ctxl[n];
    int tid = threadIdx.x;
    int w = tid >> 5, lane = tid & 31;

    float acc[4][6];
#pragma unroll
    for (int j = 0; j < 4; j++)
#pragma unroll
        for (int i = 0; i < 6; i++) acc[j][i] = 0.f;

    int ph = tid >> 3, pl0 = (tid & 7) * 8;
    float ptau = tau_i[n*HEADS + ph];
    float pm   = m_i[n*HEADS + ph];
    float piv  = iv_i[n*HEADS + ph];

    for (int b8 = 0; b8 < 8; b8++) {
        int b = chunk*8 + b8;
        int base = b * BS;
        if (base >= ctx) break;
        int blk = bt[n*MAXB + b];
        {
            int row = tid >> 2, qp = tid & 3;
            int lg = base + row;
            const float* src = (lg == ctx-1) ? (kvnew + (size_t)n*HDIM)
                                             : (kvc + ((size_t)blk*BS + row)*HDIM);
            const float4* s4 = (const float4*)src;
#pragma unroll
            for (int j = 0; j < 12; j++) {
                int d4 = qp*12 + j;
                float4 v = s4[d4];
                float* dst = KVs + row*HDIM + d4*4;
                dst[0]=v.x; dst[1]=v.y; dst[2]=v.z; dst[3]=v.w;
            }
        }
        const float* lsrc = logits + ((size_t)(n*HEADS + ph))*LMAX + base + pl0;
#pragma unroll
        for (int j = 0; j < 8; j++) {
            float lg = lsrc[j];
            float p = (lg >= ptau) ? (expf(lg - pm) * piv) : 0.f;
            ps[ph*BS + pl0 + j] = p;
        }
        __syncthreads();
#pragma unroll 2
        for (int l = 0; l < BS; l++) {
            float pj[4];
#pragma unroll
            for (int j = 0; j < 4; j++) pj[j] = ps[(w + 8*j)*BS + l];
#pragma unroll
            for (int i = 0; i < 6; i++) {
                float kvv = KVs[l*HDIM + lane + 32*i];
#pragma unroll
                for (int j = 0; j < 4; j++) acc[j][i] += pj[j]*kvv;
            }
        }
        __syncthreads();
    }
#pragma unroll
    for (int j = 0; j < 4; j++) {
        int h = w + 8*j;
        float* dst = opart + (((size_t)chunk*NB + n)*HEADS + h)*HDIM;
#pragma unroll
        for (int i = 0; i < 6; i++) dst[lane + 32*i] = acc[j][i];
    }
}

__global__ void k_reduce_o(const float* __restrict__ opart, float* __restrict__ o)
{
    int idx = blockIdx.x*256 + threadIdx.x;   /* < 64*6144 */
    float s = 0.f;
#pragma unroll
    for (int c = 0; c < 8; c++) s += opart[(size_t)c*NB*QDIM + idx];
    o[idx] = s;
}

/* ------------------------------------------------------------------ */
/* host launcher                                                      */
/* ------------------------------------------------------------------ */
extern "C" void kernel_launch(void* const* d_in, const int* in_sizes, int n_in,
                              void* d_out, int out_size)
{
    const float* x    = (const float*)d_in[0];
    const float* kvc  = (const float*)d_in[1];
    const int*   bt   = (const int*)  d_in[2];
    const int*   ctxl = (const int*)  d_in[3];
    /* d_in[4] slot_mapping unused (override at pos ctx-1 instead)    */
    const float* wqa  = (const float*)d_in[5];
    const float* qnw  = (const float*)d_in[6];
    const float* wqb  = (const float*)d_in[7];
    const float* wkv  = (const float*)d_in[8];
    const float* kvnw = (const float*)d_in[9];
    const float* woa  = (const float*)d_in[10];
    const float* wob  = (const float*)d_in[11];
    const float* sink = (const float*)d_in[12];
    float* out = (float*)d_out;

    float *qa, *kv, *qq, *lg, *tau, *mr, *iv, *op, *oo, *lat;
    cudaGetSymbolAddress((void**)&qa,  g_qa);
    cudaGetSymbolAddress((void**)&kv,  g_kv);
    cudaGetSymbolAddress((void**)&qq,  g_q);
    cudaGetSymbolAddress((void**)&lg,  g_logits);
    cudaGetSymbolAddress((void**)&tau, g_tau);
    cudaGetSymbolAddress((void**)&mr,  g_mrow);
    cudaGetSymbolAddress((void**)&iv,  g_invden);
    cudaGetSymbolAddress((void**)&op,  g_opart);
    cudaGetSymbolAddress((void**)&oo,  g_o);
    cudaGetSymbolAddress((void**)&lat, g_lat);

    const int SMEM_LOGITS = (QDIM + 64*193) * 4;        /* 73984 B */
    const int SMEM_ACCUM  = (BS*HDIM + HEADS*BS) * 4;   /* 57344 B */
    cudaFuncSetAttribute(k_logits, cudaFuncAttributeMaxDynamicSharedMemorySize, SMEM_LOGITS);
    cudaFuncSetAttribute(k_accum,  cudaFuncAttributeMaxDynamicSharedMemorySize, SMEM_ACCUM);

    /* q_a = x @ wq_a^T ; kv = x @ wkv^T */
    k_gemm<<<dim3(QLRK/64,1,1), 256>>>(x, DIMX, 0, wqa, DIMX, 0, qa, QLRK, 0, DIMX);
    k_gemm<<<dim3(HDIM/64,1,1), 256>>>(x, DIMX, 0, wkv, DIMX, 0, kv, HDIM, 0, DIMX);
    k_rms_qa<<<NB, 256>>>(qa, qnw);
    k_kv_finish<<<NB, 64>>>(kv, kvnw, ctxl);
    /* q = qa_n @ wq_b^T ; rope */
    k_gemm<<<dim3(QDIM/64,1,1), 256>>>(qa, QLRK, 0, wqb, QLRK, 0, qq, QDIM, 0, QLRK);
    k_rope_q<<<NB, 256>>>(qq, ctxl);
    /* attention */
    k_logits<<<dim3(MAXB, NB), 256, SMEM_LOGITS>>>(kvc, bt, ctxl, qq, kv, lg);
    k_select<<<NB*HEADS, 256>>>(lg, sink, tau, mr, iv);
    k_accum<<<dim3(8, NB), 256, SMEM_ACCUM>>>(kvc, bt, ctxl, kv, lg, tau, mr, iv, op);
    k_reduce_o<<<NB*QDIM/256, 256>>>(op, oo);
    /* epilogue GEMMs */
    k_gemm<<<dim3(OLRK/64,1,GRP), 256>>>(oo, QDIM, 768,
                                         woa, 768, (long long)OLRK*768,
                                         lat, GRP*OLRK, OLRK, 768);
    k_gemm<<<dim3(DIMX/64,1,1), 256>>>(lat, GRP*OLRK, 0, wob, DIMX, 0, out, DIMX, 0, DIMX);
}

// round 4
// speedup vs baseline: 2.9447x; 2.9447x over previous
#include <cuda_runtime.h>
#include <cuda_bf16.h>
#include <math.h>
#include <stdint.h>

#define NB    64
#define DIMX  4096
#define HEADS 32
#define HDIM  192
#define RDIM  64
#define QLRK  1536
#define OLRK  512
#define GRP   8
#define BS    64
#define MAXB  64
#define LMAX  4096
#define TOPKK 1024
#define EPSI  1e-6f
#define NEGF  -1e30f
#define QDIM  (HEADS*HDIM)   /* 6144 */
#define SCALE_F 0.07216878364870323f  /* 192^-0.5 */

/* ------------------------------------------------------------------ */
/* scratch                                                            */
/* ------------------------------------------------------------------ */
__device__ float g_qa[NB*QLRK];
__device__ float g_kv[NB*HDIM];
__device__ float g_q[NB*QDIM];
__device__ float g_logits[(size_t)NB*HEADS*LMAX];       /* 32 MB */
__device__ float g_tau[NB*HEADS];
__device__ float g_mrow[NB*HEADS];
__device__ float g_invden[NB*HEADS];
__device__ float g_opart[(size_t)8*NB*HEADS*HDIM];      /* 12.6 MB */
__device__ float g_o[NB*QDIM];
__device__ float g_lat[NB*GRP*OLRK];
__device__ float g_part[1179648];                       /* split-K partials */

/* ------------------------------------------------------------------ */
/* helpers                                                            */
/* ------------------------------------------------------------------ */
__device__ __forceinline__ uint32_t smem_u32(const void* p){
    uint32_t a;
    asm("{ .reg .u64 t; cvta.to.shared.u64 t, %1; cvt.u32.u64 %0, t; }"
        : "=r"(a) : "l"(p));
    return a;
}
__device__ __forceinline__ uint32_t sw128(uint32_t b){ return b ^ ((b >> 3) & 0x70); }
__device__ __forceinline__ uint32_t pk2(__nv_bfloat16 a, __nv_bfloat16 b){
    __nv_bfloat162 t(a, b);
    return *reinterpret_cast<uint32_t*>(&t);
}
__device__ __forceinline__ void mma16816(float* c, const uint32_t* a, const uint32_t* b){
    asm volatile("mma.sync.aligned.m16n8k16.row.col.f32.bf16.bf16.f32 "
        "{%0,%1,%2,%3}, {%4,%5,%6,%7}, {%8,%9}, {%0,%1,%2,%3};"
        : "+f"(c[0]), "+f"(c[1]), "+f"(c[2]), "+f"(c[3])
        : "r"(a[0]), "r"(a[1]), "r"(a[2]), "r"(a[3]), "r"(b[0]), "r"(b[1]));
}
__device__ __forceinline__ void ldm_x4(uint32_t* r, uint32_t addr){
    asm volatile("ldmatrix.sync.aligned.m8n8.x4.shared.b16 {%0,%1,%2,%3}, [%4];"
        : "=r"(r[0]), "=r"(r[1]), "=r"(r[2]), "=r"(r[3]) : "r"(addr));
}
__device__ __forceinline__ void cvt_store(char* hiB, char* loB, uint32_t off, float4 v){
    __nv_bfloat16 hx = __float2bfloat16(v.x), hy = __float2bfloat16(v.y);
    __nv_bfloat16 hz = __float2bfloat16(v.z), hw = __float2bfloat16(v.w);
    __nv_bfloat16 lx = __float2bfloat16(v.x - __bfloat162float(hx));
    __nv_bfloat16 ly = __float2bfloat16(v.y - __bfloat162float(hy));
    __nv_bfloat16 lz = __float2bfloat16(v.z - __bfloat162float(hz));
    __nv_bfloat16 lw = __float2bfloat16(v.w - __bfloat162float(hw));
    uint2 hh; hh.x = pk2(hx, hy); hh.y = pk2(hz, hw);
    uint2 ll; ll.x = pk2(lx, ly); ll.y = pk2(lz, lw);
    *(uint2*)(hiB + off) = hh;
    *(uint2*)(loB + off) = ll;
}

/* ------------------------------------------------------------------ */
/* HMMA GEMM:  C[m,n] = sum_k X[m,k] * W[n,k]     (M = 64 batch rows) */
/* per CTA: N-tile 128, K-chunk 64; bf16 hi/lo split, 3 MMA passes    */
/* smem: Xhi 8K | Xlo 8K | Whi 16K | Wlo 16K  (SW128 swizzle)         */
/* ------------------------------------------------------------------ */
#define MM_SMEM 49152
__global__ void __launch_bounds__(256,1) k_gemm_mma(
    const float* __restrict__ X, int ldx, long long xGrp,
    const float* __restrict__ W, int ldw, long long wGrp,
    float* __restrict__ C, int ldc, long long cGrp, long long cSplit,
    int Kloc, int Nw)
{
    extern __shared__ char sm[];
    char* sXhi = sm;
    char* sXlo = sm + 8192;
    char* sWhi = sm + 16384;
    char* sWlo = sm + 32768;
    uint32_t smb = smem_u32(sm);

    int tid = threadIdx.x, wid = tid >> 5, lane = tid & 31;
    int n0 = blockIdx.x * 128;
    int s  = blockIdx.y;
    int g  = blockIdx.z;
    X += (size_t)g * xGrp + (size_t)s * Kloc;
    W += (size_t)g * wGrp + (size_t)s * Kloc;
    C += (size_t)g * cGrp + (size_t)s * cSplit;

    int wm = (wid & 3) * 16;      /* warp M offset (batch rows)   */
    int wn = (wid >> 2) * 64;     /* warp N offset within tile    */

    float acc[8][4];
#pragma unroll
    for (int i = 0; i < 8; i++)
#pragma unroll
        for (int j = 0; j < 4; j++) acc[i][j] = 0.f;

    /* load indices */
    int xrow = tid >> 2;                      /* 0..63  */
    int xc   = tid & 3;                       /* c4 = xc + 4j */
    int wrow = tid >> 1;                      /* 0..127 */
    int wc   = tid & 1;                       /* c4 = wc + 2j */
    int wrg  = n0 + wrow; if (wrg >= Nw) wrg = Nw - 1;

    const int NC = Kloc / 64;
    float4 xv[4], wv[8];
#pragma unroll
    for (int j = 0; j < 4; j++)
        xv[j] = *(const float4*)(X + (size_t)xrow * ldx + (xc + 4*j) * 4);
#pragma unroll
    for (int j = 0; j < 8; j++)
        wv[j] = *(const float4*)(W + (size_t)wrg * ldw + (wc + 2*j) * 4);

    for (int ch = 0; ch < NC; ch++) {
        if (ch) __syncthreads();
        /* convert + swizzled store */
#pragma unroll
        for (int j = 0; j < 4; j++) {
            uint32_t off = sw128((uint32_t)(xrow * 128 + (xc + 4*j) * 8));
            cvt_store(sXhi, sXlo, off, xv[j]);
        }
#pragma unroll
        for (int j = 0; j < 8; j++) {
            uint32_t off = sw128((uint32_t)(wrow * 128 + (wc + 2*j) * 8));
            cvt_store(sWhi, sWlo, off, wv[j]);
        }
        __syncthreads();
        /* prefetch next chunk (LDGs overlap with MMA below) */
        if (ch + 1 < NC) {
            int kb = (ch + 1) * 64;
#pragma unroll
            for (int j = 0; j < 4; j++)
                xv[j] = *(const float4*)(X + (size_t)xrow * ldx + kb + (xc + 4*j) * 4);
#pragma unroll
            for (int j = 0; j < 8; j++)
                wv[j] = *(const float4*)(W + (size_t)wrg * ldw + kb + (wc + 2*j) * 4);
        }
        /* MMA over the 64-K chunk: 4 ksteps of 16 */
#pragma unroll
        for (int ks = 0; ks < 4; ks++) {
            uint32_t ah[4], al[4];
            {
                int arow = wm + (lane & 15);
                uint32_t aoff = sw128((uint32_t)(arow * 128 + (ks*2 + (lane >> 4)) * 16));
                ldm_x4(ah, smb + aoff);            /* Xhi base = 0     */
                ldm_x4(al, smb + 8192 + aoff);     /* Xlo              */
            }
#pragma unroll
            for (int t = 0; t < 4; t++) {
                int brow = wn + 16*t + ((lane >> 4) & 1) * 8 + (lane & 7);
                uint32_t boff = sw128((uint32_t)(brow * 128 + (ks*2 + ((lane >> 3) & 1)) * 16));
                uint32_t bh[4], bl[4];
                ldm_x4(bh, smb + 16384 + boff);
                ldm_x4(bl, smb + 32768 + boff);
                mma16816(acc[2*t],   ah, bh);
                mma16816(acc[2*t],   ah, bl);
                mma16816(acc[2*t],   al, bh);
                mma16816(acc[2*t+1], ah, bh + 2);
                mma16816(acc[2*t+1], ah, bl + 2);
                mma16816(acc[2*t+1], al, bh + 2);
            }
        }
    }

    /* epilogue */
    int mr = wm + (lane >> 2);
#pragma unroll
    for (int sub = 0; sub < 8; sub++) {
        int nc = n0 + wn + sub * 8 + (lane & 3) * 2;
        if (nc < Nw) {
            C[(size_t)mr * ldc + nc]       = acc[sub][0];
            C[(size_t)(mr + 8) * ldc + nc] = acc[sub][2];
        }
        if (nc + 1 < Nw) {
            C[(size_t)mr * ldc + nc + 1]       = acc[sub][1];
            C[(size_t)(mr + 8) * ldc + nc + 1] = acc[sub][3];
        }
    }
}

/* split-K reduce */
__global__ void k_reduce(const float* __restrict__ part, float* __restrict__ out,
                         int E, int S)
{
    int i = blockIdx.x * 256 + threadIdx.x;
    if (i >= E) return;
    float s = 0.f;
    for (int p = 0; p < S; p++) s += part[(size_t)p * E + i];
    out[i] = s;
}

/* ------------------------------------------------------------------ */
/* RMS norm over rows of g_qa                                         */
/* ------------------------------------------------------------------ */
__global__ void __launch_bounds__(256) k_rms_qa(float* __restrict__ a,
                                                const float* __restrict__ wt)
{
    __shared__ float red[256];
    int n = blockIdx.x, tid = threadIdx.x;
    float v[6]; float s = 0.f;
#pragma unroll
    for (int i = 0; i < 6; i++) {
        v[i] = a[(size_t)n*QLRK + tid + i*256];
        s += v[i]*v[i];
    }
    red[tid] = s; __syncthreads();
    for (int k = 128; k > 0; k >>= 1) { if (tid < k) red[tid] += red[tid+k]; __syncthreads(); }
    float scale = rsqrtf(red[0] / (float)QLRK + EPSI);
#pragma unroll
    for (int i = 0; i < 6; i++) {
        int c = tid + i*256;
        a[(size_t)n*QLRK + c] = v[i] * scale * wt[c];
    }
}

__device__ __forceinline__ void rope_cs(int i, float pos, float& c, float& s)
{
    float inv = (float)exp(-(double)i * 0.28782313662425574); /* ln(1e4)/32 */
    float ang = pos * inv;
    double ad = (double)ang;
    c = (float)cos(ad); s = (float)sin(ad);
}

__global__ void k_kv_finish(float* __restrict__ kv, const float* __restrict__ wt,
                            const int* __restrict__ ctxl)
{
    __shared__ float srow[HDIM];
    __shared__ float rs[64];
    int n = blockIdx.x, tid = threadIdx.x;
    float s = 0.f;
#pragma unroll
    for (int j = 0; j < 3; j++) {
        float v = kv[(size_t)n*HDIM + tid + j*64];
        srow[tid + j*64] = v; s += v*v;
    }
    rs[tid] = s; __syncthreads();
    for (int k = 32; k > 0; k >>= 1) { if (tid < k) rs[tid] += rs[tid+k]; __syncthreads(); }
    float scale = rsqrtf(rs[0] / (float)HDIM + EPSI);
#pragma unroll
    for (int j = 0; j < 3; j++) { int i = tid + j*64; srow[i] = srow[i]*scale*wt[i]; }
    __syncthreads();
    float pos = (float)(ctxl[n] - 1);
    if (tid < 32) {
        int i = tid;
        float x0 = srow[HDIM-RDIM + 2*i], x1 = srow[HDIM-RDIM + 2*i + 1];
        float c, sn; rope_cs(i, pos, c, sn);
        srow[HDIM-RDIM + 2*i]     = x0*c - x1*sn;
        srow[HDIM-RDIM + 2*i + 1] = x0*sn + x1*c;
    }
    __syncthreads();
#pragma unroll
    for (int j = 0; j < 3; j++) { int i = tid + j*64; kv[(size_t)n*HDIM + i] = srow[i]; }
}

__global__ void __launch_bounds__(256) k_rope_q(float* __restrict__ q,
                                                const int* __restrict__ ctxl)
{
    int n = blockIdx.x, tid = threadIdx.x;
    float pos = (float)(ctxl[n] - 1);
#pragma unroll
    for (int k = 0; k < 4; k++) {
        int pi = tid + k*256;
        int h = pi >> 5, i = pi & 31;
        float* base = q + (size_t)n*QDIM + h*HDIM + (HDIM-RDIM) + 2*i;
        float x0 = base[0], x1 = base[1];
        float c, s; rope_cs(i, pos, c, s);
        base[0] = x0*c - x1*s;
        base[1] = x0*s + x1*c;
    }
}

/* ------------------------------------------------------------------ */
/* logits                                                             */
/* ------------------------------------------------------------------ */
__global__ void __launch_bounds__(256) k_logits(
    const float* __restrict__ kvc, const int* __restrict__ bt,
    const int* __restrict__ ctxl, const float* __restrict__ q,
    const float* __restrict__ kvnew, float* __restrict__ logits)
{
    extern __shared__ float sm1[];
    int n = blockIdx.y, b = blockIdx.x;
    int ctx = ctxl[n];
    int base = b * BS;
    int tid = threadIdx.x;
    int w = tid >> 5, lane = tid & 31;

    if (base >= ctx) {
#pragma unroll
        for (int j = 0; j < 4; j++) {
            int h = w + 8*j;
            float* dst = logits + ((size_t)(n*HEADS + h))*LMAX + base;
            dst[lane] = NEGF; dst[lane+32] = NEGF;
        }
        return;
    }
    float* Qs  = sm1;
    float* KVs = sm1 + QDIM;

    const float4* qsrc = (const float4*)(q + (size_t)n*QDIM);
#pragma unroll
    for (int i = 0; i < 6; i++) {
        int idx = tid + i*256;
        float4 v = qsrc[idx];
        Qs[idx*4+0]=v.x; Qs[idx*4+1]=v.y; Qs[idx*4+2]=v.z; Qs[idx*4+3]=v.w;
    }
    int blk = bt[n*MAXB + b];
    {
        int row = tid >> 2, qp = tid & 3;
        int lg = base + row;
        const float* src = (lg == ctx-1) ? (kvnew + (size_t)n*HDIM)
                                         : (kvc + ((size_t)blk*BS + row)*HDIM);
        const float4* s4 = (const float4*)src;
#pragma unroll
        for (int j = 0; j < 12; j++) {
            int d4 = qp*12 + j;
            float4 v = s4[d4];
            float* dst = KVs + row*193 + d4*4;
            dst[0]=v.x; dst[1]=v.y; dst[2]=v.z; dst[3]=v.w;
        }
    }
    __syncthreads();

    float acc[4][2];
#pragma unroll
    for (int j = 0; j < 4; j++) { acc[j][0]=0.f; acc[j][1]=0.f; }
#pragma unroll 4
    for (int d = 0; d < HDIM; d++) {
        float k0 = KVs[lane*193 + d];
        float k1 = KVs[(lane+32)*193 + d];
#pragma unroll
        for (int j = 0; j < 4; j++) {
            float qv = Qs[(w + 8*j)*HDIM + d];
            acc[j][0] += qv*k0;
            acc[j][1] += qv*k1;
        }
    }
    bool v0 = (base + lane)      < ctx;
    bool v1 = (base + lane + 32) < ctx;
#pragma unroll
    for (int j = 0; j < 4; j++) {
        int h = w + 8*j;
        float* dst = logits + ((size_t)(n*HEADS + h))*LMAX + base;
        dst[lane]    = v0 ? acc[j][0]*SCALE_F : NEGF;
        dst[lane+32] = v1 ? acc[j][1]*SCALE_F : NEGF;
    }
}

/* ------------------------------------------------------------------ */
/* top-k radix select                                                 */
/* ------------------------------------------------------------------ */
__device__ __forceinline__ unsigned f2ord(float f) {
    unsigned b = __float_as_uint(f);
    return (b & 0x80000000u) ? ~b : (b | 0x80000000u);
}
__device__ __forceinline__ float ord2f(unsigned u) {
    return (u & 0x80000000u) ? __uint_as_float(u ^ 0x80000000u)
                             : __uint_as_float(~u);
}

__global__ void __launch_bounds__(256) k_select(
    const float* __restrict__ logits, const float* __restrict__ sink,
    float* __restrict__ tau_o, float* __restrict__ m_o, float* __restrict__ iv_o)
{
    __shared__ unsigned keys[LMAX];
    __shared__ unsigned hist[256];
    __shared__ unsigned rmax[256];
    __shared__ float    red[256];
    __shared__ unsigned s_prefix;
    __shared__ int      s_k;

    int rowid = blockIdx.x;
    int h = rowid & 31;
    int tid = threadIdx.x;
    const float* src = logits + (size_t)rowid * LMAX;

    unsigned um = 0u;
#pragma unroll
    for (int i = 0; i < 16; i++) {
        int idx = tid + i*256;
        unsigned u = f2ord(src[idx]);
        keys[idx] = u;
        um = max(um, u);
    }
    rmax[tid] = um; __syncthreads();
    for (int k = 128; k > 0; k >>= 1) { if (tid < k) rmax[tid] = max(rmax[tid], rmax[tid+k]); __syncthreads(); }
    if (tid == 0) { s_prefix = 0u; s_k = TOPKK; }
    __syncthreads();

    for (int shift = 24; shift >= 0; shift -= 8) {
        hist[tid] = 0u;
        __syncthreads();
        unsigned pref = s_prefix;
        unsigned himask = (shift == 24) ? 0u : (0xFFFFFFFFu << (shift + 8));
#pragma unroll
        for (int i = 0; i < 16; i++) {
            unsigned u = keys[tid + i*256];
            if ((u & himask) == pref) atomicAdd(&hist[(u >> shift) & 255u], 1u);
        }
        __syncthreads();
        if (tid == 0) {
            int kk = s_k; unsigned cum = 0u; int bin = 255;
            for (; bin > 0; bin--) {
                unsigned c = hist[bin];
                if (cum + c >= (unsigned)kk) break;
                cum += c;
            }
            s_prefix = pref | ((unsigned)bin << shift);
            s_k = kk - (int)cum;
        }
        __syncthreads();
    }
    unsigned tu = s_prefix;
    float tauf = ord2f(tu);
    float maxf = ord2f(rmax[0]);
    float snk  = sink[h];
    float m    = fmaxf(maxf, snk);

    float local = 0.f;
#pragma unroll
    for (int i = 0; i < 16; i++) {
        unsigned u = keys[tid + i*256];
        if (u >= tu) local += expf(ord2f(u) - m);
    }
    red[tid] = local; __syncthreads();
    for (int k = 128; k > 0; k >>= 1) { if (tid < k) red[tid] += red[tid+k]; __syncthreads(); }
    if (tid == 0) {
        float denom = red[0] + expf(snk - m);
        tau_o[rowid] = tauf; m_o[rowid] = m; iv_o[rowid] = 1.f / denom;
    }
}

/* ------------------------------------------------------------------ */
/* o accumulation                                                     */
/* ------------------------------------------------------------------ */
__global__ void __launch_bounds__(256) k_accum(
    const float* __restrict__ kvc, const int* __restrict__ bt,
    const int* __restrict__ ctxl, const float* __restrict__ kvnew,
    const float* __restrict__ logits, const float* __restrict__ tau_i,
    const float* __restrict__ m_i, const float* __restrict__ iv_i,
    float* __restrict__ opart)
{
    extern __shared__ float sm2[];
    float* KVs = sm2;
    float* ps  = sm2 + BS*HDIM;

    int chunk = blockIdx.x, n = blockIdx.y;
    int ctx = ctxl[n];
    int tid = threadIdx.x;
    int w = tid >> 5, lane = tid & 31;

    float acc[4][6];
#pragma unroll
    for (int j = 0; j < 4; j++)
#pragma unroll
        for (int i = 0; i < 6; i++) acc[j][i] = 0.f;

    int ph = tid >> 3, pl0 = (tid & 7) * 8;
    float ptau = tau_i[n*HEADS + ph];
    float pm   = m_i[n*HEADS + ph];
    float piv  = iv_i[n*HEADS + ph];

    for (int b8 = 0; b8 < 8; b8++) {
        int b = chunk*8 + b8;
        int base = b * BS;
        if (base >= ctx) break;
        int blk = bt[n*MAXB + b];
        {
            int row = tid >> 2, qp = tid & 3;
            int lg = base + row;
            const float* src = (lg == ctx-1) ? (kvnew + (size_t)n*HDIM)
                                             : (kvc + ((size_t)blk*BS + row)*HDIM);
            const float4* s4 = (const float4*)src;
#pragma unroll
            for (int j = 0; j < 12; j++) {
                int d4 = qp*12 + j;
                float4 v = s4[d4];
                float* dst = KVs + row*HDIM + d4*4;
                dst[0]=v.x; dst[1]=v.y; dst[2]=v.z; dst[3]=v.w;
            }
        }
        const float* lsrc = logits + ((size_t)(n*HEADS + ph))*LMAX + base + pl0;
#pragma unroll
        for (int j = 0; j < 8; j++) {
            float lg = lsrc[j];
            float p = (lg >= ptau) ? (expf(lg - pm) * piv) : 0.f;
            ps[ph*BS + pl0 + j] = p;
        }
        __syncthreads();
#pragma unroll 2
        for (int l = 0; l < BS; l++) {
            float pj[4];
#pragma unroll
            for (int j = 0; j < 4; j++) pj[j] = ps[(w + 8*j)*BS + l];
#pragma unroll
            for (int i = 0; i < 6; i++) {
                float kvv = KVs[l*HDIM + lane + 32*i];
#pragma unroll
                for (int j = 0; j < 4; j++) acc[j][i] += pj[j]*kvv;
            }
        }
        __syncthreads();
    }
#pragma unroll
    for (int j = 0; j < 4; j++) {
        int h = w + 8*j;
        float* dst = opart + (((size_t)chunk*NB + n)*HEADS + h)*HDIM;
#pragma unroll
        for (int i = 0; i < 6; i++) dst[lane + 32*i] = acc[j][i];
    }
}

__global__ void k_reduce_o(const float* __restrict__ opart, float* __restrict__ o)
{
    int idx = blockIdx.x*256 + threadIdx.x;
    float s = 0.f;
#pragma unroll
    for (int c = 0; c < 8; c++) s += opart[(size_t)c*NB*QDIM + idx];
    o[idx] = s;
}

/* ------------------------------------------------------------------ */
/* host launcher                                                      */
/* ------------------------------------------------------------------ */
extern "C" void kernel_launch(void* const* d_in, const int* in_sizes, int n_in,
                              void* d_out, int out_size)
{
    const float* x    = (const float*)d_in[0];
    const float* kvc  = (const float*)d_in[1];
    const int*   bt   = (const int*)  d_in[2];
    const int*   ctxl = (const int*)  d_in[3];
    const float* wqa  = (const float*)d_in[5];
    const float* qnw  = (const float*)d_in[6];
    const float* wqb  = (const float*)d_in[7];
    const float* wkv  = (const float*)d_in[8];
    const float* kvnw = (const float*)d_in[9];
    const float* woa  = (const float*)d_in[10];
    const float* wob  = (const float*)d_in[11];
    const float* sink = (const float*)d_in[12];
    float* out = (float*)d_out;

    float *qa, *kv, *qq, *lg, *tau, *mr, *iv, *op, *oo, *lat, *part;
    cudaGetSymbolAddress((void**)&qa,   g_qa);
    cudaGetSymbolAddress((void**)&kv,   g_kv);
    cudaGetSymbolAddress((void**)&qq,   g_q);
    cudaGetSymbolAddress((void**)&lg,   g_logits);
    cudaGetSymbolAddress((void**)&tau,  g_tau);
    cudaGetSymbolAddress((void**)&mr,   g_mrow);
    cudaGetSymbolAddress((void**)&iv,   g_invden);
    cudaGetSymbolAddress((void**)&op,   g_opart);
    cudaGetSymbolAddress((void**)&oo,   g_o);
    cudaGetSymbolAddress((void**)&lat,  g_lat);
    cudaGetSymbolAddress((void**)&part, g_part);

    const int SMEM_LOGITS = (QDIM + 64*193) * 4;        /* 73984  */
    const int SMEM_ACCUM  = (BS*HDIM + HEADS*BS) * 4;   /* 57344  */
    cudaFuncSetAttribute(k_gemm_mma, cudaFuncAttributeMaxDynamicSharedMemorySize, MM_SMEM);
    cudaFuncSetAttribute(k_logits,   cudaFuncAttributeMaxDynamicSharedMemorySize, SMEM_LOGITS);
    cudaFuncSetAttribute(k_accum,    cudaFuncAttributeMaxDynamicSharedMemorySize, SMEM_ACCUM);

    /* ---- q_a = x @ wq_a^T : N=1536, K=4096, split 8 ---- */
    k_gemm_mma<<<dim3(12, 8, 1), 256, MM_SMEM>>>(
        x, DIMX, 0, wqa, DIMX, 0,
        part, QLRK, 0, (long long)64*QLRK, 512, QLRK);
    k_reduce<<<(64*QLRK+255)/256, 256>>>(part, qa, 64*QLRK, 8);

    /* ---- kv = x @ wkv^T : N=192, K=4096, split 16 ---- */
    k_gemm_mma<<<dim3(2, 16, 1), 256, MM_SMEM>>>(
        x, DIMX, 0, wkv, DIMX, 0,
        part, HDIM, 0, (long long)64*HDIM, 256, HDIM);
    k_reduce<<<(64*HDIM+255)/256, 256>>>(part, kv, 64*HDIM, 16);

    k_rms_qa<<<NB, 256>>>(qa, qnw);
    k_kv_finish<<<NB, 64>>>(kv, kvnw, ctxl);

    /* ---- q = qa_n @ wq_b^T : N=6144, K=1536, split 3 ---- */
    k_gemm_mma<<<dim3(48, 3, 1), 256, MM_SMEM>>>(
        qa, QLRK, 0, wqb, QLRK, 0,
        part, QDIM, 0, (long long)64*QDIM, 512, QDIM);
    k_reduce<<<(64*QDIM+255)/256, 256>>>(part, qq, 64*QDIM, 3);
    k_rope_q<<<NB, 256>>>(qq, ctxl);

    /* ---- attention ---- */
    k_logits<<<dim3(MAXB, NB), 256, SMEM_LOGITS>>>(kvc, bt, ctxl, qq, kv, lg);
    k_select<<<NB*HEADS, 256>>>(lg, sink, tau, mr, iv);
    k_accum<<<dim3(8, NB), 256, SMEM_ACCUM>>>(kvc, bt, ctxl, kv, lg, tau, mr, iv, op);
    k_reduce_o<<<NB*QDIM/256, 256>>>(op, oo);

    /* ---- lat = grouped wo_a : per-group N=512, K=768, split 4 ---- */
    k_gemm_mma<<<dim3(4, 4, GRP), 256, MM_SMEM>>>(
        oo, QDIM, 768, woa, 768, (long long)OLRK*768,
        part, GRP*OLRK, OLRK, (long long)64*GRP*OLRK, 192, OLRK);
    k_reduce<<<(64*GRP*OLRK+255)/256, 256>>>(part, lat, 64*GRP*OLRK, 4);

    /* ---- out = lat @ wo_b^T : N=4096, K=4096, split 4 ---- */
    k_gemm_mma<<<dim3(32, 4, 1), 256, MM_SMEM>>>(
        lat, GRP*OLRK, 0, wob, DIMX, 0,
        part, DIMX, 0, (long long)64*DIMX, 1024, DIMX);
    k_reduce<<<(64*DIMX+255)/256, 256>>>(part, out, 64*DIMX, 4);
}

// round 5
// speedup vs baseline: 3.4677x; 1.1776x over previous
#include <cuda_runtime.h>
#include <cuda_bf16.h>
#include <math.h>
#include <stdint.h>

#define NB    64
#define DIMX  4096
#define HEADS 32
#define HDIM  192
#define RDIM  64
#define QLRK  1536
#define OLRK  512
#define GRP   8
#define BS    64
#define MAXB  64
#define LMAX  4096
#define TOPKK 1024
#define EPSI  1e-6f
#define NEGF  -1e30f
#define QDIM  (HEADS*HDIM)   /* 6144 */
#define SCALE_F 0.07216878364870323f  /* 192^-0.5 */

/* ------------------------------------------------------------------ */
/* scratch                                                            */
/* ------------------------------------------------------------------ */
__device__ float g_qa[NB*QLRK];
__device__ float g_kv[NB*HDIM];
__device__ float g_q[NB*QDIM];
__device__ __nv_bfloat16 g_qhi[NB*QDIM];
__device__ __nv_bfloat16 g_qlo[NB*QDIM];
__device__ float g_logits[(size_t)NB*HEADS*LMAX];       /* 32 MB */
__device__ float g_tau[NB*HEADS];
__device__ float g_mrow[NB*HEADS];
__device__ float g_invden[NB*HEADS];
__device__ float g_opart[(size_t)8*NB*HEADS*HDIM];      /* 12.6 MB */
__device__ float g_o[NB*QDIM];
__device__ float g_lat[NB*GRP*OLRK];
__device__ float g_part[1179648];                       /* split-K partials */

/* ------------------------------------------------------------------ */
/* helpers                                                            */
/* ------------------------------------------------------------------ */
__device__ __forceinline__ uint32_t smem_u32(const void* p){
    uint32_t a;
    asm("{ .reg .u64 t; cvta.to.shared.u64 t, %1; cvt.u32.u64 %0, t; }"
        : "=r"(a) : "l"(p));
    return a;
}
__device__ __forceinline__ uint32_t sw128(uint32_t b){ return b ^ ((b >> 3) & 0x70); }
__device__ __forceinline__ uint32_t pk2(__nv_bfloat16 a, __nv_bfloat16 b){
    __nv_bfloat162 t(a, b);
    return *reinterpret_cast<uint32_t*>(&t);
}
__device__ __forceinline__ void mma16816(float* c, const uint32_t* a, const uint32_t* b){
    asm volatile("mma.sync.aligned.m16n8k16.row.col.f32.bf16.bf16.f32 "
        "{%0,%1,%2,%3}, {%4,%5,%6,%7}, {%8,%9}, {%0,%1,%2,%3};"
        : "+f"(c[0]), "+f"(c[1]), "+f"(c[2]), "+f"(c[3])
        : "r"(a[0]), "r"(a[1]), "r"(a[2]), "r"(a[3]), "r"(b[0]), "r"(b[1]));
}
__device__ __forceinline__ void ldm_x4(uint32_t* r, uint32_t addr){
    asm volatile("ldmatrix.sync.aligned.m8n8.x4.shared.b16 {%0,%1,%2,%3}, [%4];"
        : "=r"(r[0]), "=r"(r[1]), "=r"(r[2]), "=r"(r[3]) : "r"(addr));
}
__device__ __forceinline__ void cvt_store(char* hiB, char* loB, uint32_t off, float4 v){
    __nv_bfloat16 hx = __float2bfloat16(v.x), hy = __float2bfloat16(v.y);
    __nv_bfloat16 hz = __float2bfloat16(v.z), hw = __float2bfloat16(v.w);
    __nv_bfloat16 lx = __float2bfloat16(v.x - __bfloat162float(hx));
    __nv_bfloat16 ly = __float2bfloat16(v.y - __bfloat162float(hy));
    __nv_bfloat16 lz = __float2bfloat16(v.z - __bfloat162float(hz));
    __nv_bfloat16 lw = __float2bfloat16(v.w - __bfloat162float(hw));
    uint2 hh; hh.x = pk2(hx, hy); hh.y = pk2(hz, hw);
    uint2 ll; ll.x = pk2(lx, ly); ll.y = pk2(lz, lw);
    *(uint2*)(hiB + off) = hh;
    *(uint2*)(loB + off) = ll;
}

/* ------------------------------------------------------------------ */
/* HMMA GEMM (dense projections) — unchanged from round 4             */
/* ------------------------------------------------------------------ */
#define MM_SMEM 49152
__global__ void __launch_bounds__(256,1) k_gemm_mma(
    const float* __restrict__ X, int ldx, long long xGrp,
    const float* __restrict__ W, int ldw, long long wGrp,
    float* __restrict__ C, int ldc, long long cGrp, long long cSplit,
    int Kloc, int Nw)
{
    extern __shared__ char sm[];
    char* sXhi = sm;
    char* sXlo = sm + 8192;
    char* sWhi = sm + 16384;
    char* sWlo = sm + 32768;
    uint32_t smb = smem_u32(sm);

    int tid = threadIdx.x, wid = tid >> 5, lane = tid & 31;
    int n0 = blockIdx.x * 128;
    int s  = blockIdx.y;
    int g  = blockIdx.z;
    X += (size_t)g * xGrp + (size_t)s * Kloc;
    W += (size_t)g * wGrp + (size_t)s * Kloc;
    C += (size_t)g * cGrp + (size_t)s * cSplit;

    int wm = (wid & 3) * 16;
    int wn = (wid >> 2) * 64;

    float acc[8][4];
#pragma unroll
    for (int i = 0; i < 8; i++)
#pragma unroll
        for (int j = 0; j < 4; j++) acc[i][j] = 0.f;

    int xrow = tid >> 2;
    int xc   = tid & 3;
    int wrow = tid >> 1;
    int wc   = tid & 1;
    int wrg  = n0 + wrow; if (wrg >= Nw) wrg = Nw - 1;

    const int NC = Kloc / 64;
    float4 xv[4], wv[8];
#pragma unroll
    for (int j = 0; j < 4; j++)
        xv[j] = *(const float4*)(X + (size_t)xrow * ldx + (xc + 4*j) * 4);
#pragma unroll
    for (int j = 0; j < 8; j++)
        wv[j] = *(const float4*)(W + (size_t)wrg * ldw + (wc + 2*j) * 4);

    for (int ch = 0; ch < NC; ch++) {
        if (ch) __syncthreads();
#pragma unroll
        for (int j = 0; j < 4; j++) {
            uint32_t off = sw128((uint32_t)(xrow * 128 + (xc + 4*j) * 8));
            cvt_store(sXhi, sXlo, off, xv[j]);
        }
#pragma unroll
        for (int j = 0; j < 8; j++) {
            uint32_t off = sw128((uint32_t)(wrow * 128 + (wc + 2*j) * 8));
            cvt_store(sWhi, sWlo, off, wv[j]);
        }
        __syncthreads();
        if (ch + 1 < NC) {
            int kb = (ch + 1) * 64;
#pragma unroll
            for (int j = 0; j < 4; j++)
                xv[j] = *(const float4*)(X + (size_t)xrow * ldx + kb + (xc + 4*j) * 4);
#pragma unroll
            for (int j = 0; j < 8; j++)
                wv[j] = *(const float4*)(W + (size_t)wrg * ldw + kb + (wc + 2*j) * 4);
        }
#pragma unroll
        for (int ks = 0; ks < 4; ks++) {
            uint32_t ah[4], al[4];
            {
                int arow = wm + (lane & 15);
                uint32_t aoff = sw128((uint32_t)(arow * 128 + (ks*2 + (lane >> 4)) * 16));
                ldm_x4(ah, smb + aoff);
                ldm_x4(al, smb + 8192 + aoff);
            }
#pragma unroll
            for (int t = 0; t < 4; t++) {
                int brow = wn + 16*t + ((lane >> 4) & 1) * 8 + (lane & 7);
                uint32_t boff = sw128((uint32_t)(brow * 128 + (ks*2 + ((lane >> 3) & 1)) * 16));
                uint32_t bh[4], bl[4];
                ldm_x4(bh, smb + 16384 + boff);
                ldm_x4(bl, smb + 32768 + boff);
                mma16816(acc[2*t],   ah, bh);
                mma16816(acc[2*t],   ah, bl);
                mma16816(acc[2*t],   al, bh);
                mma16816(acc[2*t+1], ah, bh + 2);
                mma16816(acc[2*t+1], ah, bl + 2);
                mma16816(acc[2*t+1], al, bh + 2);
            }
        }
    }

    int mr = wm + (lane >> 2);
#pragma unroll
    for (int sub = 0; sub < 8; sub++) {
        int nc = n0 + wn + sub * 8 + (lane & 3) * 2;
        if (nc < Nw) {
            C[(size_t)mr * ldc + nc]       = acc[sub][0];
            C[(size_t)(mr + 8) * ldc + nc] = acc[sub][2];
        }
        if (nc + 1 < Nw) {
            C[(size_t)mr * ldc + nc + 1]       = acc[sub][1];
            C[(size_t)(mr + 8) * ldc + nc + 1] = acc[sub][3];
        }
    }
}

/* split-K reduce */
__global__ void k_reduce(const float* __restrict__ part, float* __restrict__ out,
                         int E, int S)
{
    int i = blockIdx.x * 256 + threadIdx.x;
    if (i >= E) return;
    float s = 0.f;
    for (int p = 0; p < S; p++) s += part[(size_t)p * E + i];
    out[i] = s;
}

/* ------------------------------------------------------------------ */
/* RMS norm over rows of g_qa                                         */
/* ------------------------------------------------------------------ */
__global__ void __launch_bounds__(256) k_rms_qa(float* __restrict__ a,
                                                const float* __restrict__ wt)
{
    __shared__ float red[256];
    int n = blockIdx.x, tid = threadIdx.x;
    float v[6]; float s = 0.f;
#pragma unroll
    for (int i = 0; i < 6; i++) {
        v[i] = a[(size_t)n*QLRK + tid + i*256];
        s += v[i]*v[i];
    }
    red[tid] = s; __syncthreads();
    for (int k = 128; k > 0; k >>= 1) { if (tid < k) red[tid] += red[tid+k]; __syncthreads(); }
    float scale = rsqrtf(red[0] / (float)QLRK + EPSI);
#pragma unroll
    for (int i = 0; i < 6; i++) {
        int c = tid + i*256;
        a[(size_t)n*QLRK + c] = v[i] * scale * wt[c];
    }
}

__device__ __forceinline__ void rope_cs(int i, float pos, float& c, float& s)
{
    float inv = (float)exp(-(double)i * 0.28782313662425574); /* ln(1e4)/32 */
    float ang = pos * inv;
    double ad = (double)ang;
    c = (float)cos(ad); s = (float)sin(ad);
}

__global__ void k_kv_finish(float* __restrict__ kv, const float* __restrict__ wt,
                            const int* __restrict__ ctxl)
{
    __shared__ float srow[HDIM];
    __shared__ float rs[64];
    int n = blockIdx.x, tid = threadIdx.x;
    float s = 0.f;
#pragma unroll
    for (int j = 0; j < 3; j++) {
        float v = kv[(size_t)n*HDIM + tid + j*64];
        srow[tid + j*64] = v; s += v*v;
    }
    rs[tid] = s; __syncthreads();
    for (int k = 32; k > 0; k >>= 1) { if (tid < k) rs[tid] += rs[tid+k]; __syncthreads(); }
    float scale = rsqrtf(rs[0] / (float)HDIM + EPSI);
#pragma unroll
    for (int j = 0; j < 3; j++) { int i = tid + j*64; srow[i] = srow[i]*scale*wt[i]; }
    __syncthreads();
    float pos = (float)(ctxl[n] - 1);
    if (tid < 32) {
        int i = tid;
        float x0 = srow[HDIM-RDIM + 2*i], x1 = srow[HDIM-RDIM + 2*i + 1];
        float c, sn; rope_cs(i, pos, c, sn);
        srow[HDIM-RDIM + 2*i]     = x0*c - x1*sn;
        srow[HDIM-RDIM + 2*i + 1] = x0*sn + x1*c;
    }
    __syncthreads();
#pragma unroll
    for (int j = 0; j < 3; j++) { int i = tid + j*64; kv[(size_t)n*HDIM + i] = srow[i]; }
}

__global__ void __launch_bounds__(256) k_rope_q(float* __restrict__ q,
                                                const int* __restrict__ ctxl)
{
    int n = blockIdx.x, tid = threadIdx.x;
    float pos = (float)(ctxl[n] - 1);
#pragma unroll
    for (int k = 0; k < 4; k++) {
        int pi = tid + k*256;
        int h = pi >> 5, i = pi & 31;
        float* base = q + (size_t)n*QDIM + h*HDIM + (HDIM-RDIM) + 2*i;
        float x0 = base[0], x1 = base[1];
        float c, s; rope_cs(i, pos, c, s);
        base[0] = x0*c - x1*s;
        base[1] = x0*s + x1*c;
    }
}

/* q fp32 -> bf16 hi/lo (one float4 per thread) */
__global__ void __launch_bounds__(256) k_q2bf(const float* __restrict__ q,
                                              __nv_bfloat16* __restrict__ qhi,
                                              __nv_bfloat16* __restrict__ qlo)
{
    int idx = blockIdx.x * 256 + threadIdx.x;      /* < NB*QDIM/4 */
    float4 v = ((const float4*)q)[idx];
    __nv_bfloat16 hx = __float2bfloat16(v.x), hy = __float2bfloat16(v.y);
    __nv_bfloat16 hz = __float2bfloat16(v.z), hw = __float2bfloat16(v.w);
    __nv_bfloat16 lx = __float2bfloat16(v.x - __bfloat162float(hx));
    __nv_bfloat16 ly = __float2bfloat16(v.y - __bfloat162float(hy));
    __nv_bfloat16 lz = __float2bfloat16(v.z - __bfloat162float(hz));
    __nv_bfloat16 lw = __float2bfloat16(v.w - __bfloat162float(hw));
    uint2 hh; hh.x = pk2(hx, hy); hh.y = pk2(hz, hw);
    uint2 ll; ll.x = pk2(lx, ly); ll.y = pk2(lz, lw);
    ((uint2*)qhi)[idx] = hh;
    ((uint2*)qlo)[idx] = ll;
}

/* ------------------------------------------------------------------ */
/* logits via HMMA: CTA = (block b, batch n), only valid blocks       */
/* smem: Qhi[0,12800) Qlo[12800,25600) KVhi[25600,51200) KVlo[51200,76800) */
/* pitch 400 B (25 quads -> conflict-free ldmatrix)                   */
/* ------------------------------------------------------------------ */
#define LG_SMEM 76800
__global__ void __launch_bounds__(256) k_logits_mma(
    const float* __restrict__ kvc, const int* __restrict__ bt,
    const int* __restrict__ ctxl,
    const __nv_bfloat16* __restrict__ qhi, const __nv_bfloat16* __restrict__ qlo,
    const float* __restrict__ kvnew, float* __restrict__ logits)
{
    extern __shared__ char sm[];
    uint32_t smb = smem_u32(sm);
    int n = blockIdx.y, b = blockIdx.x;
    int ctx = ctxl[n];
    int base = b * BS;
    if (base >= ctx) return;
    int tid = threadIdx.x, wid = tid >> 5, lane = tid & 31;

    /* Q hi/lo: 32 rows x 384B -> pitch 400 */
    {
        const char* gh = (const char*)(qhi + (size_t)n * QDIM);
        const char* gl = (const char*)(qlo + (size_t)n * QDIM);
#pragma unroll
        for (int i = 0; i < 3; i++) {
            int c = tid + i * 256;            /* 768 chunks of 16B */
            int r = c / 24, k16 = c % 24;
            *(uint4*)(sm + r * 400 + k16 * 16) = *(const uint4*)(gh + r * 384 + k16 * 16);
            *(uint4*)(sm + 12800 + r * 400 + k16 * 16) = *(const uint4*)(gl + r * 384 + k16 * 16);
        }
    }
    /* KV tile: 64 rows fp32 -> bf16 hi/lo, pitch 400 */
    int blk = bt[n * MAXB + b];
    {
        int row = tid >> 2, qp = tid & 3;
        int lg = base + row;
        const float* src = (lg == ctx - 1) ? (kvnew + (size_t)n * HDIM)
                                           : (kvc + ((size_t)blk * BS + row) * HDIM);
#pragma unroll
        for (int j = 0; j < 12; j++) {
            int d4 = qp * 12 + j;
            float4 v = ((const float4*)src)[d4];
            cvt_store(sm + 25600, sm + 51200, (uint32_t)(row * 400 + d4 * 8), v);
        }
    }
    __syncthreads();

    int mt = wid & 3;       /* l tile: 16 positions */
    int nt = wid >> 2;      /* h tile: 16 heads     */
    float acc[2][4];
#pragma unroll
    for (int i = 0; i < 2; i++)
#pragma unroll
        for (int j = 0; j < 4; j++) acc[i][j] = 0.f;

#pragma unroll
    for (int ks = 0; ks < 12; ks++) {
        uint32_t ah[4], al[4];
        int arow = mt * 16 + (lane & 15);
        uint32_t aoff = (uint32_t)(arow * 400 + ks * 32 + (lane >> 4) * 16);
        ldm_x4(ah, smb + 25600 + aoff);
        ldm_x4(al, smb + 51200 + aoff);
        int brow = nt * 16 + ((lane >> 4) & 1) * 8 + (lane & 7);
        uint32_t boff = (uint32_t)(brow * 400 + ks * 32 + ((lane >> 3) & 1) * 16);
        uint32_t bh[4], bl[4];
        ldm_x4(bh, smb + boff);
        ldm_x4(bl, smb + 12800 + boff);
        mma16816(acc[0], ah, bh);
        mma16816(acc[0], ah, bl);
        mma16816(acc[0], al, bh);
        mma16816(acc[1], ah, bh + 2);
        mma16816(acc[1], ah, bl + 2);
        mma16816(acc[1], al, bh + 2);
    }
    __syncthreads();
    /* stage D[h][l] in smem (reuse Q area), then coalesced write */
    float* D = (float*)sm;
#pragma unroll
    for (int n8 = 0; n8 < 2; n8++) {
        int h = nt * 16 + n8 * 8 + (lane & 3) * 2;
        int l = mt * 16 + (lane >> 2);
        D[h * 64 + l]           = acc[n8][0];
        D[(h + 1) * 64 + l]     = acc[n8][1];
        D[h * 64 + l + 8]       = acc[n8][2];
        D[(h + 1) * 64 + l + 8] = acc[n8][3];
    }
    __syncthreads();
    int h = tid >> 3, l0 = (tid & 7) * 8;
    float* dst = logits + ((size_t)(n * HEADS + h)) * LMAX + base + l0;
#pragma unroll
    for (int j = 0; j < 8; j++) {
        int l = l0 + j;
        float v = D[h * 64 + l];
        dst[j] = (base + l < ctx) ? v * SCALE_F : NEGF;
    }
}

/* ------------------------------------------------------------------ */
/* top-k radix select (variable length)                               */
/* ------------------------------------------------------------------ */
__device__ __forceinline__ unsigned f2ord(float f) {
    unsigned b = __float_as_uint(f);
    return (b & 0x80000000u) ? ~b : (b | 0x80000000u);
}
__device__ __forceinline__ float ord2f(unsigned u) {
    return (u & 0x80000000u) ? __uint_as_float(u ^ 0x80000000u)
                             : __uint_as_float(~u);
}

__global__ void __launch_bounds__(256) k_select(
    const float* __restrict__ logits, const float* __restrict__ sink,
    const int* __restrict__ ctxl,
    float* __restrict__ tau_o, float* __restrict__ m_o, float* __restrict__ iv_o)
{
    __shared__ unsigned keys[LMAX];
    __shared__ unsigned hist[256];
    __shared__ unsigned rmax[256];
    __shared__ float    red[256];
    __shared__ unsigned s_prefix;
    __shared__ int      s_k;

    int rowid = blockIdx.x;
    int n = rowid >> 5;
    int h = rowid & 31;
    int tid = threadIdx.x;
    int ctx = ctxl[n];
    int nb = ((ctx + 63) >> 6) << 6;      /* multiple of 64, <= LMAX */
    const float* src = logits + (size_t)rowid * LMAX;

    unsigned um = 0u;
    for (int idx = tid; idx < nb; idx += 256) {
        unsigned u = f2ord(src[idx]);
        keys[idx] = u;
        um = max(um, u);
    }
    rmax[tid] = um; __syncthreads();
    for (int k = 128; k > 0; k >>= 1) { if (tid < k) rmax[tid] = max(rmax[tid], rmax[tid+k]); __syncthreads(); }

    float maxf = ord2f(rmax[0]);
    float snk  = sink[h];
    float m    = fmaxf(maxf, snk);

    float tauf;
    unsigned tu;
    if (nb <= TOPKK) {
        tauf = -__builtin_huge_valf();
        tu = 0u;
        float local = 0.f;
        for (int idx = tid; idx < nb; idx += 256)
            local += expf(ord2f(keys[idx]) - m);
        red[tid] = local; __syncthreads();
        for (int k = 128; k > 0; k >>= 1) { if (tid < k) red[tid] += red[tid+k]; __syncthreads(); }
        if (tid == 0) {
            float denom = red[0] + expf(snk - m);
            tau_o[rowid] = tauf; m_o[rowid] = m; iv_o[rowid] = 1.f / denom;
        }
        return;
    }

    if (tid == 0) { s_prefix = 0u; s_k = TOPKK; }
    __syncthreads();

    for (int shift = 24; shift >= 0; shift -= 8) {
        hist[tid] = 0u;
        __syncthreads();
        unsigned pref = s_prefix;
        unsigned himask = (shift == 24) ? 0u : (0xFFFFFFFFu << (shift + 8));
        for (int idx = tid; idx < nb; idx += 256) {
            unsigned u = keys[idx];
            if ((u & himask) == pref) atomicAdd(&hist[(u >> shift) & 255u], 1u);
        }
        __syncthreads();
        if (tid == 0) {
            int kk = s_k; unsigned cum = 0u; int bin = 255;
            for (; bin > 0; bin--) {
                unsigned c = hist[bin];
                if (cum + c >= (unsigned)kk) break;
                cum += c;
            }
            s_prefix = pref | ((unsigned)bin << shift);
            s_k = kk - (int)cum;
        }
        __syncthreads();
    }
    tu = s_prefix;
    tauf = ord2f(tu);

    float local = 0.f;
    for (int idx = tid; idx < nb; idx += 256) {
        unsigned u = keys[idx];
        if (u >= tu) local += expf(ord2f(u) - m);
    }
    red[tid] = local; __syncthreads();
    for (int k = 128; k > 0; k >>= 1) { if (tid < k) red[tid] += red[tid+k]; __syncthreads(); }
    if (tid == 0) {
        float denom = red[0] + expf(snk - m);
        tau_o[rowid] = tauf; m_o[rowid] = m; iv_o[rowid] = 1.f / denom;
    }
}

/* ------------------------------------------------------------------ */
/* o accumulation via HMMA                                            */
/* smem: Phi[0,4608) Plo[4608,9216) KThi[9216,36864) KTlo[36864,64512)*/
/* P: 32 h rows x 64 l (pitch 144); KT: 192 d rows x 64 l (pitch 144) */
/* ------------------------------------------------------------------ */
#define AC_SMEM 64512
__global__ void __launch_bounds__(256) k_accum_mma(
    const float* __restrict__ kvc, const int* __restrict__ bt,
    const int* __restrict__ ctxl, const float* __restrict__ kvnew,
    const float* __restrict__ logits, const float* __restrict__ tau_i,
    const float* __restrict__ m_i, const float* __restrict__ iv_i,
    float* __restrict__ opart)
{
    extern __shared__ char sm[];
    uint32_t smb = smem_u32(sm);
    int chunk = blockIdx.x, n = blockIdx.y;
    int ctx = ctxl[n];
    int tid = threadIdx.x, wid = tid >> 5, lane = tid & 31;

    int mt = wid & 1;          /* h tile (16) */
    int ng = wid >> 1;         /* d group (48) */
    float acc[6][4];
#pragma unroll
    for (int i = 0; i < 6; i++)
#pragma unroll
        for (int j = 0; j < 4; j++) acc[i][j] = 0.f;

    int ph = tid >> 3, pl0 = (tid & 7) * 8;
    float ptau = tau_i[n*HEADS + ph];
    float pm   = m_i[n*HEADS + ph];
    float piv  = iv_i[n*HEADS + ph];

    for (int b8 = 0; b8 < 8; b8++) {
        int b = chunk * 8 + b8;
        int base = b * BS;
        if (base >= ctx) break;
        int blk = bt[n*MAXB + b];
        if (b8) __syncthreads();

        /* probs -> bf16 hi/lo, A operand (h rows, l cols) */
        const float* lsrc = logits + ((size_t)(n*HEADS + ph))*LMAX + base + pl0;
#pragma unroll
        for (int j = 0; j < 8; j += 2) {
            float lg0 = lsrc[j], lg1 = lsrc[j+1];
            float p0 = (lg0 >= ptau) ? (expf(lg0 - pm) * piv) : 0.f;
            float p1 = (lg1 >= ptau) ? (expf(lg1 - pm) * piv) : 0.f;
            __nv_bfloat16 h0 = __float2bfloat16(p0), h1 = __float2bfloat16(p1);
            __nv_bfloat16 l0 = __float2bfloat16(p0 - __bfloat162float(h0));
            __nv_bfloat16 l1 = __float2bfloat16(p1 - __bfloat162float(h1));
            uint32_t off = (uint32_t)(ph * 144 + (pl0 + j) * 2);
            *(uint32_t*)(sm + off)        = pk2(h0, h1);
            *(uint32_t*)(sm + 4608 + off) = pk2(l0, l1);
        }
        /* KV -> transposed bf16 hi/lo, B operand (d rows, l cols) */
#pragma unroll
        for (int it = 0; it < 6; it++) {
            int task = tid + it * 256;             /* < 1536 */
            int dg = task % 48, lp = task / 48;
            int r0 = 2*lp, r1 = 2*lp + 1;
            const float* s0 = (base + r0 == ctx-1) ? (kvnew + (size_t)n*HDIM)
                                                   : (kvc + ((size_t)blk*BS + r0)*HDIM);
            const float* s1 = (base + r1 == ctx-1) ? (kvnew + (size_t)n*HDIM)
                                                   : (kvc + ((size_t)blk*BS + r1)*HDIM);
            float4 v0 = ((const float4*)s0)[dg];
            float4 v1 = ((const float4*)s1)[dg];
            float a0[4] = {v0.x, v0.y, v0.z, v0.w};
            float a1[4] = {v1.x, v1.y, v1.z, v1.w};
#pragma unroll
            for (int j = 0; j < 4; j++) {
                int d = dg * 4 + j;
                __nv_bfloat16 h0 = __float2bfloat16(a0[j]), h1 = __float2bfloat16(a1[j]);
                __nv_bfloat16 l0 = __float2bfloat16(a0[j] - __bfloat162float(h0));
                __nv_bfloat16 l1 = __float2bfloat16(a1[j] - __bfloat162float(h1));
                uint32_t off = (uint32_t)(d * 144 + lp * 4);
                *(uint32_t*)(sm + 9216 + off)  = pk2(h0, h1);
                *(uint32_t*)(sm + 36864 + off) = pk2(l0, l1);
            }
        }
        __syncthreads();

#pragma unroll
        for (int ks = 0; ks < 4; ks++) {
            uint32_t ah[4], al[4];
            int arow = mt * 16 + (lane & 15);
            uint32_t aoff = (uint32_t)(arow * 144 + ks * 32 + (lane >> 4) * 16);
            ldm_x4(ah, smb + aoff);
            ldm_x4(al, smb + 4608 + aoff);
#pragma unroll
            for (int t = 0; t < 3; t++) {
                int brow = ng * 48 + t * 16 + ((lane >> 4) & 1) * 8 + (lane & 7);
                uint32_t boff = (uint32_t)(brow * 144 + ks * 32 + ((lane >> 3) & 1) * 16);
                uint32_t bh[4], bl[4];
                ldm_x4(bh, smb + 9216 + boff);
                ldm_x4(bl, smb + 36864 + boff);
                mma16816(acc[2*t],   ah, bh);
                mma16816(acc[2*t],   ah, bl);
                mma16816(acc[2*t],   al, bh);
                mma16816(acc[2*t+1], ah, bh + 2);
                mma16816(acc[2*t+1], ah, bl + 2);
                mma16816(acc[2*t+1], al, bh + 2);
            }
        }
    }

    float* dst = opart + ((size_t)(chunk * NB + n)) * HEADS * HDIM;
#pragma unroll
    for (int t6 = 0; t6 < 6; t6++) {
        int d = ng * 48 + t6 * 8 + (lane & 3) * 2;
        int h = mt * 16 + (lane >> 2);
        dst[(size_t)h * HDIM + d]           = acc[t6][0];
        dst[(size_t)h * HDIM + d + 1]       = acc[t6][1];
        dst[(size_t)(h + 8) * HDIM + d]     = acc[t6][2];
        dst[(size_t)(h + 8) * HDIM + d + 1] = acc[t6][3];
    }
}

__global__ void k_reduce_o(const float* __restrict__ opart, float* __restrict__ o)
{
    int idx = blockIdx.x*256 + threadIdx.x;
    float s = 0.f;
#pragma unroll
    for (int c = 0; c < 8; c++) s += opart[(size_t)c*NB*QDIM + idx];
    o[idx] = s;
}

/* ------------------------------------------------------------------ */
/* host launcher                                                      */
/* ------------------------------------------------------------------ */
extern "C" void kernel_launch(void* const* d_in, const int* in_sizes, int n_in,
                              void* d_out, int out_size)
{
    const float* x    = (const float*)d_in[0];
    const float* kvc  = (const float*)d_in[1];
    const int*   bt   = (const int*)  d_in[2];
    const int*   ctxl = (const int*)  d_in[3];
    const float* wqa  = (const float*)d_in[5];
    const float* qnw  = (const float*)d_in[6];
    const float* wqb  = (const float*)d_in[7];
    const float* wkv  = (const float*)d_in[8];
    const float* kvnw = (const float*)d_in[9];
    const float* woa  = (const float*)d_in[10];
    const float* wob  = (const float*)d_in[11];
    const float* sink = (const float*)d_in[12];
    float* out = (float*)d_out;

    float *qa, *kv, *qq, *lg, *tau, *mr, *iv, *op, *oo, *lat, *part;
    __nv_bfloat16 *qhi, *qlo;
    cudaGetSymbolAddress((void**)&qa,   g_qa);
    cudaGetSymbolAddress((void**)&kv,   g_kv);
    cudaGetSymbolAddress((void**)&qq,   g_q);
    cudaGetSymbolAddress((void**)&qhi,  g_qhi);
    cudaGetSymbolAddress((void**)&qlo,  g_qlo);
    cudaGetSymbolAddress((void**)&lg,   g_logits);
    cudaGetSymbolAddress((void**)&tau,  g_tau);
    cudaGetSymbolAddress((void**)&mr,   g_mrow);
    cudaGetSymbolAddress((void**)&iv,   g_invden);
    cudaGetSymbolAddress((void**)&op,   g_opart);
    cudaGetSymbolAddress((void**)&oo,   g_o);
    cudaGetSymbolAddress((void**)&lat,  g_lat);
    cudaGetSymbolAddress((void**)&part, g_part);

    cudaFuncSetAttribute(k_gemm_mma,   cudaFuncAttributeMaxDynamicSharedMemorySize, MM_SMEM);
    cudaFuncSetAttribute(k_logits_mma, cudaFuncAttributeMaxDynamicSharedMemorySize, LG_SMEM);
    cudaFuncSetAttribute(k_accum_mma,  cudaFuncAttributeMaxDynamicSharedMemorySize, AC_SMEM);

    /* ---- q_a = x @ wq_a^T : N=1536, K=4096, split 8 ---- */
    k_gemm_mma<<<dim3(12, 8, 1), 256, MM_SMEM>>>(
        x, DIMX, 0, wqa, DIMX, 0,
        part, QLRK, 0, (long long)64*QLRK, 512, QLRK);
    k_reduce<<<(64*QLRK+255)/256, 256>>>(part, qa, 64*QLRK, 8);

    /* ---- kv = x @ wkv^T : N=192, K=4096, split 16 ---- */
    k_gemm_mma<<<dim3(2, 16, 1), 256, MM_SMEM>>>(
        x, DIMX, 0, wkv, DIMX, 0,
        part, HDIM, 0, (long long)64*HDIM, 256, HDIM);
    k_reduce<<<(64*HDIM+255)/256, 256>>>(part, kv, 64*HDIM, 16);

    k_rms_qa<<<NB, 256>>>(qa, qnw);
    k_kv_finish<<<NB, 64>>>(kv, kvnw, ctxl);

    /* ---- q = qa_n @ wq_b^T : N=6144, K=1536, split 3 ---- */
    k_gemm_mma<<<dim3(48, 3, 1), 256, MM_SMEM>>>(
        qa, QLRK, 0, wqb, QLRK, 0,
        part, QDIM, 0, (long long)64*QDIM, 512, QDIM);
    k_reduce<<<(64*QDIM+255)/256, 256>>>(part, qq, 64*QDIM, 3);
    k_rope_q<<<NB, 256>>>(qq, ctxl);
    k_q2bf<<<NB*QDIM/1024, 256>>>(qq, qhi, qlo);

    /* ---- attention ---- */
    k_logits_mma<<<dim3(MAXB, NB), 256, LG_SMEM>>>(kvc, bt, ctxl, qhi, qlo, kv, lg);
    k_select<<<NB*HEADS, 256>>>(lg, sink, ctxl, tau, mr, iv);
    k_accum_mma<<<dim3(8, NB), 256, AC_SMEM>>>(kvc, bt, ctxl, kv, lg, tau, mr, iv, op);
    k_reduce_o<<<NB*QDIM/256, 256>>>(op, oo);

    /* ---- lat = grouped wo_a : per-group N=512, K=768, split 4 ---- */
    k_gemm_mma<<<dim3(4, 4, GRP), 256, MM_SMEM>>>(
        oo, QDIM, 768, woa, 768, (long long)OLRK*768,
        part, GRP*OLRK, OLRK, (long long)64*GRP*OLRK, 192, OLRK);
    k_reduce<<<(64*GRP*OLRK+255)/256, 256>>>(part, lat, 64*GRP*OLRK, 4);

    /* ---- out = lat @ wo_b^T : N=4096, K=4096, split 4 ---- */
    k_gemm_mma<<<dim3(32, 4, 1), 256, MM_SMEM>>>(
        lat, GRP*OLRK, 0, wob, DIMX, 0,
        part, DIMX, 0, (long long)64*DIMX, 1024, DIMX);
    k_reduce<<<(64*DIMX+255)/256, 256>>>(part, out, 64*DIMX, 4);
}

// round 6
// speedup vs baseline: 3.5507x; 1.0239x over previous
#include <cuda_runtime.h>
#include <cuda_bf16.h>
#include <math.h>
#include <stdint.h>

#define NB    64
#define DIMX  4096
#define HEADS 32
#define HDIM  192
#define RDIM  64
#define QLRK  1536
#define OLRK  512
#define GRP   8
#define BS    64
#define MAXB  64
#define LMAX  4096
#define TOPKK 1024
#define EPSI  1e-6f
#define NEGF  -1e30f
#define QDIM  (HEADS*HDIM)   /* 6144 */
#define SCALE_F 0.07216878364870323f  /* 192^-0.5 */

/* ------------------------------------------------------------------ */
/* scratch                                                            */
/* ------------------------------------------------------------------ */
__device__ float g_qa[NB*QLRK];
__device__ float g_kv[NB*HDIM];
__device__ __nv_bfloat16 g_qhi[NB*QDIM];
__device__ __nv_bfloat16 g_qlo[NB*QDIM];
__device__ float g_logits[(size_t)NB*HEADS*LMAX];       /* 32 MB */
__device__ float g_tau[NB*HEADS];
__device__ float g_mrow[NB*HEADS];
__device__ float g_invden[NB*HEADS];
__device__ float g_opart[(size_t)8*NB*HEADS*HDIM];      /* 12.6 MB */
__device__ float g_o[NB*QDIM];
__device__ float g_lat[NB*GRP*OLRK];
__device__ float g_part[1179648];                       /* split-K partials */

/* ------------------------------------------------------------------ */
/* helpers                                                            */
/* ------------------------------------------------------------------ */
__device__ __forceinline__ uint32_t smem_u32(const void* p){
    uint32_t a;
    asm("{ .reg .u64 t; cvta.to.shared.u64 t, %1; cvt.u32.u64 %0, t; }"
        : "=r"(a) : "l"(p));
    return a;
}
__device__ __forceinline__ uint32_t sw128(uint32_t b){ return b ^ ((b >> 3) & 0x70); }
__device__ __forceinline__ uint32_t pk2(__nv_bfloat16 a, __nv_bfloat16 b){
    __nv_bfloat162 t(a, b);
    return *reinterpret_cast<uint32_t*>(&t);
}
__device__ __forceinline__ void mma16816(float* c, const uint32_t* a, const uint32_t* b){
    asm volatile("mma.sync.aligned.m16n8k16.row.col.f32.bf16.bf16.f32 "
        "{%0,%1,%2,%3}, {%4,%5,%6,%7}, {%8,%9}, {%0,%1,%2,%3};"
        : "+f"(c[0]), "+f"(c[1]), "+f"(c[2]), "+f"(c[3])
        : "r"(a[0]), "r"(a[1]), "r"(a[2]), "r"(a[3]), "r"(b[0]), "r"(b[1]));
}
__device__ __forceinline__ void ldm_x4(uint32_t* r, uint32_t addr){
    asm volatile("ldmatrix.sync.aligned.m8n8.x4.shared.b16 {%0,%1,%2,%3}, [%4];"
        : "=r"(r[0]), "=r"(r[1]), "=r"(r[2]), "=r"(r[3]) : "r"(addr));
}
__device__ __forceinline__ void ldm_x4t(uint32_t* r, uint32_t addr){
    asm volatile("ldmatrix.sync.aligned.m8n8.x4.trans.shared.b16 {%0,%1,%2,%3}, [%4];"
        : "=r"(r[0]), "=r"(r[1]), "=r"(r[2]), "=r"(r[3]) : "r"(addr));
}
__device__ __forceinline__ void cvt_store(char* hiB, char* loB, uint32_t off, float4 v){
    __nv_bfloat16 hx = __float2bfloat16(v.x), hy = __float2bfloat16(v.y);
    __nv_bfloat16 hz = __float2bfloat16(v.z), hw = __float2bfloat16(v.w);
    __nv_bfloat16 lx = __float2bfloat16(v.x - __bfloat162float(hx));
    __nv_bfloat16 ly = __float2bfloat16(v.y - __bfloat162float(hy));
    __nv_bfloat16 lz = __float2bfloat16(v.z - __bfloat162float(hz));
    __nv_bfloat16 lw = __float2bfloat16(v.w - __bfloat162float(hw));
    uint2 hh; hh.x = pk2(hx, hy); hh.y = pk2(hz, hw);
    uint2 ll; ll.x = pk2(lx, ly); ll.y = pk2(lz, lw);
    *(uint2*)(hiB + off) = hh;
    *(uint2*)(loB + off) = ll;
}
__device__ __forceinline__ void hilo(float v, __nv_bfloat16& h, __nv_bfloat16& l){
    h = __float2bfloat16(v);
    l = __float2bfloat16(v - __bfloat162float(h));
}

/* ------------------------------------------------------------------ */
/* HMMA GEMM (dense projections)                                      */
/* ------------------------------------------------------------------ */
#define MM_SMEM 49152
__global__ void __launch_bounds__(256,1) k_gemm_mma(
    const float* __restrict__ X, int ldx, long long xGrp,
    const float* __restrict__ W, int ldw, long long wGrp,
    float* __restrict__ C, int ldc, long long cGrp, long long cSplit,
    int Kloc, int Nw)
{
    extern __shared__ char sm[];
    char* sXhi = sm;
    char* sXlo = sm + 8192;
    char* sWhi = sm + 16384;
    char* sWlo = sm + 32768;
    uint32_t smb = smem_u32(sm);

    int tid = threadIdx.x, wid = tid >> 5, lane = tid & 31;
    int n0 = blockIdx.x * 128;
    int s  = blockIdx.y;
    int g  = blockIdx.z;
    X += (size_t)g * xGrp + (size_t)s * Kloc;
    W += (size_t)g * wGrp + (size_t)s * Kloc;
    C += (size_t)g * cGrp + (size_t)s * cSplit;

    int wm = (wid & 3) * 16;
    int wn = (wid >> 2) * 64;

    float acc[8][4];
#pragma unroll
    for (int i = 0; i < 8; i++)
#pragma unroll
        for (int j = 0; j < 4; j++) acc[i][j] = 0.f;

    int xrow = tid >> 2;
    int xc   = tid & 3;
    int wrow = tid >> 1;
    int wc   = tid & 1;
    int wrg  = n0 + wrow; if (wrg >= Nw) wrg = Nw - 1;

    const int NC = Kloc / 64;
    float4 xv[4], wv[8];
#pragma unroll
    for (int j = 0; j < 4; j++)
        xv[j] = *(const float4*)(X + (size_t)xrow * ldx + (xc + 4*j) * 4);
#pragma unroll
    for (int j = 0; j < 8; j++)
        wv[j] = *(const float4*)(W + (size_t)wrg * ldw + (wc + 2*j) * 4);

    for (int ch = 0; ch < NC; ch++) {
        if (ch) __syncthreads();
#pragma unroll
        for (int j = 0; j < 4; j++) {
            uint32_t off = sw128((uint32_t)(xrow * 128 + (xc + 4*j) * 8));
            cvt_store(sXhi, sXlo, off, xv[j]);
        }
#pragma unroll
        for (int j = 0; j < 8; j++) {
            uint32_t off = sw128((uint32_t)(wrow * 128 + (wc + 2*j) * 8));
            cvt_store(sWhi, sWlo, off, wv[j]);
        }
        __syncthreads();
        if (ch + 1 < NC) {
            int kb = (ch + 1) * 64;
#pragma unroll
            for (int j = 0; j < 4; j++)
                xv[j] = *(const float4*)(X + (size_t)xrow * ldx + kb + (xc + 4*j) * 4);
#pragma unroll
            for (int j = 0; j < 8; j++)
                wv[j] = *(const float4*)(W + (size_t)wrg * ldw + kb + (wc + 2*j) * 4);
        }
#pragma unroll
        for (int ks = 0; ks < 4; ks++) {
            uint32_t ah[4], al[4];
            {
                int arow = wm + (lane & 15);
                uint32_t aoff = sw128((uint32_t)(arow * 128 + (ks*2 + (lane >> 4)) * 16));
                ldm_x4(ah, smb + aoff);
                ldm_x4(al, smb + 8192 + aoff);
            }
#pragma unroll
            for (int t = 0; t < 4; t++) {
                int brow = wn + 16*t + ((lane >> 4) & 1) * 8 + (lane & 7);
                uint32_t boff = sw128((uint32_t)(brow * 128 + (ks*2 + ((lane >> 3) & 1)) * 16));
                uint32_t bh[4], bl[4];
                ldm_x4(bh, smb + 16384 + boff);
                ldm_x4(bl, smb + 32768 + boff);
                mma16816(acc[2*t],   ah, bh);
                mma16816(acc[2*t],   ah, bl);
                mma16816(acc[2*t],   al, bh);
                mma16816(acc[2*t+1], ah, bh + 2);
                mma16816(acc[2*t+1], ah, bl + 2);
                mma16816(acc[2*t+1], al, bh + 2);
            }
        }
    }

    int mr = wm + (lane >> 2);
#pragma unroll
    for (int sub = 0; sub < 8; sub++) {
        int nc = n0 + wn + sub * 8 + (lane & 3) * 2;
        if (nc < Nw) {
            C[(size_t)mr * ldc + nc]       = acc[sub][0];
            C[(size_t)(mr + 8) * ldc + nc] = acc[sub][2];
        }
        if (nc + 1 < Nw) {
            C[(size_t)mr * ldc + nc + 1]       = acc[sub][1];
            C[(size_t)(mr + 8) * ldc + nc + 1] = acc[sub][3];
        }
    }
}

/* generic split-K reduce (for wo_a, wo_b) */
__global__ void k_reduce(const float* __restrict__ part, float* __restrict__ out,
                         int E, int S)
{
    int i = blockIdx.x * 256 + threadIdx.x;
    if (i >= E) return;
    float s = 0.f;
    for (int p = 0; p < S; p++) s += part[(size_t)p * E + i];
    out[i] = s;
}

/* ------------------------------------------------------------------ */
/* fused: reduce 8 partials + RMS(q_norm) -> g_qa                     */
/* ------------------------------------------------------------------ */
__global__ void __launch_bounds__(256) k_fuse_qa(const float* __restrict__ part,
                                                 const float* __restrict__ wt,
                                                 float* __restrict__ qa)
{
    __shared__ float red[256];
    int n = blockIdx.x, tid = threadIdx.x;
    float v[6]; float s = 0.f;
#pragma unroll
    for (int i = 0; i < 6; i++) {
        int c = tid + i*256;
        float t = 0.f;
#pragma unroll
        for (int p = 0; p < 8; p++) t += part[(size_t)p*NB*QLRK + (size_t)n*QLRK + c];
        v[i] = t; s += t*t;
    }
    red[tid] = s; __syncthreads();
    for (int k = 128; k > 0; k >>= 1) { if (tid < k) red[tid] += red[tid+k]; __syncthreads(); }
    float scale = rsqrtf(red[0] / (float)QLRK + EPSI);
#pragma unroll
    for (int i = 0; i < 6; i++) {
        int c = tid + i*256;
        qa[(size_t)n*QLRK + c] = v[i] * scale * wt[c];
    }
}

__device__ __forceinline__ void rope_cs(int i, float pos, float& c, float& s)
{
    float inv = (float)exp(-(double)i * 0.28782313662425574); /* ln(1e4)/32 */
    float ang = pos * inv;
    double ad = (double)ang;
    c = (float)cos(ad); s = (float)sin(ad);
}

/* fused: reduce 16 partials + RMS + rope -> g_kv */
__global__ void k_fuse_kv(const float* __restrict__ part,
                          const float* __restrict__ wt,
                          const int* __restrict__ ctxl,
                          float* __restrict__ kv)
{
    __shared__ float srow[HDIM];
    __shared__ float rs[64];
    int n = blockIdx.x, tid = threadIdx.x;  /* 64 threads */
    float s = 0.f;
#pragma unroll
    for (int j = 0; j < 3; j++) {
        int c = tid + j*64;
        float t = 0.f;
#pragma unroll
        for (int p = 0; p < 16; p++) t += part[(size_t)p*NB*HDIM + (size_t)n*HDIM + c];
        srow[c] = t; s += t*t;
    }
    rs[tid] = s; __syncthreads();
    for (int k = 32; k > 0; k >>= 1) { if (tid < k) rs[tid] += rs[tid+k]; __syncthreads(); }
    float scale = rsqrtf(rs[0] / (float)HDIM + EPSI);
#pragma unroll
    for (int j = 0; j < 3; j++) { int i = tid + j*64; srow[i] = srow[i]*scale*wt[i]; }
    __syncthreads();
    float pos = (float)(ctxl[n] - 1);
    if (tid < 32) {
        int i = tid;
        float x0 = srow[HDIM-RDIM + 2*i], x1 = srow[HDIM-RDIM + 2*i + 1];
        float c, sn; rope_cs(i, pos, c, sn);
        srow[HDIM-RDIM + 2*i]     = x0*c - x1*sn;
        srow[HDIM-RDIM + 2*i + 1] = x0*sn + x1*c;
    }
    __syncthreads();
#pragma unroll
    for (int j = 0; j < 3; j++) { int i = tid + j*64; kv[(size_t)n*HDIM + i] = srow[i]; }
}

/* fused: reduce 3 partials + rope + bf16 hi/lo split -> g_qhi/g_qlo  */
__global__ void __launch_bounds__(256) k_fuse_q(const float* __restrict__ part,
                                                const int* __restrict__ ctxl,
                                                __nv_bfloat16* __restrict__ qhi,
                                                __nv_bfloat16* __restrict__ qlo)
{
    int n = blockIdx.x, tid = threadIdx.x;
    float pos = (float)(ctxl[n] - 1);
#pragma unroll
    for (int i = 0; i < 12; i++) {
        int p = tid + i*256;                 /* pair index < 3072 */
        int e0 = 2*p;
        float v0 = 0.f, v1 = 0.f;
#pragma unroll
        for (int q = 0; q < 3; q++) {
            v0 += part[(size_t)q*NB*QDIM + (size_t)n*QDIM + e0];
            v1 += part[(size_t)q*NB*QDIM + (size_t)n*QDIM + e0 + 1];
        }
        int dd = e0 % HDIM;
        if (dd >= HDIM - RDIM) {
            int ir = (dd - (HDIM - RDIM)) >> 1;
            float c, s; rope_cs(ir, pos, c, s);
            float x0 = v0, x1 = v1;
            v0 = x0*c - x1*s;
            v1 = x0*s + x1*c;
        }
        __nv_bfloat16 h0, l0, h1, l1;
        hilo(v0, h0, l0); hilo(v1, h1, l1);
        ((uint32_t*)qhi)[(size_t)n*(QDIM/2) + p] = pk2(h0, h1);
        ((uint32_t*)qlo)[(size_t)n*(QDIM/2) + p] = pk2(l0, l1);
    }
}

/* ------------------------------------------------------------------ */
/* logits via HMMA: CTA = (4-block group, batch n)                    */
/* smem: Qhi[0,12800) Qlo[12800,25600) KVhi[25600,51200) KVlo[51200,76800) */
/* D staging reuses KV area after MMA                                 */
/* ------------------------------------------------------------------ */
#define LG_SMEM 76800
__global__ void __launch_bounds__(256) k_logits_mma(
    const float* __restrict__ kvc, const int* __restrict__ bt,
    const int* __restrict__ ctxl,
    const __nv_bfloat16* __restrict__ qhi, const __nv_bfloat16* __restrict__ qlo,
    const float* __restrict__ kvnew, float* __restrict__ logits)
{
    extern __shared__ char sm[];
    uint32_t smb = smem_u32(sm);
    int n = blockIdx.y;
    int ctx = ctxl[n];
    int b0 = blockIdx.x * 4;
    if (b0 * BS >= ctx) return;
    int tid = threadIdx.x, wid = tid >> 5, lane = tid & 31;

    /* Q hi/lo: 32 rows x 384B -> pitch 400 (loaded once) */
    {
        const char* gh = (const char*)(qhi + (size_t)n * QDIM);
        const char* gl = (const char*)(qlo + (size_t)n * QDIM);
#pragma unroll
        for (int i = 0; i < 3; i++) {
            int c = tid + i * 256;
            int r = c / 24, k16 = c % 24;
            *(uint4*)(sm + r * 400 + k16 * 16) = *(const uint4*)(gh + r * 384 + k16 * 16);
            *(uint4*)(sm + 12800 + r * 400 + k16 * 16) = *(const uint4*)(gl + r * 384 + k16 * 16);
        }
    }

    int mt = wid & 3;       /* l tile: 16 positions */
    int nt = wid >> 2;      /* h tile: 16 heads     */
    int kvrow = tid >> 2, kvqp = tid & 3;

    for (int bi = 0; bi < 4; bi++) {
        int b = b0 + bi;
        int base = b * BS;
        if (base >= ctx) break;
        if (bi) __syncthreads();            /* prior D reads done     */

        int blk = bt[n * MAXB + b];
        {
            int lg = base + kvrow;
            const float* src = (lg == ctx - 1) ? (kvnew + (size_t)n * HDIM)
                                               : (kvc + ((size_t)blk * BS + kvrow) * HDIM);
#pragma unroll
            for (int j = 0; j < 12; j++) {
                int d4 = kvqp * 12 + j;
                float4 v = ((const float4*)src)[d4];
                cvt_store(sm + 25600, sm + 51200, (uint32_t)(kvrow * 400 + d4 * 8), v);
            }
        }
        __syncthreads();

        float acc[2][4];
#pragma unroll
        for (int i = 0; i < 2; i++)
#pragma unroll
            for (int j = 0; j < 4; j++) acc[i][j] = 0.f;

#pragma unroll
        for (int ks = 0; ks < 12; ks++) {
            uint32_t ah[4], al[4];
            int arow = mt * 16 + (lane & 15);
            uint32_t aoff = (uint32_t)(arow * 400 + ks * 32 + (lane >> 4) * 16);
            ldm_x4(ah, smb + 25600 + aoff);
            ldm_x4(al, smb + 51200 + aoff);
            int brow = nt * 16 + ((lane >> 4) & 1) * 8 + (lane & 7);
            uint32_t boff = (uint32_t)(brow * 400 + ks * 32 + ((lane >> 3) & 1) * 16);
            uint32_t bh[4], bl[4];
            ldm_x4(bh, smb + boff);
            ldm_x4(bl, smb + 12800 + boff);
            mma16816(acc[0], ah, bh);
            mma16816(acc[0], ah, bl);
            mma16816(acc[0], al, bh);
            mma16816(acc[1], ah, bh + 2);
            mma16816(acc[1], ah, bl + 2);
            mma16816(acc[1], al, bh + 2);
        }
        __syncthreads();                    /* KV reads done -> D ok  */

        float* D = (float*)(sm + 25600);
#pragma unroll
        for (int n8 = 0; n8 < 2; n8++) {
            int h = nt * 16 + n8 * 8 + (lane & 3) * 2;
            int l = mt * 16 + (lane >> 2);
            D[h * 64 + l]           = acc[n8][0];
            D[(h + 1) * 64 + l]     = acc[n8][1];
            D[h * 64 + l + 8]       = acc[n8][2];
            D[(h + 1) * 64 + l + 8] = acc[n8][3];
        }
        __syncthreads();
        int h = tid >> 3, l0 = (tid & 7) * 8;
        float* dst = logits + ((size_t)(n * HEADS + h)) * LMAX + base + l0;
#pragma unroll
        for (int j = 0; j < 8; j++) {
            int l = l0 + j;
            float v = D[h * 64 + l];
            dst[j] = (base + l < ctx) ? v * SCALE_F : NEGF;
        }
    }
}

/* ------------------------------------------------------------------ */
/* top-k radix select (variable length)                               */
/* ------------------------------------------------------------------ */
__device__ __forceinline__ unsigned f2ord(float f) {
    unsigned b = __float_as_uint(f);
    return (b & 0x80000000u) ? ~b : (b | 0x80000000u);
}
__device__ __forceinline__ float ord2f(unsigned u) {
    return (u & 0x80000000u) ? __uint_as_float(u ^ 0x80000000u)
                             : __uint_as_float(~u);
}

__global__ void __launch_bounds__(256) k_select(
    const float* __restrict__ logits, const float* __restrict__ sink,
    const int* __restrict__ ctxl,
    float* __restrict__ tau_o, float* __restrict__ m_o, float* __restrict__ iv_o)
{
    __shared__ unsigned keys[LMAX];
    __shared__ unsigned hist[256];
    __shared__ unsigned rmax[256];
    __shared__ float    red[256];
    __shared__ unsigned s_prefix;
    __shared__ int      s_k;

    int rowid = blockIdx.x;
    int n = rowid >> 5;
    int h = rowid & 31;
    int tid = threadIdx.x;
    int ctx = ctxl[n];
    int nb = ((ctx + 63) >> 6) << 6;
    const float* src = logits + (size_t)rowid * LMAX;

    unsigned um = 0u;
    for (int idx = tid; idx < nb; idx += 256) {
        unsigned u = f2ord(src[idx]);
        keys[idx] = u;
        um = max(um, u);
    }
    rmax[tid] = um; __syncthreads();
    for (int k = 128; k > 0; k >>= 1) { if (tid < k) rmax[tid] = max(rmax[tid], rmax[tid+k]); __syncthreads(); }

    float maxf = ord2f(rmax[0]);
    float snk  = sink[h];
    float m    = fmaxf(maxf, snk);

    if (nb <= TOPKK) {
        float local = 0.f;
        for (int idx = tid; idx < nb; idx += 256)
            local += expf(ord2f(keys[idx]) - m);
        red[tid] = local; __syncthreads();
        for (int k = 128; k > 0; k >>= 1) { if (tid < k) red[tid] += red[tid+k]; __syncthreads(); }
        if (tid == 0) {
            float denom = red[0] + expf(snk - m);
            tau_o[rowid] = -__builtin_huge_valf(); m_o[rowid] = m; iv_o[rowid] = 1.f / denom;
        }
        return;
    }

    if (tid == 0) { s_prefix = 0u; s_k = TOPKK; }
    __syncthreads();

    for (int shift = 24; shift >= 0; shift -= 8) {
        hist[tid] = 0u;
        __syncthreads();
        unsigned pref = s_prefix;
        unsigned himask = (shift == 24) ? 0u : (0xFFFFFFFFu << (shift + 8));
        for (int idx = tid; idx < nb; idx += 256) {
            unsigned u = keys[idx];
            if ((u & himask) == pref) atomicAdd(&hist[(u >> shift) & 255u], 1u);
        }
        __syncthreads();
        if (tid == 0) {
            int kk = s_k; unsigned cum = 0u; int bin = 255;
            for (; bin > 0; bin--) {
                unsigned c = hist[bin];
                if (cum + c >= (unsigned)kk) break;
                cum += c;
            }
            s_prefix = pref | ((unsigned)bin << shift);
            s_k = kk - (int)cum;
        }
        __syncthreads();
    }
    unsigned tu = s_prefix;

    float local = 0.f;
    for (int idx = tid; idx < nb; idx += 256) {
        unsigned u = keys[idx];
        if (u >= tu) local += expf(ord2f(u) - m);
    }
    red[tid] = local; __syncthreads();
    for (int k = 128; k > 0; k >>= 1) { if (tid < k) red[tid] += red[tid+k]; __syncthreads(); }
    if (tid == 0) {
        float denom = red[0] + expf(snk - m);
        tau_o[rowid] = ord2f(tu); m_o[rowid] = m; iv_o[rowid] = 1.f / denom;
    }
}

/* ------------------------------------------------------------------ */
/* o accumulation via HMMA + ldmatrix.trans (no transpose store)      */
/* smem: Phi[0,4608) Plo[4608,9216) pitch 144 (32 h rows x 64 l)      */
/*       KVhi[9216,34816) KVlo[34816,60416) natural [l][d], pitch 400 */
/* ------------------------------------------------------------------ */
#define AC_SMEM 60416
__global__ void __launch_bounds__(256) k_accum_mma(
    const float* __restrict__ kvc, const int* __restrict__ bt,
    const int* __restrict__ ctxl, const float* __restrict__ kvnew,
    const float* __restrict__ logits, const float* __restrict__ tau_i,
    const float* __restrict__ m_i, const float* __restrict__ iv_i,
    float* __restrict__ opart)
{
    extern __shared__ char sm[];
    uint32_t smb = smem_u32(sm);
    int chunk = blockIdx.x, n = blockIdx.y;
    int ctx = ctxl[n];
    int tid = threadIdx.x, wid = tid >> 5, lane = tid & 31;

    int mt = wid & 1;          /* h tile (16) */
    int ng = wid >> 1;         /* d group (48) */
    float acc[6][4];
#pragma unroll
    for (int i = 0; i < 6; i++)
#pragma unroll
        for (int j = 0; j < 4; j++) acc[i][j] = 0.f;

    int ph = tid >> 3, pl0 = (tid & 7) * 8;
    float ptau = tau_i[n*HEADS + ph];
    float pm   = m_i[n*HEADS + ph];
    float piv  = iv_i[n*HEADS + ph];
    int kvrow = tid >> 2, kvqp = tid & 3;

    for (int b8 = 0; b8 < 8; b8++) {
        int b = chunk * 8 + b8;
        int base = b * BS;
        if (base >= ctx) break;
        int blk = bt[n*MAXB + b];
        if (b8) __syncthreads();

        /* probs -> bf16 hi/lo (A operand) */
        const float* lsrc = logits + ((size_t)(n*HEADS + ph))*LMAX + base + pl0;
#pragma unroll
        for (int j = 0; j < 8; j += 2) {
            float lg0 = lsrc[j], lg1 = lsrc[j+1];
            float p0 = (lg0 >= ptau) ? (expf(lg0 - pm) * piv) : 0.f;
            float p1 = (lg1 >= ptau) ? (expf(lg1 - pm) * piv) : 0.f;
            __nv_bfloat16 h0, l0, h1, l1;
            hilo(p0, h0, l0); hilo(p1, h1, l1);
            uint32_t off = (uint32_t)(ph * 144 + (pl0 + j) * 2);
            *(uint32_t*)(sm + off)        = pk2(h0, h1);
            *(uint32_t*)(sm + 4608 + off) = pk2(l0, l1);
        }
        /* KV natural layout [l][d] (same conflict-free pattern as logits) */
        {
            int lg = base + kvrow;
            const float* src = (lg == ctx - 1) ? (kvnew + (size_t)n*HDIM)
                                               : (kvc + ((size_t)blk*BS + kvrow)*HDIM);
#pragma unroll
            for (int j = 0; j < 12; j++) {
                int d4 = kvqp * 12 + j;
                float4 v = ((const float4*)src)[d4];
                cvt_store(sm + 9216, sm + 34816, (uint32_t)(kvrow * 400 + d4 * 8), v);
            }
        }
        __syncthreads();

#pragma unroll
        for (int ks = 0; ks < 4; ks++) {
            uint32_t ah[4], al[4];
            int arow = mt * 16 + (lane & 15);
            uint32_t aoff = (uint32_t)(arow * 144 + ks * 32 + (lane >> 4) * 16);
            ldm_x4(ah, smb + aoff);
            ldm_x4(al, smb + 4608 + aoff);
            int l_in = ks * 16 + ((lane >> 3) & 1) * 8 + (lane & 7);
#pragma unroll
            for (int t = 0; t < 3; t++) {
                uint32_t dByte = (uint32_t)((ng * 48 + t * 16) * 2 + ((lane >> 4) & 1) * 16);
                uint32_t boff = (uint32_t)(l_in * 400) + dByte;
                uint32_t bh[4], bl[4];
                ldm_x4t(bh, smb + 9216 + boff);
                ldm_x4t(bl, smb + 34816 + boff);
                mma16816(acc[2*t],   ah, bh);
                mma16816(acc[2*t],   ah, bl);
                mma16816(acc[2*t],   al, bh);
                mma16816(acc[2*t+1], ah, bh + 2);
                mma16816(acc[2*t+1], ah, bl + 2);
                mma16816(acc[2*t+1], al, bh + 2);
            }
        }
    }

    float* dst = opart + ((size_t)(chunk * NB + n)) * HEADS * HDIM;
#pragma unroll
    for (int t6 = 0; t6 < 6; t6++) {
        int d = ng * 48 + t6 * 8 + (lane & 3) * 2;
        int h = mt * 16 + (lane >> 2);
        dst[(size_t)h * HDIM + d]           = acc[t6][0];
        dst[(size_t)h * HDIM + d + 1]       = acc[t6][1];
        dst[(size_t)(h + 8) * HDIM + d]     = acc[t6][2];
        dst[(size_t)(h + 8) * HDIM + d + 1] = acc[t6][3];
    }
}

__global__ void k_reduce_o(const float* __restrict__ opart, float* __restrict__ o)
{
    int idx = blockIdx.x*256 + threadIdx.x;
    float s = 0.f;
#pragma unroll
    for (int c = 0; c < 8; c++) s += opart[(size_t)c*NB*QDIM + idx];
    o[idx] = s;
}

/* ------------------------------------------------------------------ */
/* host launcher                                                      */
/* ------------------------------------------------------------------ */
extern "C" void kernel_launch(void* const* d_in, const int* in_sizes, int n_in,
                              void* d_out, int out_size)
{
    const float* x    = (const float*)d_in[0];
    const float* kvc  = (const float*)d_in[1];
    const int*   bt   = (const int*)  d_in[2];
    const int*   ctxl = (const int*)  d_in[3];
    const float* wqa  = (const float*)d_in[5];
    const float* qnw  = (const float*)d_in[6];
    const float* wqb  = (const float*)d_in[7];
    const float* wkv  = (const float*)d_in[8];
    const float* kvnw = (const float*)d_in[9];
    const float* woa  = (const float*)d_in[10];
    const float* wob  = (const float*)d_in[11];
    const float* sink = (const float*)d_in[12];
    float* out = (float*)d_out;

    float *qa, *kv, *lg, *tau, *mr, *iv, *op, *oo, *lat, *part;
    __nv_bfloat16 *qhi, *qlo;
    cudaGetSymbolAddress((void**)&qa,   g_qa);
    cudaGetSymbolAddress((void**)&kv,   g_kv);
    cudaGetSymbolAddress((void**)&qhi,  g_qhi);
    cudaGetSymbolAddress((void**)&qlo,  g_qlo);
    cudaGetSymbolAddress((void**)&lg,   g_logits);
    cudaGetSymbolAddress((void**)&tau,  g_tau);
    cudaGetSymbolAddress((void**)&mr,   g_mrow);
    cudaGetSymbolAddress((void**)&iv,   g_invden);
    cudaGetSymbolAddress((void**)&op,   g_opart);
    cudaGetSymbolAddress((void**)&oo,   g_o);
    cudaGetSymbolAddress((void**)&lat,  g_lat);
    cudaGetSymbolAddress((void**)&part, g_part);

    cudaFuncSetAttribute(k_gemm_mma,   cudaFuncAttributeMaxDynamicSharedMemorySize, MM_SMEM);
    cudaFuncSetAttribute(k_logits_mma, cudaFuncAttributeMaxDynamicSharedMemorySize, LG_SMEM);
    cudaFuncSetAttribute(k_accum_mma,  cudaFuncAttributeMaxDynamicSharedMemorySize, AC_SMEM);

    /* ---- q_a = x @ wq_a^T : split 8 ---- */
    k_gemm_mma<<<dim3(12, 8, 1), 256, MM_SMEM>>>(
        x, DIMX, 0, wqa, DIMX, 0,
        part, QLRK, 0, (long long)NB*QLRK, 512, QLRK);
    k_fuse_qa<<<NB, 256>>>(part, qnw, qa);

    /* ---- kv = x @ wkv^T : split 16 ---- */
    k_gemm_mma<<<dim3(2, 16, 1), 256, MM_SMEM>>>(
        x, DIMX, 0, wkv, DIMX, 0,
        part, HDIM, 0, (long long)NB*HDIM, 256, HDIM);
    k_fuse_kv<<<NB, 64>>>(part, kvnw, ctxl, kv);

    /* ---- q = qa_n @ wq_b^T : split 3 ---- */
    k_gemm_mma<<<dim3(48, 3, 1), 256, MM_SMEM>>>(
        qa, QLRK, 0, wqb, QLRK, 0,
        part, QDIM, 0, (long long)NB*QDIM, 512, QDIM);
    k_fuse_q<<<NB, 256>>>(part, ctxl, qhi, qlo);

    /* ---- attention ---- */
    k_logits_mma<<<dim3(16, NB), 256, LG_SMEM>>>(kvc, bt, ctxl, qhi, qlo, kv, lg);
    k_select<<<NB*HEADS, 256>>>(lg, sink, ctxl, tau, mr, iv);
    k_accum_mma<<<dim3(8, NB), 256, AC_SMEM>>>(kvc, bt, ctxl, kv, lg, tau, mr, iv, op);
    k_reduce_o<<<NB*QDIM/256, 256>>>(op, oo);

    /* ---- lat = grouped wo_a : split 4 ---- */
    k_gemm_mma<<<dim3(4, 4, GRP), 256, MM_SMEM>>>(
        oo, QDIM, 768, woa, 768, (long long)OLRK*768,
        part, GRP*OLRK, OLRK, (long long)NB*GRP*OLRK, 192, OLRK);
    k_reduce<<<(NB*GRP*OLRK+255)/256, 256>>>(part, lat, NB*GRP*OLRK, 4);

    /* ---- out = lat @ wo_b^T : split 4 ---- */
    k_gemm_mma<<<dim3(32, 4, 1), 256, MM_SMEM>>>(
        lat, GRP*OLRK, 0, wob, DIMX, 0,
        part, DIMX, 0, (long long)NB*DIMX, 1024, DIMX);
    k_reduce<<<(NB*DIMX+255)/256, 256>>>(part, out, NB*DIMX, 4);
}

// round 7
// speedup vs baseline: 3.7606x; 1.0591x over previous
#include <cuda_runtime.h>
#include <cuda_bf16.h>
#include <math.h>
#include <stdint.h>

#define NB    64
#define DIMX  4096
#define HEADS 32
#define HDIM  192
#define RDIM  64
#define QLRK  1536
#define OLRK  512
#define GRP   8
#define BS    64
#define MAXB  64
#define LMAX  4096
#define TOPKK 1024
#define EPSI  1e-6f
#define NEGF  -1e30f
#define QDIM  (HEADS*HDIM)   /* 6144 */
#define SCALE_F 0.07216878364870323f  /* 192^-0.5 */

/* ------------------------------------------------------------------ */
/* scratch                                                            */
/* ------------------------------------------------------------------ */
__device__ __nv_bfloat16 g_xhi[NB*DIMX];
__device__ __nv_bfloat16 g_xlo[NB*DIMX];
__device__ __nv_bfloat16 g_qahi[NB*QLRK];
__device__ __nv_bfloat16 g_qalo[NB*QLRK];
__device__ float g_kv[NB*HDIM];
__device__ __nv_bfloat16 g_qhi[NB*QDIM];
__device__ __nv_bfloat16 g_qlo[NB*QDIM];
__device__ float g_logits[(size_t)NB*HEADS*LMAX];       /* 32 MB */
__device__ float g_tau[NB*HEADS];
__device__ float g_mrow[NB*HEADS];
__device__ float g_invden[NB*HEADS];
__device__ float g_opart[(size_t)8*NB*HEADS*HDIM];      /* 12.6 MB */
__device__ __nv_bfloat16 g_oohi[NB*QDIM];
__device__ __nv_bfloat16 g_oolo[NB*QDIM];
__device__ __nv_bfloat16 g_lathi[NB*GRP*OLRK];
__device__ __nv_bfloat16 g_latlo[NB*GRP*OLRK];
__device__ float g_part[1179648];                       /* split-K partials */

/* ------------------------------------------------------------------ */
/* helpers                                                            */
/* ------------------------------------------------------------------ */
__device__ __forceinline__ uint32_t smem_u32(const void* p){
    uint32_t a;
    asm("{ .reg .u64 t; cvta.to.shared.u64 t, %1; cvt.u32.u64 %0, t; }"
        : "=r"(a) : "l"(p));
    return a;
}
__device__ __forceinline__ uint32_t sw128(uint32_t b){ return b ^ ((b >> 3) & 0x70); }

/* fast exact split: hi = truncate-to-bf16 (bit prefix), lo = rn(v-hi). */
/* returns packed pairs: hp = {lo16: hi(x), hi16: hi(y)}, lp likewise.  */
__device__ __forceinline__ void split2(float x, float y, uint32_t& hp, uint32_t& lp){
    uint32_t bx = __float_as_uint(x), by = __float_as_uint(y);
    uint32_t h;
    asm("prmt.b32 %0, %1, %2, 0x7632;" : "=r"(h) : "r"(bx), "r"(by));
    float fx = __uint_as_float(h << 16);
    float fy = __uint_as_float(h & 0xFFFF0000u);
    float lx = x - fx, ly = y - fy;
    uint32_t l;
    asm("cvt.rn.bf16x2.f32 %0, %1, %2;" : "=r"(l) : "f"(ly), "f"(lx));
    hp = h; lp = l;
}
__device__ __forceinline__ void mma16816(float* c, const uint32_t* a, const uint32_t* b){
    asm volatile("mma.sync.aligned.m16n8k16.row.col.f32.bf16.bf16.f32 "
        "{%0,%1,%2,%3}, {%4,%5,%6,%7}, {%8,%9}, {%0,%1,%2,%3};"
        : "+f"(c[0]), "+f"(c[1]), "+f"(c[2]), "+f"(c[3])
        : "r"(a[0]), "r"(a[1]), "r"(a[2]), "r"(a[3]), "r"(b[0]), "r"(b[1]));
}
__device__ __forceinline__ void ldm_x4(uint32_t* r, uint32_t addr){
    asm volatile("ldmatrix.sync.aligned.m8n8.x4.shared.b16 {%0,%1,%2,%3}, [%4];"
        : "=r"(r[0]), "=r"(r[1]), "=r"(r[2]), "=r"(r[3]) : "r"(addr));
}
__device__ __forceinline__ void ldm_x4t(uint32_t* r, uint32_t addr){
    asm volatile("ldmatrix.sync.aligned.m8n8.x4.trans.shared.b16 {%0,%1,%2,%3}, [%4];"
        : "=r"(r[0]), "=r"(r[1]), "=r"(r[2]), "=r"(r[3]) : "r"(addr));
}
__device__ __forceinline__ void cvt_store(char* hiB, char* loB, uint32_t off, float4 v){
    uint2 hh, ll;
    split2(v.x, v.y, hh.x, ll.x);
    split2(v.z, v.w, hh.y, ll.y);
    *(uint2*)(hiB + off) = hh;
    *(uint2*)(loB + off) = ll;
}

/* ------------------------------------------------------------------ */
/* HMMA GEMM: X pre-converted bf16 hi/lo in gmem; W fp32 (fast split) */
/* ------------------------------------------------------------------ */
#define MM_SMEM 49152
__global__ void __launch_bounds__(256,1) k_gemm_mma(
    const __nv_bfloat16* __restrict__ Xhi, const __nv_bfloat16* __restrict__ Xlo,
    int ldx, long long xGrp,
    const float* __restrict__ W, int ldw, long long wGrp,
    float* __restrict__ C, int ldc, long long cGrp, long long cSplit,
    int Kloc, int Nw)
{
    extern __shared__ char sm[];
    char* sXhi = sm;
    char* sXlo = sm + 8192;
    char* sWhi = sm + 16384;
    char* sWlo = sm + 32768;
    uint32_t smb = smem_u32(sm);

    int tid = threadIdx.x, wid = tid >> 5, lane = tid & 31;
    int n0 = blockIdx.x * 128;
    int s  = blockIdx.y;
    int g  = blockIdx.z;
    Xhi += (size_t)g * xGrp + (size_t)s * Kloc;
    Xlo += (size_t)g * xGrp + (size_t)s * Kloc;
    W   += (size_t)g * wGrp + (size_t)s * Kloc;
    C   += (size_t)g * cGrp + (size_t)s * cSplit;

    int wm = (wid & 3) * 16;
    int wn = (wid >> 2) * 64;

    float acc[8][4];
#pragma unroll
    for (int i = 0; i < 8; i++)
#pragma unroll
        for (int j = 0; j < 4; j++) acc[i][j] = 0.f;

    /* X copy indices: 512 16B-chunks (64 rows x 8), 2 per thread */
    int xr0 = tid >> 3, xr1 = (tid + 256) >> 3;
    int xc16 = tid & 7;
    /* W conversion indices */
    int wrow = tid >> 1;
    int wc   = tid & 1;
    int wrg  = n0 + wrow; if (wrg >= Nw) wrg = Nw - 1;

    const int NC = Kloc / 64;
    uint4 xh[2], xl[2];
    float4 wv[8];
    xh[0] = *(const uint4*)(Xhi + (size_t)xr0 * ldx + xc16 * 8);
    xh[1] = *(const uint4*)(Xhi + (size_t)xr1 * ldx + xc16 * 8);
    xl[0] = *(const uint4*)(Xlo + (size_t)xr0 * ldx + xc16 * 8);
    xl[1] = *(const uint4*)(Xlo + (size_t)xr1 * ldx + xc16 * 8);
#pragma unroll
    for (int j = 0; j < 8; j++)
        wv[j] = *(const float4*)(W + (size_t)wrg * ldw + (wc + 2*j) * 4);

    for (int ch = 0; ch < NC; ch++) {
        if (ch) __syncthreads();
        {
            uint32_t o0 = sw128((uint32_t)(xr0 * 128 + xc16 * 16));
            uint32_t o1 = sw128((uint32_t)(xr1 * 128 + xc16 * 16));
            *(uint4*)(sXhi + o0) = xh[0];
            *(uint4*)(sXhi + o1) = xh[1];
            *(uint4*)(sXlo + o0) = xl[0];
            *(uint4*)(sXlo + o1) = xl[1];
        }
#pragma unroll
        for (int j = 0; j < 8; j++) {
            uint32_t off = sw128((uint32_t)(wrow * 128 + (wc + 2*j) * 8));
            cvt_store(sWhi, sWlo, off, wv[j]);
        }
        __syncthreads();
        if (ch + 1 < NC) {
            int kb = (ch + 1) * 64;
            xh[0] = *(const uint4*)(Xhi + (size_t)xr0 * ldx + kb + xc16 * 8);
            xh[1] = *(const uint4*)(Xhi + (size_t)xr1 * ldx + kb + xc16 * 8);
            xl[0] = *(const uint4*)(Xlo + (size_t)xr0 * ldx + kb + xc16 * 8);
            xl[1] = *(const uint4*)(Xlo + (size_t)xr1 * ldx + kb + xc16 * 8);
#pragma unroll
            for (int j = 0; j < 8; j++)
                wv[j] = *(const float4*)(W + (size_t)wrg * ldw + kb + (wc + 2*j) * 4);
        }
#pragma unroll
        for (int ks = 0; ks < 4; ks++) {
            uint32_t ah[4], al[4];
            {
                int arow = wm + (lane & 15);
                uint32_t aoff = sw128((uint32_t)(arow * 128 + (ks*2 + (lane >> 4)) * 16));
                ldm_x4(ah, smb + aoff);
                ldm_x4(al, smb + 8192 + aoff);
            }
#pragma unroll
            for (int t = 0; t < 4; t++) {
                int brow = wn + 16*t + ((lane >> 4) & 1) * 8 + (lane & 7);
                uint32_t boff = sw128((uint32_t)(brow * 128 + (ks*2 + ((lane >> 3) & 1)) * 16));
                uint32_t bh[4], bl[4];
                ldm_x4(bh, smb + 16384 + boff);
                ldm_x4(bl, smb + 32768 + boff);
                mma16816(acc[2*t],   ah, bh);
                mma16816(acc[2*t],   ah, bl);
                mma16816(acc[2*t],   al, bh);
                mma16816(acc[2*t+1], ah, bh + 2);
                mma16816(acc[2*t+1], ah, bl + 2);
                mma16816(acc[2*t+1], al, bh + 2);
            }
        }
    }

    int mr = wm + (lane >> 2);
#pragma unroll
    for (int sub = 0; sub < 8; sub++) {
        int nc = n0 + wn + sub * 8 + (lane & 3) * 2;
        if (nc < Nw) {
            C[(size_t)mr * ldc + nc]       = acc[sub][0];
            C[(size_t)(mr + 8) * ldc + nc] = acc[sub][2];
        }
        if (nc + 1 < Nw) {
            C[(size_t)mr * ldc + nc + 1]       = acc[sub][1];
            C[(size_t)(mr + 8) * ldc + nc + 1] = acc[sub][3];
        }
    }
}

/* generic split-K reduce -> fp32 (final output) */
__global__ void k_reduce(const float* __restrict__ part, float* __restrict__ out,
                         int E, int S)
{
    int i = blockIdx.x * 256 + threadIdx.x;
    if (i >= E) return;
    float s = 0.f;
    for (int p = 0; p < S; p++) s += part[(size_t)p * E + i];
    out[i] = s;
}

/* split-K reduce -> bf16 hi/lo pairs */
__global__ void k_reduce_bf(const float* __restrict__ part,
                            __nv_bfloat16* __restrict__ ohi,
                            __nv_bfloat16* __restrict__ olo,
                            int Epairs, int E, int S)
{
    int p = blockIdx.x * 256 + threadIdx.x;
    if (p >= Epairs) return;
    int e0 = 2 * p;
    float v0 = 0.f, v1 = 0.f;
    for (int q = 0; q < S; q++) {
        v0 += part[(size_t)q * E + e0];
        v1 += part[(size_t)q * E + e0 + 1];
    }
    uint32_t hp, lp;
    split2(v0, v1, hp, lp);
    ((uint32_t*)ohi)[p] = hp;
    ((uint32_t*)olo)[p] = lp;
}

/* x fp32 -> bf16 hi/lo */
__global__ void __launch_bounds__(256) k_x2bf(const float* __restrict__ x,
                                              __nv_bfloat16* __restrict__ xhi,
                                              __nv_bfloat16* __restrict__ xlo)
{
    int p = blockIdx.x * 256 + threadIdx.x;     /* pair idx < NB*DIMX/2 */
    float2 v = ((const float2*)x)[p];
    uint32_t hp, lp;
    split2(v.x, v.y, hp, lp);
    ((uint32_t*)xhi)[p] = hp;
    ((uint32_t*)xlo)[p] = lp;
}

/* ------------------------------------------------------------------ */
/* fused: reduce 8 partials + RMS(q_norm) -> bf16 hi/lo               */
/* ------------------------------------------------------------------ */
__global__ void __launch_bounds__(256) k_fuse_qa(const float* __restrict__ part,
                                                 const float* __restrict__ wt,
                                                 __nv_bfloat16* __restrict__ qahi,
                                                 __nv_bfloat16* __restrict__ qalo)
{
    __shared__ float red[256];
    int n = blockIdx.x, tid = threadIdx.x;
    float v0[3], v1[3]; float s = 0.f;
#pragma unroll
    for (int i = 0; i < 3; i++) {
        int e0 = 2 * (tid + i*256);
        float a = 0.f, b = 0.f;
#pragma unroll
        for (int p = 0; p < 8; p++) {
            a += part[(size_t)p*NB*QLRK + (size_t)n*QLRK + e0];
            b += part[(size_t)p*NB*QLRK + (size_t)n*QLRK + e0 + 1];
        }
        v0[i] = a; v1[i] = b; s += a*a + b*b;
    }
    red[tid] = s; __syncthreads();
    for (int k = 128; k > 0; k >>= 1) { if (tid < k) red[tid] += red[tid+k]; __syncthreads(); }
    float scale = rsqrtf(red[0] / (float)QLRK + EPSI);
#pragma unroll
    for (int i = 0; i < 3; i++) {
        int p = tid + i*256;
        int e0 = 2 * p;
        float f0 = v0[i] * scale * wt[e0];
        float f1 = v1[i] * scale * wt[e0 + 1];
        uint32_t hp, lp;
        split2(f0, f1, hp, lp);
        ((uint32_t*)qahi)[(size_t)n*(QLRK/2) + p] = hp;
        ((uint32_t*)qalo)[(size_t)n*(QLRK/2) + p] = lp;
    }
}

__device__ __forceinline__ void rope_cs(int i, float pos, float& c, float& s)
{
    float inv = (float)exp(-(double)i * 0.28782313662425574); /* ln(1e4)/32 */
    float ang = pos * inv;
    double ad = (double)ang;
    c = (float)cos(ad); s = (float)sin(ad);
}

/* fused: reduce 16 partials + RMS + rope -> g_kv (fp32)              */
__global__ void k_fuse_kv(const float* __restrict__ part,
                          const float* __restrict__ wt,
                          const int* __restrict__ ctxl,
                          float* __restrict__ kv)
{
    __shared__ float srow[HDIM];
    __shared__ float rs[64];
    int n = blockIdx.x, tid = threadIdx.x;  /* 64 threads */
    float s = 0.f;
#pragma unroll
    for (int j = 0; j < 3; j++) {
        int c = tid + j*64;
        float t = 0.f;
#pragma unroll
        for (int p = 0; p < 16; p++) t += part[(size_t)p*NB*HDIM + (size_t)n*HDIM + c];
        srow[c] = t; s += t*t;
    }
    rs[tid] = s; __syncthreads();
    for (int k = 32; k > 0; k >>= 1) { if (tid < k) rs[tid] += rs[tid+k]; __syncthreads(); }
    float scale = rsqrtf(rs[0] / (float)HDIM + EPSI);
#pragma unroll
    for (int j = 0; j < 3; j++) { int i = tid + j*64; srow[i] = srow[i]*scale*wt[i]; }
    __syncthreads();
    float pos = (float)(ctxl[n] - 1);
    if (tid < 32) {
        int i = tid;
        float x0 = srow[HDIM-RDIM + 2*i], x1 = srow[HDIM-RDIM + 2*i + 1];
        float c, sn; rope_cs(i, pos, c, sn);
        srow[HDIM-RDIM + 2*i]     = x0*c - x1*sn;
        srow[HDIM-RDIM + 2*i + 1] = x0*sn + x1*c;
    }
    __syncthreads();
#pragma unroll
    for (int j = 0; j < 3; j++) { int i = tid + j*64; kv[(size_t)n*HDIM + i] = srow[i]; }
}

/* fused: reduce 3 partials + rope + bf16 split -> g_qhi/g_qlo        */
__global__ void __launch_bounds__(256) k_fuse_q(const float* __restrict__ part,
                                                const int* __restrict__ ctxl,
                                                __nv_bfloat16* __restrict__ qhi,
                                                __nv_bfloat16* __restrict__ qlo)
{
    int n = blockIdx.x, tid = threadIdx.x;
    float pos = (float)(ctxl[n] - 1);
#pragma unroll
    for (int i = 0; i < 12; i++) {
        int p = tid + i*256;                 /* pair index < 3072 */
        int e0 = 2*p;
        float v0 = 0.f, v1 = 0.f;
#pragma unroll
        for (int q = 0; q < 3; q++) {
            v0 += part[(size_t)q*NB*QDIM + (size_t)n*QDIM + e0];
            v1 += part[(size_t)q*NB*QDIM + (size_t)n*QDIM + e0 + 1];
        }
        int dd = e0 % HDIM;
        if (dd >= HDIM - RDIM) {
            int ir = (dd - (HDIM - RDIM)) >> 1;
            float c, s; rope_cs(ir, pos, c, s);
            float x0 = v0, x1 = v1;
            v0 = x0*c - x1*s;
            v1 = x0*s + x1*c;
        }
        uint32_t hp, lp;
        split2(v0, v1, hp, lp);
        ((uint32_t*)qhi)[(size_t)n*(QDIM/2) + p] = hp;
        ((uint32_t*)qlo)[(size_t)n*(QDIM/2) + p] = lp;
    }
}

/* ------------------------------------------------------------------ */
/* logits via HMMA: CTA = (4-block group, batch n)                    */
/* ------------------------------------------------------------------ */
#define LG_SMEM 76800
__global__ void __launch_bounds__(256) k_logits_mma(
    const float* __restrict__ kvc, const int* __restrict__ bt,
    const int* __restrict__ ctxl,
    const __nv_bfloat16* __restrict__ qhi, const __nv_bfloat16* __restrict__ qlo,
    const float* __restrict__ kvnew, float* __restrict__ logits)
{
    extern __shared__ char sm[];
    uint32_t smb = smem_u32(sm);
    int n = blockIdx.y;
    int ctx = ctxl[n];
    int b0 = blockIdx.x * 4;
    if (b0 * BS >= ctx) return;
    int tid = threadIdx.x, wid = tid >> 5, lane = tid & 31;

    {
        const char* gh = (const char*)(qhi + (size_t)n * QDIM);
        const char* gl = (const char*)(qlo + (size_t)n * QDIM);
#pragma unroll
        for (int i = 0; i < 3; i++) {
            int c = tid + i * 256;
            int r = c / 24, k16 = c % 24;
            *(uint4*)(sm + r * 400 + k16 * 16) = *(const uint4*)(gh + r * 384 + k16 * 16);
            *(uint4*)(sm + 12800 + r * 400 + k16 * 16) = *(const uint4*)(gl + r * 384 + k16 * 16);
        }
    }

    int mt = wid & 3;
    int nt = wid >> 2;
    int kvrow = tid >> 2, kvqp = tid & 3;

    for (int bi = 0; bi < 4; bi++) {
        int b = b0 + bi;
        int base = b * BS;
        if (base >= ctx) break;
        if (bi) __syncthreads();

        int blk = bt[n * MAXB + b];
        {
            int lg = base + kvrow;
            const float* src = (lg == ctx - 1) ? (kvnew + (size_t)n * HDIM)
                                               : (kvc + ((size_t)blk * BS + kvrow) * HDIM);
#pragma unroll
            for (int j = 0; j < 12; j++) {
                int d4 = kvqp * 12 + j;
                float4 v = ((const float4*)src)[d4];
                cvt_store(sm + 25600, sm + 51200, (uint32_t)(kvrow * 400 + d4 * 8), v);
            }
        }
        __syncthreads();

        float acc[2][4];
#pragma unroll
        for (int i = 0; i < 2; i++)
#pragma unroll
            for (int j = 0; j < 4; j++) acc[i][j] = 0.f;

#pragma unroll
        for (int ks = 0; ks < 12; ks++) {
            uint32_t ah[4], al[4];
            int arow = mt * 16 + (lane & 15);
            uint32_t aoff = (uint32_t)(arow * 400 + ks * 32 + (lane >> 4) * 16);
            ldm_x4(ah, smb + 25600 + aoff);
            ldm_x4(al, smb + 51200 + aoff);
            int brow = nt * 16 + ((lane >> 4) & 1) * 8 + (lane & 7);
            uint32_t boff = (uint32_t)(brow * 400 + ks * 32 + ((lane >> 3) & 1) * 16);
            uint32_t bh[4], bl[4];
            ldm_x4(bh, smb + boff);
            ldm_x4(bl, smb + 12800 + boff);
            mma16816(acc[0], ah, bh);
            mma16816(acc[0], ah, bl);
            mma16816(acc[0], al, bh);
            mma16816(acc[1], ah, bh + 2);
            mma16816(acc[1], ah, bl + 2);
            mma16816(acc[1], al, bh + 2);
        }
        __syncthreads();

        float* D = (float*)(sm + 25600);
#pragma unroll
        for (int n8 = 0; n8 < 2; n8++) {
            int h = nt * 16 + n8 * 8 + (lane & 3) * 2;
            int l = mt * 16 + (lane >> 2);
            D[h * 64 + l]           = acc[n8][0];
            D[(h + 1) * 64 + l]     = acc[n8][1];
            D[h * 64 + l + 8]       = acc[n8][2];
            D[(h + 1) * 64 + l + 8] = acc[n8][3];
        }
        __syncthreads();
        int h = tid >> 3, l0 = (tid & 7) * 8;
        float* dst = logits + ((size_t)(n * HEADS + h)) * LMAX + base + l0;
#pragma unroll
        for (int j = 0; j < 8; j++) {
            int l = l0 + j;
            float v = D[h * 64 + l];
            dst[j] = (base + l < ctx) ? v * SCALE_F : NEGF;
        }
    }
}

/* ------------------------------------------------------------------ */
/* top-k radix select (variable length)                               */
/* ------------------------------------------------------------------ */
__device__ __forceinline__ unsigned f2ord(float f) {
    unsigned b = __float_as_uint(f);
    return (b & 0x80000000u) ? ~b : (b | 0x80000000u);
}
__device__ __forceinline__ float ord2f(unsigned u) {
    return (u & 0x80000000u) ? __uint_as_float(u ^ 0x80000000u)
                             : __uint_as_float(~u);
}

__global__ void __launch_bounds__(256) k_select(
    const float* __restrict__ logits, const float* __restrict__ sink,
    const int* __restrict__ ctxl,
    float* __restrict__ tau_o, float* __restrict__ m_o, float* __restrict__ iv_o)
{
    __shared__ unsigned keys[LMAX];
    __shared__ unsigned hist[256];
    __shared__ unsigned rmax[256];
    __shared__ float    red[256];
    __shared__ unsigned s_prefix;
    __shared__ int      s_k;

    int rowid = blockIdx.x;
    int n = rowid >> 5;
    int h = rowid & 31;
    int tid = threadIdx.x;
    int ctx = ctxl[n];
    int nb = ((ctx + 63) >> 6) << 6;
    const float* src = logits + (size_t)rowid * LMAX;

    unsigned um = 0u;
    for (int idx = tid; idx < nb; idx += 256) {
        unsigned u = f2ord(src[idx]);
        keys[idx] = u;
        um = max(um, u);
    }
    rmax[tid] = um; __syncthreads();
    for (int k = 128; k > 0; k >>= 1) { if (tid < k) rmax[tid] = max(rmax[tid], rmax[tid+k]); __syncthreads(); }

    float maxf = ord2f(rmax[0]);
    float snk  = sink[h];
    float m    = fmaxf(maxf, snk);

    if (nb <= TOPKK) {
        float local = 0.f;
        for (int idx = tid; idx < nb; idx += 256)
            local += expf(ord2f(keys[idx]) - m);
        red[tid] = local; __syncthreads();
        for (int k = 128; k > 0; k >>= 1) { if (tid < k) red[tid] += red[tid+k]; __syncthreads(); }
        if (tid == 0) {
            float denom = red[0] + expf(snk - m);
            tau_o[rowid] = -__builtin_huge_valf(); m_o[rowid] = m; iv_o[rowid] = 1.f / denom;
        }
        return;
    }

    if (tid == 0) { s_prefix = 0u; s_k = TOPKK; }
    __syncthreads();

    for (int shift = 24; shift >= 0; shift -= 8) {
        hist[tid] = 0u;
        __syncthreads();
        unsigned pref = s_prefix;
        unsigned himask = (shift == 24) ? 0u : (0xFFFFFFFFu << (shift + 8));
        for (int idx = tid; idx < nb; idx += 256) {
            unsigned u = keys[idx];
            if ((u & himask) == pref) atomicAdd(&hist[(u >> shift) & 255u], 1u);
        }
        __syncthreads();
        if (tid == 0) {
            int kk = s_k; unsigned cum = 0u; int bin = 255;
            for (; bin > 0; bin--) {
                unsigned c = hist[bin];
                if (cum + c >= (unsigned)kk) break;
                cum += c;
            }
            s_prefix = pref | ((unsigned)bin << shift);
            s_k = kk - (int)cum;
        }
        __syncthreads();
    }
    unsigned tu = s_prefix;

    float local = 0.f;
    for (int idx = tid; idx < nb; idx += 256) {
        unsigned u = keys[idx];
        if (u >= tu) local += expf(ord2f(u) - m);
    }
    red[tid] = local; __syncthreads();
    for (int k = 128; k > 0; k >>= 1) { if (tid < k) red[tid] += red[tid+k]; __syncthreads(); }
    if (tid == 0) {
        float denom = red[0] + expf(snk - m);
        tau_o[rowid] = ord2f(tu); m_o[rowid] = m; iv_o[rowid] = 1.f / denom;
    }
}

/* ------------------------------------------------------------------ */
/* o accumulation via HMMA + ldmatrix.trans                           */
/* ------------------------------------------------------------------ */
#define AC_SMEM 60416
__global__ void __launch_bounds__(256) k_accum_mma(
    const float* __restrict__ kvc, const int* __restrict__ bt,
    const int* __restrict__ ctxl, const float* __restrict__ kvnew,
    const float* __restrict__ logits, const float* __restrict__ tau_i,
    const float* __restrict__ m_i, const float* __restrict__ iv_i,
    float* __restrict__ opart)
{
    extern __shared__ char sm[];
    uint32_t smb = smem_u32(sm);
    int chunk = blockIdx.x, n = blockIdx.y;
    int ctx = ctxl[n];
    int tid = threadIdx.x, wid = tid >> 5, lane = tid & 31;

    int mt = wid & 1;
    int ng = wid >> 1;
    float acc[6][4];
#pragma unroll
    for (int i = 0; i < 6; i++)
#pragma unroll
        for (int j = 0; j < 4; j++) acc[i][j] = 0.f;

    int ph = tid >> 3, pl0 = (tid & 7) * 8;
    float ptau = tau_i[n*HEADS + ph];
    float pm   = m_i[n*HEADS + ph];
    float piv  = iv_i[n*HEADS + ph];
    int kvrow = tid >> 2, kvqp = tid & 3;

    for (int b8 = 0; b8 < 8; b8++) {
        int b = chunk * 8 + b8;
        int base = b * BS;
        if (base >= ctx) break;
        int blk = bt[n*MAXB + b];
        if (b8) __syncthreads();

        const float* lsrc = logits + ((size_t)(n*HEADS + ph))*LMAX + base + pl0;
#pragma unroll
        for (int j = 0; j < 8; j += 2) {
            float lg0 = lsrc[j], lg1 = lsrc[j+1];
            float p0 = (lg0 >= ptau) ? (expf(lg0 - pm) * piv) : 0.f;
            float p1 = (lg1 >= ptau) ? (expf(lg1 - pm) * piv) : 0.f;
            uint32_t hp, lp;
            split2(p0, p1, hp, lp);
            uint32_t off = (uint32_t)(ph * 144 + (pl0 + j) * 2);
            *(uint32_t*)(sm + off)        = hp;
            *(uint32_t*)(sm + 4608 + off) = lp;
        }
        {
            int lg = base + kvrow;
            const float* src = (lg == ctx - 1) ? (kvnew + (size_t)n*HDIM)
                                               : (kvc + ((size_t)blk*BS + kvrow)*HDIM);
#pragma unroll
            for (int j = 0; j < 12; j++) {
                int d4 = kvqp * 12 + j;
                float4 v = ((const float4*)src)[d4];
                cvt_store(sm + 9216, sm + 34816, (uint32_t)(kvrow * 400 + d4 * 8), v);
            }
        }
        __syncthreads();

#pragma unroll
        for (int ks = 0; ks < 4; ks++) {
            uint32_t ah[4], al[4];
            int arow = mt * 16 + (lane & 15);
            uint32_t aoff = (uint32_t)(arow * 144 + ks * 32 + (lane >> 4) * 16);
            ldm_x4(ah, smb + aoff);
            ldm_x4(al, smb + 4608 + aoff);
            int l_in = ks * 16 + ((lane >> 3) & 1) * 8 + (lane & 7);
#pragma unroll
            for (int t = 0; t < 3; t++) {
                uint32_t dByte = (uint32_t)((ng * 48 + t * 16) * 2 + ((lane >> 4) & 1) * 16);
                uint32_t boff = (uint32_t)(l_in * 400) + dByte;
                uint32_t bh[4], bl[4];
                ldm_x4t(bh, smb + 9216 + boff);
                ldm_x4t(bl, smb + 34816 + boff);
                mma16816(acc[2*t],   ah, bh);
                mma16816(acc[2*t],   ah, bl);
                mma16816(acc[2*t],   al, bh);
                mma16816(acc[2*t+1], ah, bh + 2);
                mma16816(acc[2*t+1], ah, bl + 2);
                mma16816(acc[2*t+1], al, bh + 2);
            }
        }
    }

    float* dst = opart + ((size_t)(chunk * NB + n)) * HEADS * HDIM;
#pragma unroll
    for (int t6 = 0; t6 < 6; t6++) {
        int d = ng * 48 + t6 * 8 + (lane & 3) * 2;
        int h = mt * 16 + (lane >> 2);
        dst[(size_t)h * HDIM + d]           = acc[t6][0];
        dst[(size_t)h * HDIM + d + 1]       = acc[t6][1];
        dst[(size_t)(h + 8) * HDIM + d]     = acc[t6][2];
        dst[(size_t)(h + 8) * HDIM + d + 1] = acc[t6][3];
    }
}

/* reduce 8 o-partials -> bf16 hi/lo pairs */
__global__ void k_reduce_o(const float* __restrict__ opart,
                           __nv_bfloat16* __restrict__ ohi,
                           __nv_bfloat16* __restrict__ olo)
{
    int p = blockIdx.x*256 + threadIdx.x;       /* pair idx < NB*QDIM/2 */
    int e0 = 2 * p;
    float v0 = 0.f, v1 = 0.f;
#pragma unroll
    for (int c = 0; c < 8; c++) {
        v0 += opart[(size_t)c*NB*QDIM + e0];
        v1 += opart[(size_t)c*NB*QDIM + e0 + 1];
    }
    uint32_t hp, lp;
    split2(v0, v1, hp, lp);
    ((uint32_t*)ohi)[p] = hp;
    ((uint32_t*)olo)[p] = lp;
}

/* ------------------------------------------------------------------ */
/* host launcher                                                      */
/* ------------------------------------------------------------------ */
extern "C" void kernel_launch(void* const* d_in, const int* in_sizes, int n_in,
                              void* d_out, int out_size)
{
    const float* x    = (const float*)d_in[0];
    const float* kvc  = (const float*)d_in[1];
    const int*   bt   = (const int*)  d_in[2];
    const int*   ctxl = (const int*)  d_in[3];
    const float* wqa  = (const float*)d_in[5];
    const float* qnw  = (const float*)d_in[6];
    const float* wqb  = (const float*)d_in[7];
    const float* wkv  = (const float*)d_in[8];
    const float* kvnw = (const float*)d_in[9];
    const float* woa  = (const float*)d_in[10];
    const float* wob  = (const float*)d_in[11];
    const float* sink = (const float*)d_in[12];
    float* out = (float*)d_out;

    float *kv, *lg, *tau, *mr, *iv, *op, *part;
    __nv_bfloat16 *xhi, *xlo, *qahi, *qalo, *qhi, *qlo, *oohi, *oolo, *lathi, *latlo;
    cudaGetSymbolAddress((void**)&xhi,  g_xhi);
    cudaGetSymbolAddress((void**)&xlo,  g_xlo);
    cudaGetSymbolAddress((void**)&qahi, g_qahi);
    cudaGetSymbolAddress((void**)&qalo, g_qalo);
    cudaGetSymbolAddress((void**)&kv,   g_kv);
    cudaGetSymbolAddress((void**)&qhi,  g_qhi);
    cudaGetSymbolAddress((void**)&qlo,  g_qlo);
    cudaGetSymbolAddress((void**)&lg,   g_logits);
    cudaGetSymbolAddress((void**)&tau,  g_tau);
    cudaGetSymbolAddress((void**)&mr,   g_mrow);
    cudaGetSymbolAddress((void**)&iv,   g_invden);
    cudaGetSymbolAddress((void**)&op,   g_opart);
    cudaGetSymbolAddress((void**)&oohi, g_oohi);
    cudaGetSymbolAddress((void**)&oolo, g_oolo);
    cudaGetSymbolAddress((void**)&lathi,g_lathi);
    cudaGetSymbolAddress((void**)&latlo,g_latlo);
    cudaGetSymbolAddress((void**)&part, g_part);

    cudaFuncSetAttribute(k_gemm_mma,   cudaFuncAttributeMaxDynamicSharedMemorySize, MM_SMEM);
    cudaFuncSetAttribute(k_logits_mma, cudaFuncAttributeMaxDynamicSharedMemorySize, LG_SMEM);
    cudaFuncSetAttribute(k_accum_mma,  cudaFuncAttributeMaxDynamicSharedMemorySize, AC_SMEM);

    /* ---- x -> bf16 hi/lo ---- */
    k_x2bf<<<NB*DIMX/512, 256>>>(x, xhi, xlo);

    /* ---- q_a = x @ wq_a^T : split 8 ---- */
    k_gemm_mma<<<dim3(12, 8, 1), 256, MM_SMEM>>>(
        xhi, xlo, DIMX, 0, wqa, DIMX, 0,
        part, QLRK, 0, (long long)NB*QLRK, 512, QLRK);
    k_fuse_qa<<<NB, 256>>>(part, qnw, qahi, qalo);

    /* ---- kv = x @ wkv^T : split 16 ---- */
    k_gemm_mma<<<dim3(2, 16, 1), 256, MM_SMEM>>>(
        xhi, xlo, DIMX, 0, wkv, DIMX, 0,
        part, HDIM, 0, (long long)NB*HDIM, 256, HDIM);
    k_fuse_kv<<<NB, 64>>>(part, kvnw, ctxl, kv);

    /* ---- q = qa_n @ wq_b^T : split 3 ---- */
    k_gemm_mma<<<dim3(48, 3, 1), 256, MM_SMEM>>>(
        qahi, qalo, QLRK, 0, wqb, QLRK, 0,
        part, QDIM, 0, (long long)NB*QDIM, 512, QDIM);
    k_fuse_q<<<NB, 256>>>(part, ctxl, qhi, qlo);

    /* ---- attention ---- */
    k_logits_mma<<<dim3(16, NB), 256, LG_SMEM>>>(kvc, bt, ctxl, qhi, qlo, kv, lg);
    k_select<<<NB*HEADS, 256>>>(lg, sink, ctxl, tau, mr, iv);
    k_accum_mma<<<dim3(8, NB), 256, AC_SMEM>>>(kvc, bt, ctxl, kv, lg, tau, mr, iv, op);
    k_reduce_o<<<NB*QDIM/512, 256>>>(op, oohi, oolo);

    /* ---- lat = grouped wo_a : split 4 ---- */
    k_gemm_mma<<<dim3(4, 4, GRP), 256, MM_SMEM>>>(
        oohi, oolo, QDIM, 768, woa, 768, (long long)OLRK*768,
        part, GRP*OLRK, OLRK, (long long)NB*GRP*OLRK, 192, OLRK);
    k_reduce_bf<<<(NB*GRP*OLRK/2+255)/256, 256>>>(part, lathi, latlo,
                                                  NB*GRP*OLRK/2, NB*GRP*OLRK, 4);

    /* ---- out = lat @ wo_b^T : split 4 ---- */
    k_gemm_mma<<<dim3(32, 4, 1), 256, MM_SMEM>>>(
        lathi, latlo, GRP*OLRK, 0, wob, DIMX, 0,
        part, DIMX, 0, (long long)NB*DIMX, 1024, DIMX);
    k_reduce<<<(NB*DIMX+255)/256, 256>>>(part, out, NB*DIMX, 4);
}

// round 9
// speedup vs baseline: 3.7892x; 1.0076x over previous
#include <cuda_runtime.h>
#include <cuda_bf16.h>
#include <math.h>
#include <stdint.h>

#define NB    64
#define DIMX  4096
#define HEADS 32
#define HDIM  192
#define RDIM  64
#define QLRK  1536
#define OLRK  512
#define GRP   8
#define BS    64
#define MAXB  64
#define LMAX  4096
#define TOPKK 1024
#define EPSI  1e-6f
#define NEGF  -1e30f
#define QDIM  (HEADS*HDIM)   /* 6144 */
#define SCALE_F 0.07216878364870323f  /* 192^-0.5 */

/* disjoint split-K partial regions (floats) */
#define PART_QA_OFF 0                         /* 8*98304   = 786432  */
#define PART_KV_OFF 786432                    /* 16*12288  = 196608  */
#define PART_QB_OFF 983040                    /* 3*393216  = 1179648 */
#define PART_TOTAL  2359296                   /* 9 MB */

/* ------------------------------------------------------------------ */
/* scratch                                                            */
/* ------------------------------------------------------------------ */
__device__ __nv_bfloat16 g_xhi[NB*DIMX];
__device__ __nv_bfloat16 g_xlo[NB*DIMX];
__device__ __nv_bfloat16 g_qahi[NB*QLRK];
__device__ __nv_bfloat16 g_qalo[NB*QLRK];
__device__ float g_kv[NB*HDIM];
__device__ __nv_bfloat16 g_qhi[NB*QDIM];
__device__ __nv_bfloat16 g_qlo[NB*QDIM];
__device__ float g_logits[(size_t)NB*HEADS*LMAX];       /* 32 MB */
__device__ float g_tau[NB*HEADS];
__device__ float g_mrow[NB*HEADS];
__device__ float g_invden[NB*HEADS];
__device__ float g_opart[(size_t)8*NB*HEADS*HDIM];      /* 12.6 MB */
__device__ __nv_bfloat16 g_oohi[NB*QDIM];
__device__ __nv_bfloat16 g_oolo[NB*QDIM];
__device__ __nv_bfloat16 g_lathi[NB*GRP*OLRK];
__device__ __nv_bfloat16 g_latlo[NB*GRP*OLRK];
__device__ float g_part[PART_TOTAL];

/* ------------------------------------------------------------------ */
/* helpers                                                            */
/* ------------------------------------------------------------------ */
__device__ __forceinline__ uint32_t smem_u32(const void* p){
    uint32_t a;
    asm("{ .reg .u64 t; cvta.to.shared.u64 t, %1; cvt.u32.u64 %0, t; }"
        : "=r"(a) : "l"(p));
    return a;
}
__device__ __forceinline__ uint32_t sw128(uint32_t b){ return b ^ ((b >> 3) & 0x70); }

/* fast exact split: hi = truncate-to-bf16 (bit prefix), lo = rn(v-hi). */
__device__ __forceinline__ void split2(float x, float y, uint32_t& hp, uint32_t& lp){
    uint32_t bx = __float_as_uint(x), by = __float_as_uint(y);
    uint32_t h;
    asm("prmt.b32 %0, %1, %2, 0x7632;" : "=r"(h) : "r"(bx), "r"(by));
    float fx = __uint_as_float(h << 16);
    float fy = __uint_as_float(h & 0xFFFF0000u);
    float lx = x - fx, ly = y - fy;
    uint32_t l;
    asm("cvt.rn.bf16x2.f32 %0, %1, %2;" : "=r"(l) : "f"(ly), "f"(lx));
    hp = h; lp = l;
}
__device__ __forceinline__ void mma16816(float* c, const uint32_t* a, const uint32_t* b){
    asm volatile("mma.sync.aligned.m16n8k16.row.col.f32.bf16.bf16.f32 "
        "{%0,%1,%2,%3}, {%4,%5,%6,%7}, {%8,%9}, {%0,%1,%2,%3};"
        : "+f"(c[0]), "+f"(c[1]), "+f"(c[2]), "+f"(c[3])
        : "r"(a[0]), "r"(a[1]), "r"(a[2]), "r"(a[3]), "r"(b[0]), "r"(b[1]));
}
__device__ __forceinline__ void ldm_x4(uint32_t* r, uint32_t addr){
    asm volatile("ldmatrix.sync.aligned.m8n8.x4.shared.b16 {%0,%1,%2,%3}, [%4];"
        : "=r"(r[0]), "=r"(r[1]), "=r"(r[2]), "=r"(r[3]) : "r"(addr));
}
__device__ __forceinline__ void ldm_x4t(uint32_t* r, uint32_t addr){
    asm volatile("ldmatrix.sync.aligned.m8n8.x4.trans.shared.b16 {%0,%1,%2,%3}, [%4];"
        : "=r"(r[0]), "=r"(r[1]), "=r"(r[2]), "=r"(r[3]) : "r"(addr));
}
__device__ __forceinline__ void cvt_store(char* hiB, char* loB, uint32_t off, float4 v){
    uint2 hh, ll;
    split2(v.x, v.y, hh.x, ll.x);
    split2(v.z, v.w, hh.y, ll.y);
    *(uint2*)(hiB + off) = hh;
    *(uint2*)(loB + off) = ll;
}

/* ------------------------------------------------------------------ */
/* HMMA GEMM: X pre-converted bf16 hi/lo in gmem; W fp32 (fast split) */
/* ------------------------------------------------------------------ */
#define MM_SMEM 49152
__global__ void __launch_bounds__(256,2) k_gemm_mma(
    const __nv_bfloat16* __restrict__ Xhi, const __nv_bfloat16* __restrict__ Xlo,
    int ldx, long long xGrp,
    const float* __restrict__ W, int ldw, long long wGrp,
    float* __restrict__ C, int ldc, long long cGrp, long long cSplit,
    int Kloc, int Nw)
{
    extern __shared__ char sm[];
    char* sXhi = sm;
    char* sXlo = sm + 8192;
    char* sWhi = sm + 16384;
    char* sWlo = sm + 32768;
    uint32_t smb = smem_u32(sm);

    int tid = threadIdx.x, wid = tid >> 5, lane = tid & 31;
    int n0 = blockIdx.x * 128;
    int s  = blockIdx.y;
    int g  = blockIdx.z;
    Xhi += (size_t)g * xGrp + (size_t)s * Kloc;
    Xlo += (size_t)g * xGrp + (size_t)s * Kloc;
    W   += (size_t)g * wGrp + (size_t)s * Kloc;
    C   += (size_t)g * cGrp + (size_t)s * cSplit;

    int wm = (wid & 3) * 16;
    int wn = (wid >> 2) * 64;

    float acc[8][4];
#pragma unroll
    for (int i = 0; i < 8; i++)
#pragma unroll
        for (int j = 0; j < 4; j++) acc[i][j] = 0.f;

    int xr0 = tid >> 3, xr1 = (tid + 256) >> 3;
    int xc16 = tid & 7;
    int wrow = tid >> 1;
    int wc   = tid & 1;
    int wrg  = n0 + wrow; if (wrg >= Nw) wrg = Nw - 1;

    const int NC = Kloc / 64;
    uint4 xh[2], xl[2];
    float4 wv[8];
    xh[0] = *(const uint4*)(Xhi + (size_t)xr0 * ldx + xc16 * 8);
    xh[1] = *(const uint4*)(Xhi + (size_t)xr1 * ldx + xc16 * 8);
    xl[0] = *(const uint4*)(Xlo + (size_t)xr0 * ldx + xc16 * 8);
    xl[1] = *(const uint4*)(Xlo + (size_t)xr1 * ldx + xc16 * 8);
#pragma unroll
    for (int j = 0; j < 8; j++)
        wv[j] = *(const float4*)(W + (size_t)wrg * ldw + (wc + 2*j) * 4);

    for (int ch = 0; ch < NC; ch++) {
        if (ch) __syncthreads();
        {
            uint32_t o0 = sw128((uint32_t)(xr0 * 128 + xc16 * 16));
            uint32_t o1 = sw128((uint32_t)(xr1 * 128 + xc16 * 16));
            *(uint4*)(sXhi + o0) = xh[0];
            *(uint4*)(sXhi + o1) = xh[1];
            *(uint4*)(sXlo + o0) = xl[0];
            *(uint4*)(sXlo + o1) = xl[1];
        }
#pragma unroll
        for (int j = 0; j < 8; j++) {
            uint32_t off = sw128((uint32_t)(wrow * 128 + (wc + 2*j) * 8));
            cvt_store(sWhi, sWlo, off, wv[j]);
        }
        __syncthreads();
        if (ch + 1 < NC) {
            int kb = (ch + 1) * 64;
            xh[0] = *(const uint4*)(Xhi + (size_t)xr0 * ldx + kb + xc16 * 8);
            xh[1] = *(const uint4*)(Xhi + (size_t)xr1 * ldx + kb + xc16 * 8);
            xl[0] = *(const uint4*)(Xlo + (size_t)xr0 * ldx + kb + xc16 * 8);
            xl[1] = *(const uint4*)(Xlo + (size_t)xr1 * ldx + kb + xc16 * 8);
#pragma unroll
            for (int j = 0; j < 8; j++)
                wv[j] = *(const float4*)(W + (size_t)wrg * ldw + kb + (wc + 2*j) * 4);
        }
#pragma unroll
        for (int ks = 0; ks < 4; ks++) {
            uint32_t ah[4], al[4];
            {
                int arow = wm + (lane & 15);
                uint32_t aoff = sw128((uint32_t)(arow * 128 + (ks*2 + (lane >> 4)) * 16));
                ldm_x4(ah, smb + aoff);
                ldm_x4(al, smb + 8192 + aoff);
            }
#pragma unroll
            for (int t = 0; t < 4; t++) {
                int brow = wn + 16*t + ((lane >> 4) & 1) * 8 + (lane & 7);
                uint32_t boff = sw128((uint32_t)(brow * 128 + (ks*2 + ((lane >> 3) & 1)) * 16));
                uint32_t bh[4], bl[4];
                ldm_x4(bh, smb + 16384 + boff);
                ldm_x4(bl, smb + 32768 + boff);
                mma16816(acc[2*t],   ah, bh);
                mma16816(acc[2*t],   ah, bl);
                mma16816(acc[2*t],   al, bh);
                mma16816(acc[2*t+1], ah, bh + 2);
                mma16816(acc[2*t+1], ah, bl + 2);
                mma16816(acc[2*t+1], al, bh + 2);
            }
        }
    }

    int mr = wm + (lane >> 2);
#pragma unroll
    for (int sub = 0; sub < 8; sub++) {
        int nc = n0 + wn + sub * 8 + (lane & 3) * 2;
        if (nc < Nw) {
            C[(size_t)mr * ldc + nc]       = acc[sub][0];
            C[(size_t)(mr + 8) * ldc + nc] = acc[sub][2];
        }
        if (nc + 1 < Nw) {
            C[(size_t)mr * ldc + nc + 1]       = acc[sub][1];
            C[(size_t)(mr + 8) * ldc + nc + 1] = acc[sub][3];
        }
    }
}

/* generic split-K reduce -> fp32 */
__global__ void k_reduce(const float* __restrict__ part, float* __restrict__ out,
                         int E, int S)
{
    int i = blockIdx.x * 256 + threadIdx.x;
    if (i >= E) return;
    float s = 0.f;
    for (int p = 0; p < S; p++) s += part[(size_t)p * E + i];
    out[i] = s;
}

/* split-K reduce -> bf16 hi/lo pairs */
__global__ void k_reduce_bf(const float* __restrict__ part,
                            __nv_bfloat16* __restrict__ ohi,
                            __nv_bfloat16* __restrict__ olo,
                            int Epairs, int E, int S)
{
    int p = blockIdx.x * 256 + threadIdx.x;
    if (p >= Epairs) return;
    int e0 = 2 * p;
    float v0 = 0.f, v1 = 0.f;
    for (int q = 0; q < S; q++) {
        v0 += part[(size_t)q * E + e0];
        v1 += part[(size_t)q * E + e0 + 1];
    }
    uint32_t hp, lp;
    split2(v0, v1, hp, lp);
    ((uint32_t*)ohi)[p] = hp;
    ((uint32_t*)olo)[p] = lp;
}

/* x fp32 -> bf16 hi/lo */
__global__ void __launch_bounds__(256) k_x2bf(const float* __restrict__ x,
                                              __nv_bfloat16* __restrict__ xhi,
                                              __nv_bfloat16* __restrict__ xlo)
{
    int p = blockIdx.x * 256 + threadIdx.x;
    float2 v = ((const float2*)x)[p];
    uint32_t hp, lp;
    split2(v.x, v.y, hp, lp);
    ((uint32_t*)xhi)[p] = hp;
    ((uint32_t*)xlo)[p] = lp;
}

/* ------------------------------------------------------------------ */
/* fused: reduce 8 partials + RMS(q_norm) -> bf16 hi/lo               */
/* ------------------------------------------------------------------ */
__global__ void __launch_bounds__(256) k_fuse_qa(const float* __restrict__ part,
                                                 const float* __restrict__ wt,
                                                 __nv_bfloat16* __restrict__ qahi,
                                                 __nv_bfloat16* __restrict__ qalo)
{
    __shared__ float red[256];
    int n = blockIdx.x, tid = threadIdx.x;
    float v0[3], v1[3]; float s = 0.f;
#pragma unroll
    for (int i = 0; i < 3; i++) {
        int e0 = 2 * (tid + i*256);
        float a = 0.f, b = 0.f;
#pragma unroll
        for (int p = 0; p < 8; p++) {
            a += part[(size_t)p*NB*QLRK + (size_t)n*QLRK + e0];
            b += part[(size_t)p*NB*QLRK + (size_t)n*QLRK + e0 + 1];
        }
        v0[i] = a; v1[i] = b; s += a*a + b*b;
    }
    red[tid] = s; __syncthreads();
    for (int k = 128; k > 0; k >>= 1) { if (tid < k) red[tid] += red[tid+k]; __syncthreads(); }
    float scale = rsqrtf(red[0] / (float)QLRK + EPSI);
#pragma unroll
    for (int i = 0; i < 3; i++) {
        int p = tid + i*256;
        int e0 = 2 * p;
        float f0 = v0[i] * scale * wt[e0];
        float f1 = v1[i] * scale * wt[e0 + 1];
        uint32_t hp, lp;
        split2(f0, f1, hp, lp);
        ((uint32_t*)qahi)[(size_t)n*(QLRK/2) + p] = hp;
        ((uint32_t*)qalo)[(size_t)n*(QLRK/2) + p] = lp;
    }
}

__device__ __forceinline__ void rope_cs(int i, float pos, float& c, float& s)
{
    float inv = (float)exp(-(double)i * 0.28782313662425574); /* ln(1e4)/32 */
    float ang = pos * inv;
    double ad = (double)ang;
    c = (float)cos(ad); s = (float)sin(ad);
}

/* fused: reduce 16 partials + RMS + rope -> g_kv (fp32)              */
__global__ void k_fuse_kv(const float* __restrict__ part,
                          const float* __restrict__ wt,
                          const int* __restrict__ ctxl,
                          float* __restrict__ kv)
{
    __shared__ float srow[HDIM];
    __shared__ float rs[64];
    int n = blockIdx.x, tid = threadIdx.x;
    float s = 0.f;
#pragma unroll
    for (int j = 0; j < 3; j++) {
        int c = tid + j*64;
        float t = 0.f;
#pragma unroll
        for (int p = 0; p < 16; p++) t += part[(size_t)p*NB*HDIM + (size_t)n*HDIM + c];
        srow[c] = t; s += t*t;
    }
    rs[tid] = s; __syncthreads();
    for (int k = 32; k > 0; k >>= 1) { if (tid < k) rs[tid] += rs[tid+k]; __syncthreads(); }
    float scale = rsqrtf(rs[0] / (float)HDIM + EPSI);
#pragma unroll
    for (int j = 0; j < 3; j++) { int i = tid + j*64; srow[i] = srow[i]*scale*wt[i]; }
    __syncthreads();
    float pos = (float)(ctxl[n] - 1);
    if (tid < 32) {
        int i = tid;
        float x0 = srow[HDIM-RDIM + 2*i], x1 = srow[HDIM-RDIM + 2*i + 1];
        float c, sn; rope_cs(i, pos, c, sn);
        srow[HDIM-RDIM + 2*i]     = x0*c - x1*sn;
        srow[HDIM-RDIM + 2*i + 1] = x0*sn + x1*c;
    }
    __syncthreads();
#pragma unroll
    for (int j = 0; j < 3; j++) { int i = tid + j*64; kv[(size_t)n*HDIM + i] = srow[i]; }
}

/* fused: reduce 3 partials + rope + bf16 split -> g_qhi/g_qlo        */
__global__ void __launch_bounds__(256) k_fuse_q(const float* __restrict__ part,
                                                const int* __restrict__ ctxl,
                                                __nv_bfloat16* __restrict__ qhi,
                                                __nv_bfloat16* __restrict__ qlo)
{
    int n = blockIdx.x, tid = threadIdx.x;
    float pos = (float)(ctxl[n] - 1);
#pragma unroll
    for (int i = 0; i < 12; i++) {
        int p = tid + i*256;
        int e0 = 2*p;
        float v0 = 0.f, v1 = 0.f;
#pragma unroll
        for (int q = 0; q < 3; q++) {
            v0 += part[(size_t)q*NB*QDIM + (size_t)n*QDIM + e0];
            v1 += part[(size_t)q*NB*QDIM + (size_t)n*QDIM + e0 + 1];
        }
        int dd = e0 % HDIM;
        if (dd >= HDIM - RDIM) {
            int ir = (dd - (HDIM - RDIM)) >> 1;
            float c, s; rope_cs(ir, pos, c, s);
            float x0 = v0, x1 = v1;
            v0 = x0*c - x1*s;
            v1 = x0*s + x1*c;
        }
        uint32_t hp, lp;
        split2(v0, v1, hp, lp);
        ((uint32_t*)qhi)[(size_t)n*(QDIM/2) + p] = hp;
        ((uint32_t*)qlo)[(size_t)n*(QDIM/2) + p] = lp;
    }
}

/* ------------------------------------------------------------------ */
/* logits via HMMA: CTA bx handles blocks bx, bx+16, bx+32, bx+48     */
/* ------------------------------------------------------------------ */
#define LG_SMEM 76800
__global__ void __launch_bounds__(256) k_logits_mma(
    const float* __restrict__ kvc, const int* __restrict__ bt,
    const int* __restrict__ ctxl,
    const __nv_bfloat16* __restrict__ qhi, const __nv_bfloat16* __restrict__ qlo,
    const float* __restrict__ kvnew, float* __restrict__ logits)
{
    extern __shared__ char sm[];
    uint32_t smb = smem_u32(sm);
    int n = blockIdx.y;
    int ctx = ctxl[n];
    int bx = blockIdx.x;               /* 0..15 */
    if (bx * BS >= ctx) return;
    int tid = threadIdx.x, wid = tid >> 5, lane = tid & 31;

    {
        const char* gh = (const char*)(qhi + (size_t)n * QDIM);
        const char* gl = (const char*)(qlo + (size_t)n * QDIM);
#pragma unroll
        for (int i = 0; i < 3; i++) {
            int c = tid + i * 256;
            int r = c / 24, k16 = c % 24;
            *(uint4*)(sm + r * 400 + k16 * 16) = *(const uint4*)(gh + r * 384 + k16 * 16);
            *(uint4*)(sm + 12800 + r * 400 + k16 * 16) = *(const uint4*)(gl + r * 384 + k16 * 16);
        }
    }

    int mt = wid & 3;
    int nt = wid >> 2;
    int kvrow = tid >> 2, kvqp = tid & 3;

    for (int bi = 0; bi < 4; bi++) {
        int b = bx + 16 * bi;          /* strided */
        int base = b * BS;
        if (base >= ctx) break;
        if (bi) __syncthreads();

        int blk = bt[n * MAXB + b];
        {
            int lg = base + kvrow;
            const float* src = (lg == ctx - 1) ? (kvnew + (size_t)n * HDIM)
                                               : (kvc + ((size_t)blk * BS + kvrow) * HDIM);
#pragma unroll
            for (int j = 0; j < 12; j++) {
                int d4 = kvqp * 12 + j;
                float4 v = ((const float4*)src)[d4];
                cvt_store(sm + 25600, sm + 51200, (uint32_t)(kvrow * 400 + d4 * 8), v);
            }
        }
        __syncthreads();

        float acc[2][4];
#pragma unroll
        for (int i = 0; i < 2; i++)
#pragma unroll
            for (int j = 0; j < 4; j++) acc[i][j] = 0.f;

#pragma unroll
        for (int ks = 0; ks < 12; ks++) {
            uint32_t ah[4], al[4];
            int arow = mt * 16 + (lane & 15);
            uint32_t aoff = (uint32_t)(arow * 400 + ks * 32 + (lane >> 4) * 16);
            ldm_x4(ah, smb + 25600 + aoff);
            ldm_x4(al, smb + 51200 + aoff);
            int brow = nt * 16 + ((lane >> 4) & 1) * 8 + (lane & 7);
            uint32_t boff = (uint32_t)(brow * 400 + ks * 32 + ((lane >> 3) & 1) * 16);
            uint32_t bh[4], bl[4];
            ldm_x4(bh, smb + boff);
            ldm_x4(bl, smb + 12800 + boff);
            mma16816(acc[0], ah, bh);
            mma16816(acc[0], ah, bl);
            mma16816(acc[0], al, bh);
            mma16816(acc[1], ah, bh + 2);
            mma16816(acc[1], ah, bl + 2);
            mma16816(acc[1], al, bh + 2);
        }
        __syncthreads();

        float* D = (float*)(sm + 25600);
#pragma unroll
        for (int n8 = 0; n8 < 2; n8++) {
            int h = nt * 16 + n8 * 8 + (lane & 3) * 2;
            int l = mt * 16 + (lane >> 2);
            D[h * 64 + l]           = acc[n8][0];
            D[(h + 1) * 64 + l]     = acc[n8][1];
            D[h * 64 + l + 8]       = acc[n8][2];
            D[(h + 1) * 64 + l + 8] = acc[n8][3];
        }
        __syncthreads();
        int h = tid >> 3, l0 = (tid & 7) * 8;
        float* dst = logits + ((size_t)(n * HEADS + h)) * LMAX + base + l0;
#pragma unroll
        for (int j = 0; j < 8; j++) {
            int l = l0 + j;
            float v = D[h * 64 + l];
            dst[j] = (base + l < ctx) ? v * SCALE_F : NEGF;
        }
    }
}

/* ------------------------------------------------------------------ */
/* top-k radix select (variable length)                               */
/* ------------------------------------------------------------------ */
__device__ __forceinline__ unsigned f2ord(float f) {
    unsigned b = __float_as_uint(f);
    return (b & 0x80000000u) ? ~b : (b | 0x80000000u);
}
__device__ __forceinline__ float ord2f(unsigned u) {
    return (u & 0x80000000u) ? __uint_as_float(u ^ 0x80000000u)
                             : __uint_as_float(~u);
}

__global__ void __launch_bounds__(256) k_select(
    const float* __restrict__ logits, const float* __restrict__ sink,
    const int* __restrict__ ctxl,
    float* __restrict__ tau_o, float* __restrict__ m_o, float* __restrict__ iv_o)
{
    __shared__ unsigned keys[LMAX];
    __shared__ unsigned hist[256];
    __shared__ unsigned rmax[256];
    __shared__ float    red[256];
    __shared__ unsigned s_prefix;
    __shared__ int      s_k;

    int rowid = blockIdx.x;
    int n = rowid >> 5;
    int h = rowid & 31;
    int tid = threadIdx.x;
    int ctx = ctxl[n];
    int nb = ((ctx + 63) >> 6) << 6;
    const float* src = logits + (size_t)rowid * LMAX;

    unsigned um = 0u;
    for (int idx = tid; idx < nb; idx += 256) {
        unsigned u = f2ord(src[idx]);
        keys[idx] = u;
        um = max(um, u);
    }
    rmax[tid] = um; __syncthreads();
    for (int k = 128; k > 0; k >>= 1) { if (tid < k) rmax[tid] = max(rmax[tid], rmax[tid+k]); __syncthreads(); }

    float maxf = ord2f(rmax[0]);
    float snk  = sink[h];
    float m    = fmaxf(maxf, snk);

    if (nb <= TOPKK) {
        float local = 0.f;
        for (int idx = tid; idx < nb; idx += 256)
            local += expf(ord2f(keys[idx]) - m);
        red[tid] = local; __syncthreads();
        for (int k = 128; k > 0; k >>= 1) { if (tid < k) red[tid] += red[tid+k]; __syncthreads(); }
        if (tid == 0) {
            float denom = red[0] + expf(snk - m);
            tau_o[rowid] = -__builtin_huge_valf(); m_o[rowid] = m; iv_o[rowid] = 1.f / denom;
        }
        return;
    }

    if (tid == 0) { s_prefix = 0u; s_k = TOPKK; }
    __syncthreads();

    for (int shift = 24; shift >= 0; shift -= 8) {
        hist[tid] = 0u;
        __syncthreads();
        unsigned pref = s_prefix;
        unsigned himask = (shift == 24) ? 0u : (0xFFFFFFFFu << (shift + 8));
        for (int idx = tid; idx < nb; idx += 256) {
            unsigned u = keys[idx];
            if ((u & himask) == pref) atomicAdd(&hist[(u >> shift) & 255u], 1u);
        }
        __syncthreads();
        if (tid == 0) {
            int kk = s_k; unsigned cum = 0u; int bin = 255;
            for (; bin > 0; bin--) {
                unsigned c = hist[bin];
                if (cum + c >= (unsigned)kk) break;
                cum += c;
            }
            s_prefix = pref | ((unsigned)bin << shift);
            s_k = kk - (int)cum;
        }
        __syncthreads();
    }
    unsigned tu = s_prefix;

    float local = 0.f;
    for (int idx = tid; idx < nb; idx += 256) {
        unsigned u = keys[idx];
        if (u >= tu) local += expf(ord2f(u) - m);
    }
    red[tid] = local; __syncthreads();
    for (int k = 128; k > 0; k >>= 1) { if (tid < k) red[tid] += red[tid+k]; __syncthreads(); }
    if (tid == 0) {
        float denom = red[0] + expf(snk - m);
        tau_o[rowid] = ord2f(tu); m_o[rowid] = m; iv_o[rowid] = 1.f / denom;
    }
}

/* ------------------------------------------------------------------ */
/* o accumulation via HMMA; chunk c handles blocks c, c+8, ..., c+56  */
/* ------------------------------------------------------------------ */
#define AC_SMEM 60416
__global__ void __launch_bounds__(256) k_accum_mma(
    const float* __restrict__ kvc, const int* __restrict__ bt,
    const int* __restrict__ ctxl, const float* __restrict__ kvnew,
    const float* __restrict__ logits, const float* __restrict__ tau_i,
    const float* __restrict__ m_i, const float* __restrict__ iv_i,
    float* __restrict__ opart)
{
    extern __shared__ char sm[];
    uint32_t smb = smem_u32(sm);
    int chunk = blockIdx.x, n = blockIdx.y;
    int ctx = ctxl[n];
    int tid = threadIdx.x, wid = tid >> 5, lane = tid & 31;

    int mt = wid & 1;
    int ng = wid >> 1;
    float acc[6][4];
#pragma unroll
    for (int i = 0; i < 6; i++)
#pragma unroll
        for (int j = 0; j < 4; j++) acc[i][j] = 0.f;

    int ph = tid >> 3, pl0 = (tid & 7) * 8;
    float ptau = tau_i[n*HEADS + ph];
    float pm   = m_i[n*HEADS + ph];
    float piv  = iv_i[n*HEADS + ph];
    int kvrow = tid >> 2, kvqp = tid & 3;

    for (int b8 = 0; b8 < 8; b8++) {
        int b = chunk + 8 * b8;        /* strided */
        int base = b * BS;
        if (base >= ctx) break;
        int blk = bt[n*MAXB + b];
        if (b8) __syncthreads();

        const float* lsrc = logits + ((size_t)(n*HEADS + ph))*LMAX + base + pl0;
#pragma unroll
        for (int j = 0; j < 8; j += 2) {
            float lg0 = lsrc[j], lg1 = lsrc[j+1];
            float p0 = (lg0 >= ptau) ? (expf(lg0 - pm) * piv) : 0.f;
            float p1 = (lg1 >= ptau) ? (expf(lg1 - pm) * piv) : 0.f;
            uint32_t hp, lp;
            split2(p0, p1, hp, lp);
            uint32_t off = (uint32_t)(ph * 144 + (pl0 + j) * 2);
            *(uint32_t*)(sm + off)        = hp;
            *(uint32_t*)(sm + 4608 + off) = lp;
        }
        {
            int lg = base + kvrow;
            const float* src = (lg == ctx - 1) ? (kvnew + (size_t)n*HDIM)
                                               : (kvc + ((size_t)blk*BS + kvrow)*HDIM);
#pragma unroll
            for (int j = 0; j < 12; j++) {
                int d4 = kvqp * 12 + j;
                float4 v = ((const float4*)src)[d4];
                cvt_store(sm + 9216, sm + 34816, (uint32_t)(kvrow * 400 + d4 * 8), v);
            }
        }
        __syncthreads();

#pragma unroll
        for (int ks = 0; ks < 4; ks++) {
            uint32_t ah[4], al[4];
            int arow = mt * 16 + (lane & 15);
            uint32_t aoff = (uint32_t)(arow * 144 + ks * 32 + (lane >> 4) * 16);
            ldm_x4(ah, smb + aoff);
            ldm_x4(al, smb + 4608 + aoff);
            int l_in = ks * 16 + ((lane >> 3) & 1) * 8 + (lane & 7);
#pragma unroll
            for (int t = 0; t < 3; t++) {
                uint32_t dByte = (uint32_t)((ng * 48 + t * 16) * 2 + ((lane >> 4) & 1) * 16);
                uint32_t boff = (uint32_t)(l_in * 400) + dByte;
                uint32_t bh[4], bl[4];
                ldm_x4t(bh, smb + 9216 + boff);
                ldm_x4t(bl, smb + 34816 + boff);
                mma16816(acc[2*t],   ah, bh);
                mma16816(acc[2*t],   ah, bl);
                mma16816(acc[2*t],   al, bh);
                mma16816(acc[2*t+1], ah, bh + 2);
                mma16816(acc[2*t+1], ah, bl + 2);
                mma16816(acc[2*t+1], al, bh + 2);
            }
        }
    }

    float* dst = opart + ((size_t)(chunk * NB + n)) * HEADS * HDIM;
#pragma unroll
    for (int t6 = 0; t6 < 6; t6++) {
        int d = ng * 48 + t6 * 8 + (lane & 3) * 2;
        int h = mt * 16 + (lane >> 2);
        dst[(size_t)h * HDIM + d]           = acc[t6][0];
        dst[(size_t)h * HDIM + d + 1]       = acc[t6][1];
        dst[(size_t)(h + 8) * HDIM + d]     = acc[t6][2];
        dst[(size_t)(h + 8) * HDIM + d + 1] = acc[t6][3];
    }
}

/* reduce 8 o-partials -> bf16 hi/lo pairs */
__global__ void k_reduce_o(const float* __restrict__ opart,
                           __nv_bfloat16* __restrict__ ohi,
                           __nv_bfloat16* __restrict__ olo)
{
    int p = blockIdx.x*256 + threadIdx.x;
    int e0 = 2 * p;
    float v0 = 0.f, v1 = 0.f;
#pragma unroll
    for (int c = 0; c < 8; c++) {
        v0 += opart[(size_t)c*NB*QDIM + e0];
        v1 += opart[(size_t)c*NB*QDIM + e0 + 1];
    }
    uint32_t hp, lp;
    split2(v0, v1, hp, lp);
    ((uint32_t*)ohi)[p] = hp;
    ((uint32_t*)olo)[p] = lp;
}

/* ------------------------------------------------------------------ */
/* host launcher (stream fork/join during graph capture)              */
/* ------------------------------------------------------------------ */
extern "C" void kernel_launch(void* const* d_in, const int* in_sizes, int n_in,
                              void* d_out, int out_size)
{
    const float* x    = (const float*)d_in[0];
    const float* kvc  = (const float*)d_in[1];
    const int*   bt   = (const int*)  d_in[2];
    const int*   ctxl = (const int*)  d_in[3];
    const float* wqa  = (const float*)d_in[5];
    const float* qnw  = (const float*)d_in[6];
    const float* wqb  = (const float*)d_in[7];
    const float* wkv  = (const float*)d_in[8];
    const float* kvnw = (const float*)d_in[9];
    const float* woa  = (const float*)d_in[10];
    const float* wob  = (const float*)d_in[11];
    const float* sink = (const float*)d_in[12];
    float* out = (float*)d_out;

    float *kv, *lg, *tau, *mr, *iv, *op, *part;
    __nv_bfloat16 *xhi, *xlo, *qahi, *qalo, *qhi, *qlo, *oohi, *oolo, *lathi, *latlo;
    cudaGetSymbolAddress((void**)&xhi,  g_xhi);
    cudaGetSymbolAddress((void**)&xlo,  g_xlo);
    cudaGetSymbolAddress((void**)&qahi, g_qahi);
    cudaGetSymbolAddress((void**)&qalo, g_qalo);
    cudaGetSymbolAddress((void**)&kv,   g_kv);
    cudaGetSymbolAddress((void**)&qhi,  g_qhi);
    cudaGetSymbolAddress((void**)&qlo,  g_qlo);
    cudaGetSymbolAddress((void**)&lg,   g_logits);
    cudaGetSymbolAddress((void**)&tau,  g_tau);
    cudaGetSymbolAddress((void**)&mr,   g_mrow);
    cudaGetSymbolAddress((void**)&iv,   g_invden);
    cudaGetSymbolAddress((void**)&op,   g_opart);
    cudaGetSymbolAddress((void**)&oohi, g_oohi);
    cudaGetSymbolAddress((void**)&oolo, g_oolo);
    cudaGetSymbolAddress((void**)&lathi,g_lathi);
    cudaGetSymbolAddress((void**)&latlo,g_latlo);
    cudaGetSymbolAddress((void**)&part, g_part);

    static cudaStream_t s1 = 0;
    static cudaEvent_t  e0 = 0, e1 = 0;
    if (!s1) {
        cudaStreamCreateWithFlags(&s1, cudaStreamNonBlocking);
        cudaEventCreateWithFlags(&e0, cudaEventDisableTiming);
        cudaEventCreateWithFlags(&e1, cudaEventDisableTiming);
        cudaFuncSetAttribute(k_gemm_mma,   cudaFuncAttributeMaxDynamicSharedMemorySize, MM_SMEM);
        cudaFuncSetAttribute(k_logits_mma, cudaFuncAttributeMaxDynamicSharedMemorySize, LG_SMEM);
        cudaFuncSetAttribute(k_accum_mma,  cudaFuncAttributeMaxDynamicSharedMemorySize, AC_SMEM);
    }

    /* ---- x -> bf16 hi/lo ---- */
    k_x2bf<<<NB*DIMX/512, 256>>>(x, xhi, xlo);
    cudaEventRecord(e0, 0);
    cudaStreamWaitEvent(s1, e0, 0);

    /* ---- branch A (stream 0): wq_a -> rms -> wq_b -> rope/split ---- */
    k_gemm_mma<<<dim3(12, 8, 1), 256, MM_SMEM>>>(
        xhi, xlo, DIMX, 0, wqa, DIMX, 0,
        part + PART_QA_OFF, QLRK, 0, (long long)NB*QLRK, 512, QLRK);
    k_fuse_qa<<<NB, 256>>>(part + PART_QA_OFF, qnw, qahi, qalo);
    k_gemm_mma<<<dim3(48, 3, 1), 256, MM_SMEM>>>(
        qahi, qalo, QLRK, 0, wqb, QLRK, 0,
        part + PART_QB_OFF, QDIM, 0, (long long)NB*QDIM, 512, QDIM);
    k_fuse_q<<<NB, 256>>>(part + PART_QB_OFF, ctxl, qhi, qlo);

    /* ---- branch B (stream s1): wkv -> rms+rope ---- */
    k_gemm_mma<<<dim3(2, 16, 1), 256, MM_SMEM, s1>>>(
        xhi, xlo, DIMX, 0, wkv, DIMX, 0,
        part + PART_KV_OFF, HDIM, 0, (long long)NB*HDIM, 256, HDIM);
    k_fuse_kv<<<NB, 64, 0, s1>>>(part + PART_KV_OFF, kvnw, ctxl, kv);
    cudaEventRecord(e1, s1);
    cudaStreamWaitEvent(0, e1, 0);

    /* ---- attention ---- */
    k_logits_mma<<<dim3(16, NB), 256, LG_SMEM>>>(kvc, bt, ctxl, qhi, qlo, kv, lg);
    k_select<<<NB*HEADS, 256>>>(lg, sink, ctxl, tau, mr, iv);
    k_accum_mma<<<dim3(8, NB), 256, AC_SMEM>>>(kvc, bt, ctxl, kv, lg, tau, mr, iv, op);
    k_reduce_o<<<NB*QDIM/512, 256>>>(op, oohi, oolo);

    /* ---- lat = grouped wo_a : split 4 (sequential; reuse offset 0) ---- */
    k_gemm_mma<<<dim3(4, 4, GRP), 256, MM_SMEM>>>(
        oohi, oolo, QDIM, 768, woa, 768, (long long)OLRK*768,
        part, GRP*OLRK, OLRK, (long long)NB*GRP*OLRK, 192, OLRK);
    k_reduce_bf<<<(NB*GRP*OLRK/2+255)/256, 256>>>(part, lathi, latlo,
                                                  NB*GRP*OLRK/2, NB*GRP*OLRK, 4);

    /* ---- out = lat @ wo_b^T : split 4 ---- */
    k_gemm_mma<<<dim3(32, 4, 1), 256, MM_SMEM>>>(
        lathi, latlo, GRP*OLRK, 0, wob, DIMX, 0,
        part, DIMX, 0, (long long)NB*DIMX, 1024, DIMX);
    k_reduce<<<(NB*DIMX+255)/256, 256>>>(part, out, NB*DIMX, 4);
}

// round 10
// speedup vs baseline: 3.9200x; 1.0345x over previous
#include <cuda_runtime.h>
#include <cuda_bf16.h>
#include <math.h>
#include <stdint.h>

#define NB    64
#define DIMX  4096
#define HEADS 32
#define HDIM  192
#define RDIM  64
#define QLRK  1536
#define OLRK  512
#define GRP   8
#define BS    64
#define MAXB  64
#define LMAX  4096
#define TOPKK 1024
#define EPSI  1e-6f
#define NEGF  -1e30f
#define QDIM  (HEADS*HDIM)   /* 6144 */
#define SCALE_F 0.07216878364870323f  /* 192^-0.5 */

/* disjoint split-K partial regions (floats) */
#define PART_QA_OFF 0                         /* 8*98304   = 786432  */
#define PART_KV_OFF 786432                    /* 16*12288  = 196608  */
#define PART_QB_OFF 983040                    /* 3*393216  = 1179648 */
#define PART_TOTAL  2359296                   /* 9 MB */

/* ------------------------------------------------------------------ */
/* scratch                                                            */
/* ------------------------------------------------------------------ */
__device__ __nv_bfloat16 g_xhi[NB*DIMX];
__device__ __nv_bfloat16 g_xlo[NB*DIMX];
__device__ __nv_bfloat16 g_qahi[NB*QLRK];
__device__ __nv_bfloat16 g_qalo[NB*QLRK];
__device__ float g_kv[NB*HDIM];
__device__ __nv_bfloat16 g_qhi[NB*QDIM];
__device__ __nv_bfloat16 g_qlo[NB*QDIM];
__device__ float g_logits[(size_t)NB*HEADS*LMAX];       /* 32 MB */
__device__ float g_tau[NB*HEADS];
__device__ float g_mrow[NB*HEADS];
__device__ float g_invden[NB*HEADS];
__device__ float g_opart[(size_t)8*NB*HEADS*HDIM];      /* 12.6 MB */
__device__ __nv_bfloat16 g_oohi[NB*QDIM];
__device__ __nv_bfloat16 g_oolo[NB*QDIM];
__device__ __nv_bfloat16 g_lathi[NB*GRP*OLRK];
__device__ __nv_bfloat16 g_latlo[NB*GRP*OLRK];
__device__ float g_part[PART_TOTAL];

/* ------------------------------------------------------------------ */
/* helpers                                                            */
/* ------------------------------------------------------------------ */
__device__ __forceinline__ uint32_t smem_u32(const void* p){
    uint32_t a;
    asm("{ .reg .u64 t; cvta.to.shared.u64 t, %1; cvt.u32.u64 %0, t; }"
        : "=r"(a) : "l"(p));
    return a;
}
__device__ __forceinline__ uint32_t sw128(uint32_t b){ return b ^ ((b >> 3) & 0x70); }

/* fast exact split: hi = truncate-to-bf16 (bit prefix), lo = rn(v-hi). */
__device__ __forceinline__ void split2(float x, float y, uint32_t& hp, uint32_t& lp){
    uint32_t bx = __float_as_uint(x), by = __float_as_uint(y);
    uint32_t h;
    asm("prmt.b32 %0, %1, %2, 0x7632;" : "=r"(h) : "r"(bx), "r"(by));
    float fx = __uint_as_float(h << 16);
    float fy = __uint_as_float(h & 0xFFFF0000u);
    float lx = x - fx, ly = y - fy;
    uint32_t l;
    asm("cvt.rn.bf16x2.f32 %0, %1, %2;" : "=r"(l) : "f"(ly), "f"(lx));
    hp = h; lp = l;
}
__device__ __forceinline__ void mma16816(float* c, const uint32_t* a, const uint32_t* b){
    asm volatile("mma.sync.aligned.m16n8k16.row.col.f32.bf16.bf16.f32 "
        "{%0,%1,%2,%3}, {%4,%5,%6,%7}, {%8,%9}, {%0,%1,%2,%3};"
        : "+f"(c[0]), "+f"(c[1]), "+f"(c[2]), "+f"(c[3])
        : "r"(a[0]), "r"(a[1]), "r"(a[2]), "r"(a[3]), "r"(b[0]), "r"(b[1]));
}
__device__ __forceinline__ void ldm_x4(uint32_t* r, uint32_t addr){
    asm volatile("ldmatrix.sync.aligned.m8n8.x4.shared.b16 {%0,%1,%2,%3}, [%4];"
        : "=r"(r[0]), "=r"(r[1]), "=r"(r[2]), "=r"(r[3]) : "r"(addr));
}
__device__ __forceinline__ void ldm_x4t(uint32_t* r, uint32_t addr){
    asm volatile("ldmatrix.sync.aligned.m8n8.x4.trans.shared.b16 {%0,%1,%2,%3}, [%4];"
        : "=r"(r[0]), "=r"(r[1]), "=r"(r[2]), "=r"(r[3]) : "r"(addr));
}
__device__ __forceinline__ void cvt_store(char* hiB, char* loB, uint32_t off, float4 v){
    uint2 hh, ll;
    split2(v.x, v.y, hh.x, ll.x);
    split2(v.z, v.w, hh.y, ll.y);
    *(uint2*)(hiB + off) = hh;
    *(uint2*)(loB + off) = ll;
}

/* ------------------------------------------------------------------ */
/* HMMA GEMM: X pre-converted bf16 hi/lo in gmem; W fp32 (fast split) */
/* ------------------------------------------------------------------ */
#define MM_SMEM 49152
__global__ void __launch_bounds__(256,2) k_gemm_mma(
    const __nv_bfloat16* __restrict__ Xhi, const __nv_bfloat16* __restrict__ Xlo,
    int ldx, long long xGrp,
    const float* __restrict__ W, int ldw, long long wGrp,
    float* __restrict__ C, int ldc, long long cGrp, long long cSplit,
    int Kloc, int Nw)
{
    extern __shared__ char sm[];
    char* sXhi = sm;
    char* sXlo = sm + 8192;
    char* sWhi = sm + 16384;
    char* sWlo = sm + 32768;
    uint32_t smb = smem_u32(sm);

    int tid = threadIdx.x, wid = tid >> 5, lane = tid & 31;
    int n0 = blockIdx.x * 128;
    int s  = blockIdx.y;
    int g  = blockIdx.z;
    Xhi += (size_t)g * xGrp + (size_t)s * Kloc;
    Xlo += (size_t)g * xGrp + (size_t)s * Kloc;
    W   += (size_t)g * wGrp + (size_t)s * Kloc;
    C   += (size_t)g * cGrp + (size_t)s * cSplit;

    int wm = (wid & 3) * 16;
    int wn = (wid >> 2) * 64;

    float acc[8][4];
#pragma unroll
    for (int i = 0; i < 8; i++)
#pragma unroll
        for (int j = 0; j < 4; j++) acc[i][j] = 0.f;

    int xr0 = tid >> 3, xr1 = (tid + 256) >> 3;
    int xc16 = tid & 7;
    int wrow = tid >> 1;
    int wc   = tid & 1;
    int wrg  = n0 + wrow; if (wrg >= Nw) wrg = Nw - 1;

    const int NC = Kloc / 64;
    uint4 xh[2], xl[2];
    float4 wv[8];
    xh[0] = *(const uint4*)(Xhi + (size_t)xr0 * ldx + xc16 * 8);
    xh[1] = *(const uint4*)(Xhi + (size_t)xr1 * ldx + xc16 * 8);
    xl[0] = *(const uint4*)(Xlo + (size_t)xr0 * ldx + xc16 * 8);
    xl[1] = *(const uint4*)(Xlo + (size_t)xr1 * ldx + xc16 * 8);
#pragma unroll
    for (int j = 0; j < 8; j++)
        wv[j] = *(const float4*)(W + (size_t)wrg * ldw + (wc + 2*j) * 4);

    for (int ch = 0; ch < NC; ch++) {
        if (ch) __syncthreads();
        {
            uint32_t o0 = sw128((uint32_t)(xr0 * 128 + xc16 * 16));
            uint32_t o1 = sw128((uint32_t)(xr1 * 128 + xc16 * 16));
            *(uint4*)(sXhi + o0) = xh[0];
            *(uint4*)(sXhi + o1) = xh[1];
            *(uint4*)(sXlo + o0) = xl[0];
            *(uint4*)(sXlo + o1) = xl[1];
        }
#pragma unroll
        for (int j = 0; j < 8; j++) {
            uint32_t off = sw128((uint32_t)(wrow * 128 + (wc + 2*j) * 8));
            cvt_store(sWhi, sWlo, off, wv[j]);
        }
        __syncthreads();
        if (ch + 1 < NC) {
            int kb = (ch + 1) * 64;
            xh[0] = *(const uint4*)(Xhi + (size_t)xr0 * ldx + kb + xc16 * 8);
            xh[1] = *(const uint4*)(Xhi + (size_t)xr1 * ldx + kb + xc16 * 8);
            xl[0] = *(const uint4*)(Xlo + (size_t)xr0 * ldx + kb + xc16 * 8);
            xl[1] = *(const uint4*)(Xlo + (size_t)xr1 * ldx + kb + xc16 * 8);
#pragma unroll
            for (int j = 0; j < 8; j++)
                wv[j] = *(const float4*)(W + (size_t)wrg * ldw + kb + (wc + 2*j) * 4);
        }
#pragma unroll
        for (int ks = 0; ks < 4; ks++) {
            uint32_t ah[4], al[4];
            {
                int arow = wm + (lane & 15);
                uint32_t aoff = sw128((uint32_t)(arow * 128 + (ks*2 + (lane >> 4)) * 16));
                ldm_x4(ah, smb + aoff);
                ldm_x4(al, smb + 8192 + aoff);
            }
#pragma unroll
            for (int t = 0; t < 4; t++) {
                int brow = wn + 16*t + ((lane >> 4) & 1) * 8 + (lane & 7);
                uint32_t boff = sw128((uint32_t)(brow * 128 + (ks*2 + ((lane >> 3) & 1)) * 16));
                uint32_t bh[4], bl[4];
                ldm_x4(bh, smb + 16384 + boff);
                ldm_x4(bl, smb + 32768 + boff);
                mma16816(acc[2*t],   ah, bh);
                mma16816(acc[2*t],   ah, bl);
                mma16816(acc[2*t],   al, bh);
                mma16816(acc[2*t+1], ah, bh + 2);
                mma16816(acc[2*t+1], ah, bl + 2);
                mma16816(acc[2*t+1], al, bh + 2);
            }
        }
    }

    int mr = wm + (lane >> 2);
#pragma unroll
    for (int sub = 0; sub < 8; sub++) {
        int nc = n0 + wn + sub * 8 + (lane & 3) * 2;
        if (nc < Nw) {
            C[(size_t)mr * ldc + nc]       = acc[sub][0];
            C[(size_t)(mr + 8) * ldc + nc] = acc[sub][2];
        }
        if (nc + 1 < Nw) {
            C[(size_t)mr * ldc + nc + 1]       = acc[sub][1];
            C[(size_t)(mr + 8) * ldc + nc + 1] = acc[sub][3];
        }
    }
}

/* generic split-K reduce -> fp32 */
__global__ void k_reduce(const float* __restrict__ part, float* __restrict__ out,
                         int E, int S)
{
    int i = blockIdx.x * 256 + threadIdx.x;
    if (i >= E) return;
    float s = 0.f;
    for (int p = 0; p < S; p++) s += part[(size_t)p * E + i];
    out[i] = s;
}

/* split-K reduce -> bf16 hi/lo pairs */
__global__ void k_reduce_bf(const float* __restrict__ part,
                            __nv_bfloat16* __restrict__ ohi,
                            __nv_bfloat16* __restrict__ olo,
                            int Epairs, int E, int S)
{
    int p = blockIdx.x * 256 + threadIdx.x;
    if (p >= Epairs) return;
    int e0 = 2 * p;
    float v0 = 0.f, v1 = 0.f;
    for (int q = 0; q < S; q++) {
        v0 += part[(size_t)q * E + e0];
        v1 += part[(size_t)q * E + e0 + 1];
    }
    uint32_t hp, lp;
    split2(v0, v1, hp, lp);
    ((uint32_t*)ohi)[p] = hp;
    ((uint32_t*)olo)[p] = lp;
}

/* x fp32 -> bf16 hi/lo */
__global__ void __launch_bounds__(256) k_x2bf(const float* __restrict__ x,
                                              __nv_bfloat16* __restrict__ xhi,
                                              __nv_bfloat16* __restrict__ xlo)
{
    int p = blockIdx.x * 256 + threadIdx.x;
    float2 v = ((const float2*)x)[p];
    uint32_t hp, lp;
    split2(v.x, v.y, hp, lp);
    ((uint32_t*)xhi)[p] = hp;
    ((uint32_t*)xlo)[p] = lp;
}

/* ------------------------------------------------------------------ */
/* fused: reduce 8 partials + RMS(q_norm) -> bf16 hi/lo               */
/* ------------------------------------------------------------------ */
__global__ void __launch_bounds__(256) k_fuse_qa(const float* __restrict__ part,
                                                 const float* __restrict__ wt,
                                                 __nv_bfloat16* __restrict__ qahi,
                                                 __nv_bfloat16* __restrict__ qalo)
{
    __shared__ float red[256];
    int n = blockIdx.x, tid = threadIdx.x;
    float v0[3], v1[3]; float s = 0.f;
#pragma unroll
    for (int i = 0; i < 3; i++) {
        int e0 = 2 * (tid + i*256);
        float a = 0.f, b = 0.f;
#pragma unroll
        for (int p = 0; p < 8; p++) {
            a += part[(size_t)p*NB*QLRK + (size_t)n*QLRK + e0];
            b += part[(size_t)p*NB*QLRK + (size_t)n*QLRK + e0 + 1];
        }
        v0[i] = a; v1[i] = b; s += a*a + b*b;
    }
    red[tid] = s; __syncthreads();
    for (int k = 128; k > 0; k >>= 1) { if (tid < k) red[tid] += red[tid+k]; __syncthreads(); }
    float scale = rsqrtf(red[0] / (float)QLRK + EPSI);
#pragma unroll
    for (int i = 0; i < 3; i++) {
        int p = tid + i*256;
        int e0 = 2 * p;
        float f0 = v0[i] * scale * wt[e0];
        float f1 = v1[i] * scale * wt[e0 + 1];
        uint32_t hp, lp;
        split2(f0, f1, hp, lp);
        ((uint32_t*)qahi)[(size_t)n*(QLRK/2) + p] = hp;
        ((uint32_t*)qalo)[(size_t)n*(QLRK/2) + p] = lp;
    }
}

__device__ __forceinline__ void rope_cs(int i, float pos, float& c, float& s)
{
    float inv = (float)exp(-(double)i * 0.28782313662425574); /* ln(1e4)/32 */
    float ang = pos * inv;
    double ad = (double)ang;
    c = (float)cos(ad); s = (float)sin(ad);
}

/* fused: reduce 16 partials + RMS + rope -> g_kv (fp32)              */
__global__ void k_fuse_kv(const float* __restrict__ part,
                          const float* __restrict__ wt,
                          const int* __restrict__ ctxl,
                          float* __restrict__ kv)
{
    __shared__ float srow[HDIM];
    __shared__ float rs[64];
    int n = blockIdx.x, tid = threadIdx.x;
    float s = 0.f;
#pragma unroll
    for (int j = 0; j < 3; j++) {
        int c = tid + j*64;
        float t = 0.f;
#pragma unroll
        for (int p = 0; p < 16; p++) t += part[(size_t)p*NB*HDIM + (size_t)n*HDIM + c];
        srow[c] = t; s += t*t;
    }
    rs[tid] = s; __syncthreads();
    for (int k = 32; k > 0; k >>= 1) { if (tid < k) rs[tid] += rs[tid+k]; __syncthreads(); }
    float scale = rsqrtf(rs[0] / (float)HDIM + EPSI);
#pragma unroll
    for (int j = 0; j < 3; j++) { int i = tid + j*64; srow[i] = srow[i]*scale*wt[i]; }
    __syncthreads();
    float pos = (float)(ctxl[n] - 1);
    if (tid < 32) {
        int i = tid;
        float x0 = srow[HDIM-RDIM + 2*i], x1 = srow[HDIM-RDIM + 2*i + 1];
        float c, sn; rope_cs(i, pos, c, sn);
        srow[HDIM-RDIM + 2*i]     = x0*c - x1*sn;
        srow[HDIM-RDIM + 2*i + 1] = x0*sn + x1*c;
    }
    __syncthreads();
#pragma unroll
    for (int j = 0; j < 3; j++) { int i = tid + j*64; kv[(size_t)n*HDIM + i] = srow[i]; }
}

/* fused: reduce 3 partials + rope + bf16 split -> g_qhi/g_qlo        */
__global__ void __launch_bounds__(256) k_fuse_q(const float* __restrict__ part,
                                                const int* __restrict__ ctxl,
                                                __nv_bfloat16* __restrict__ qhi,
                                                __nv_bfloat16* __restrict__ qlo)
{
    int n = blockIdx.x, tid = threadIdx.x;
    float pos = (float)(ctxl[n] - 1);
#pragma unroll
    for (int i = 0; i < 12; i++) {
        int p = tid + i*256;
        int e0 = 2*p;
        float v0 = 0.f, v1 = 0.f;
#pragma unroll
        for (int q = 0; q < 3; q++) {
            v0 += part[(size_t)q*NB*QDIM + (size_t)n*QDIM + e0];
            v1 += part[(size_t)q*NB*QDIM + (size_t)n*QDIM + e0 + 1];
        }
        int dd = e0 % HDIM;
        if (dd >= HDIM - RDIM) {
            int ir = (dd - (HDIM - RDIM)) >> 1;
            float c, s; rope_cs(ir, pos, c, s);
            float x0 = v0, x1 = v1;
            v0 = x0*c - x1*s;
            v1 = x0*s + x1*c;
        }
        uint32_t hp, lp;
        split2(v0, v1, hp, lp);
        ((uint32_t*)qhi)[(size_t)n*(QDIM/2) + p] = hp;
        ((uint32_t*)qlo)[(size_t)n*(QDIM/2) + p] = lp;
    }
}

/* ------------------------------------------------------------------ */
/* logits via HMMA: CTA bx handles blocks bx, bx+16, bx+32, bx+48     */
/* ------------------------------------------------------------------ */
#define LG_SMEM 76800
__global__ void __launch_bounds__(256,2) k_logits_mma(
    const float* __restrict__ kvc, const int* __restrict__ bt,
    const int* __restrict__ ctxl,
    const __nv_bfloat16* __restrict__ qhi, const __nv_bfloat16* __restrict__ qlo,
    const float* __restrict__ kvnew, float* __restrict__ logits)
{
    extern __shared__ char sm[];
    uint32_t smb = smem_u32(sm);
    int n = blockIdx.y;
    int ctx = ctxl[n];
    int bx = blockIdx.x;               /* 0..15 */
    if (bx * BS >= ctx) return;
    int tid = threadIdx.x, wid = tid >> 5, lane = tid & 31;

    {
        const char* gh = (const char*)(qhi + (size_t)n * QDIM);
        const char* gl = (const char*)(qlo + (size_t)n * QDIM);
#pragma unroll
        for (int i = 0; i < 3; i++) {
            int c = tid + i * 256;
            int r = c / 24, k16 = c % 24;
            *(uint4*)(sm + r * 400 + k16 * 16) = *(const uint4*)(gh + r * 384 + k16 * 16);
            *(uint4*)(sm + 12800 + r * 400 + k16 * 16) = *(const uint4*)(gl + r * 384 + k16 * 16);
        }
    }

    int mt = wid & 3;
    int nt = wid >> 2;
    int kvrow = tid >> 2, kvqp = tid & 3;

    for (int bi = 0; bi < 4; bi++) {
        int b = bx + 16 * bi;          /* strided */
        int base = b * BS;
        if (base >= ctx) break;
        if (bi) __syncthreads();

        int blk = bt[n * MAXB + b];
        {
            int lg = base + kvrow;
            const float* src = (lg == ctx - 1) ? (kvnew + (size_t)n * HDIM)
                                               : (kvc + ((size_t)blk * BS + kvrow) * HDIM);
#pragma unroll
            for (int j = 0; j < 12; j++) {
                int d4 = kvqp * 12 + j;
                float4 v = ((const float4*)src)[d4];
                cvt_store(sm + 25600, sm + 51200, (uint32_t)(kvrow * 400 + d4 * 8), v);
            }
        }
        __syncthreads();

        float acc[2][4];
#pragma unroll
        for (int i = 0; i < 2; i++)
#pragma unroll
            for (int j = 0; j < 4; j++) acc[i][j] = 0.f;

#pragma unroll
        for (int ks = 0; ks < 12; ks++) {
            uint32_t ah[4], al[4];
            int arow = mt * 16 + (lane & 15);
            uint32_t aoff = (uint32_t)(arow * 400 + ks * 32 + (lane >> 4) * 16);
            ldm_x4(ah, smb + 25600 + aoff);
            ldm_x4(al, smb + 51200 + aoff);
            int brow = nt * 16 + ((lane >> 4) & 1) * 8 + (lane & 7);
            uint32_t boff = (uint32_t)(brow * 400 + ks * 32 + ((lane >> 3) & 1) * 16);
            uint32_t bh[4], bl[4];
            ldm_x4(bh, smb + boff);
            ldm_x4(bl, smb + 12800 + boff);
            mma16816(acc[0], ah, bh);
            mma16816(acc[0], ah, bl);
            mma16816(acc[0], al, bh);
            mma16816(acc[1], ah, bh + 2);
            mma16816(acc[1], ah, bl + 2);
            mma16816(acc[1], al, bh + 2);
        }
        __syncthreads();

        float* D = (float*)(sm + 25600);
#pragma unroll
        for (int n8 = 0; n8 < 2; n8++) {
            int h = nt * 16 + n8 * 8 + (lane & 3) * 2;
            int l = mt * 16 + (lane >> 2);
            D[h * 64 + l]           = acc[n8][0];
            D[(h + 1) * 64 + l]     = acc[n8][1];
            D[h * 64 + l + 8]       = acc[n8][2];
            D[(h + 1) * 64 + l + 8] = acc[n8][3];
        }
        __syncthreads();
        int h = tid >> 3, l0 = (tid & 7) * 8;
        float* dst = logits + ((size_t)(n * HEADS + h)) * LMAX + base + l0;
#pragma unroll
        for (int j = 0; j < 8; j++) {
            int l = l0 + j;
            float v = D[h * 64 + l];
            dst[j] = (base + l < ctx) ? v * SCALE_F : NEGF;
        }
    }
}

/* ------------------------------------------------------------------ */
/* top-k radix select (variable length, parallel suffix-sum scan)     */
/* ------------------------------------------------------------------ */
__device__ __forceinline__ unsigned f2ord(float f) {
    unsigned b = __float_as_uint(f);
    return (b & 0x80000000u) ? ~b : (b | 0x80000000u);
}
__device__ __forceinline__ float ord2f(unsigned u) {
    return (u & 0x80000000u) ? __uint_as_float(u ^ 0x80000000u)
                             : __uint_as_float(~u);
}

__global__ void __launch_bounds__(256) k_select(
    const float* __restrict__ logits, const float* __restrict__ sink,
    const int* __restrict__ ctxl,
    float* __restrict__ tau_o, float* __restrict__ m_o, float* __restrict__ iv_o)
{
    __shared__ unsigned keys[LMAX];
    __shared__ unsigned hist[256];
    __shared__ unsigned sfx[256];
    __shared__ unsigned rmax[256];
    __shared__ float    red[256];
    __shared__ unsigned s_prefix;
    __shared__ int      s_k;

    int rowid = blockIdx.x;
    int n = rowid >> 5;
    int h = rowid & 31;
    int tid = threadIdx.x;
    int ctx = ctxl[n];
    int nb = ((ctx + 63) >> 6) << 6;
    const float* src = logits + (size_t)rowid * LMAX;

    unsigned um = 0u;
    for (int idx = tid; idx < nb; idx += 256) {
        unsigned u = f2ord(src[idx]);
        keys[idx] = u;
        um = max(um, u);
    }
    rmax[tid] = um; __syncthreads();
    for (int k = 128; k > 0; k >>= 1) { if (tid < k) rmax[tid] = max(rmax[tid], rmax[tid+k]); __syncthreads(); }

    float maxf = ord2f(rmax[0]);
    float snk  = sink[h];
    float m    = fmaxf(maxf, snk);

    if (nb <= TOPKK) {
        float local = 0.f;
        for (int idx = tid; idx < nb; idx += 256)
            local += expf(ord2f(keys[idx]) - m);
        red[tid] = local; __syncthreads();
        for (int k = 128; k > 0; k >>= 1) { if (tid < k) red[tid] += red[tid+k]; __syncthreads(); }
        if (tid == 0) {
            float denom = red[0] + expf(snk - m);
            tau_o[rowid] = -__builtin_huge_valf(); m_o[rowid] = m; iv_o[rowid] = 1.f / denom;
        }
        return;
    }

    if (tid == 0) { s_prefix = 0u; s_k = TOPKK; }
    __syncthreads();

    for (int shift = 24; shift >= 0; shift -= 8) {
        hist[tid] = 0u;
        __syncthreads();
        unsigned pref = s_prefix;
        int kk = s_k;
        unsigned himask = (shift == 24) ? 0u : (0xFFFFFFFFu << (shift + 8));
        for (int idx = tid; idx < nb; idx += 256) {
            unsigned u = keys[idx];
            if ((u & himask) == pref) atomicAdd(&hist[(u >> shift) & 255u], 1u);
        }
        __syncthreads();
        /* inclusive suffix sum of hist into sfx */
        sfx[tid] = hist[tid];
        __syncthreads();
#pragma unroll
        for (int st = 1; st < 256; st <<= 1) {
            unsigned v = (tid + st < 256) ? sfx[tid + st] : 0u;
            __syncthreads();
            sfx[tid] += v;
            __syncthreads();
        }
        unsigned Sb  = sfx[tid];
        unsigned Sn  = (tid == 255) ? 0u : sfx[tid + 1];
        if (Sb >= (unsigned)kk && Sn < (unsigned)kk) {
            s_prefix = pref | ((unsigned)tid << shift);
            s_k = kk - (int)Sn;
        }
        __syncthreads();
    }
    unsigned tu = s_prefix;

    float local = 0.f;
    for (int idx = tid; idx < nb; idx += 256) {
        unsigned u = keys[idx];
        if (u >= tu) local += expf(ord2f(u) - m);
    }
    red[tid] = local; __syncthreads();
    for (int k = 128; k > 0; k >>= 1) { if (tid < k) red[tid] += red[tid+k]; __syncthreads(); }
    if (tid == 0) {
        float denom = red[0] + expf(snk - m);
        tau_o[rowid] = ord2f(tu); m_o[rowid] = m; iv_o[rowid] = 1.f / denom;
    }
}

/* ------------------------------------------------------------------ */
/* o accumulation via HMMA; chunk c handles blocks c, c+8, ..., c+56  */
/* ------------------------------------------------------------------ */
#define AC_SMEM 60416
__global__ void __launch_bounds__(256,2) k_accum_mma(
    const float* __restrict__ kvc, const int* __restrict__ bt,
    const int* __restrict__ ctxl, const float* __restrict__ kvnew,
    const float* __restrict__ logits, const float* __restrict__ tau_i,
    const float* __restrict__ m_i, const float* __restrict__ iv_i,
    float* __restrict__ opart)
{
    extern __shared__ char sm[];
    uint32_t smb = smem_u32(sm);
    int chunk = blockIdx.x, n = blockIdx.y;
    int ctx = ctxl[n];
    int tid = threadIdx.x, wid = tid >> 5, lane = tid & 31;

    int mt = wid & 1;
    int ng = wid >> 1;
    float acc[6][4];
#pragma unroll
    for (int i = 0; i < 6; i++)
#pragma unroll
        for (int j = 0; j < 4; j++) acc[i][j] = 0.f;

    int ph = tid >> 3, pl0 = (tid & 7) * 8;
    float ptau = tau_i[n*HEADS + ph];
    float pm   = m_i[n*HEADS + ph];
    float piv  = iv_i[n*HEADS + ph];
    int kvrow = tid >> 2, kvqp = tid & 3;

    for (int b8 = 0; b8 < 8; b8++) {
        int b = chunk + 8 * b8;        /* strided */
        int base = b * BS;
        if (base >= ctx) break;
        int blk = bt[n*MAXB + b];
        if (b8) __syncthreads();

        const float* lsrc = logits + ((size_t)(n*HEADS + ph))*LMAX + base + pl0;
#pragma unroll
        for (int j = 0; j < 8; j += 2) {
            float lg0 = lsrc[j], lg1 = lsrc[j+1];
            float p0 = (lg0 >= ptau) ? (expf(lg0 - pm) * piv) : 0.f;
            float p1 = (lg1 >= ptau) ? (expf(lg1 - pm) * piv) : 0.f;
            uint32_t hp, lp;
            split2(p0, p1, hp, lp);
            uint32_t off = (uint32_t)(ph * 144 + (pl0 + j) * 2);
            *(uint32_t*)(sm + off)        = hp;
            *(uint32_t*)(sm + 4608 + off) = lp;
        }
        {
            int lg = base + kvrow;
            const float* src = (lg == ctx - 1) ? (kvnew + (size_t)n*HDIM)
                                               : (kvc + ((size_t)blk*BS + kvrow)*HDIM);
#pragma unroll
            for (int j = 0; j < 12; j++) {
                int d4 = kvqp * 12 + j;
                float4 v = ((const float4*)src)[d4];
                cvt_store(sm + 9216, sm + 34816, (uint32_t)(kvrow * 400 + d4 * 8), v);
            }
        }
        __syncthreads();

#pragma unroll
        for (int ks = 0; ks < 4; ks++) {
            uint32_t ah[4], al[4];
            int arow = mt * 16 + (lane & 15);
            uint32_t aoff = (uint32_t)(arow * 144 + ks * 32 + (lane >> 4) * 16);
            ldm_x4(ah, smb + aoff);
            ldm_x4(al, smb + 4608 + aoff);
            int l_in = ks * 16 + ((lane >> 3) & 1) * 8 + (lane & 7);
#pragma unroll
            for (int t = 0; t < 3; t++) {
                uint32_t dByte = (uint32_t)((ng * 48 + t * 16) * 2 + ((lane >> 4) & 1) * 16);
                uint32_t boff = (uint32_t)(l_in * 400) + dByte;
                uint32_t bh[4], bl[4];
                ldm_x4t(bh, smb + 9216 + boff);
                ldm_x4t(bl, smb + 34816 + boff);
                mma16816(acc[2*t],   ah, bh);
                mma16816(acc[2*t],   ah, bl);
                mma16816(acc[2*t],   al, bh);
                mma16816(acc[2*t+1], ah, bh + 2);
                mma16816(acc[2*t+1], ah, bl + 2);
                mma16816(acc[2*t+1], al, bh + 2);
            }
        }
    }

    float* dst = opart + ((size_t)(chunk * NB + n)) * HEADS * HDIM;
#pragma unroll
    for (int t6 = 0; t6 < 6; t6++) {
        int d = ng * 48 + t6 * 8 + (lane & 3) * 2;
        int h = mt * 16 + (lane >> 2);
        dst[(size_t)h * HDIM + d]           = acc[t6][0];
        dst[(size_t)h * HDIM + d + 1]       = acc[t6][1];
        dst[(size_t)(h + 8) * HDIM + d]     = acc[t6][2];
        dst[(size_t)(h + 8) * HDIM + d + 1] = acc[t6][3];
    }
}

/* reduce 8 o-partials -> bf16 hi/lo pairs */
__global__ void k_reduce_o(const float* __restrict__ opart,
                           __nv_bfloat16* __restrict__ ohi,
                           __nv_bfloat16* __restrict__ olo)
{
    int p = blockIdx.x*256 + threadIdx.x;
    int e0 = 2 * p;
    float v0 = 0.f, v1 = 0.f;
#pragma unroll
    for (int c = 0; c < 8; c++) {
        v0 += opart[(size_t)c*NB*QDIM + e0];
        v1 += opart[(size_t)c*NB*QDIM + e0 + 1];
    }
    uint32_t hp, lp;
    split2(v0, v1, hp, lp);
    ((uint32_t*)ohi)[p] = hp;
    ((uint32_t*)olo)[p] = lp;
}

/* ------------------------------------------------------------------ */
/* host launcher (stream fork/join during graph capture)              */
/* ------------------------------------------------------------------ */
extern "C" void kernel_launch(void* const* d_in, const int* in_sizes, int n_in,
                              void* d_out, int out_size)
{
    const float* x    = (const float*)d_in[0];
    const float* kvc  = (const float*)d_in[1];
    const int*   bt   = (const int*)  d_in[2];
    const int*   ctxl = (const int*)  d_in[3];
    const float* wqa  = (const float*)d_in[5];
    const float* qnw  = (const float*)d_in[6];
    const float* wqb  = (const float*)d_in[7];
    const float* wkv  = (const float*)d_in[8];
    const float* kvnw = (const float*)d_in[9];
    const float* woa  = (const float*)d_in[10];
    const float* wob  = (const float*)d_in[11];
    const float* sink = (const float*)d_in[12];
    float* out = (float*)d_out;

    float *kv, *lg, *tau, *mr, *iv, *op, *part;
    __nv_bfloat16 *xhi, *xlo, *qahi, *qalo, *qhi, *qlo, *oohi, *oolo, *lathi, *latlo;
    cudaGetSymbolAddress((void**)&xhi,  g_xhi);
    cudaGetSymbolAddress((void**)&xlo,  g_xlo);
    cudaGetSymbolAddress((void**)&qahi, g_qahi);
    cudaGetSymbolAddress((void**)&qalo, g_qalo);
    cudaGetSymbolAddress((void**)&kv,   g_kv);
    cudaGetSymbolAddress((void**)&qhi,  g_qhi);
    cudaGetSymbolAddress((void**)&qlo,  g_qlo);
    cudaGetSymbolAddress((void**)&lg,   g_logits);
    cudaGetSymbolAddress((void**)&tau,  g_tau);
    cudaGetSymbolAddress((void**)&mr,   g_mrow);
    cudaGetSymbolAddress((void**)&iv,   g_invden);
    cudaGetSymbolAddress((void**)&op,   g_opart);
    cudaGetSymbolAddress((void**)&oohi, g_oohi);
    cudaGetSymbolAddress((void**)&oolo, g_oolo);
    cudaGetSymbolAddress((void**)&lathi,g_lathi);
    cudaGetSymbolAddress((void**)&latlo,g_latlo);
    cudaGetSymbolAddress((void**)&part, g_part);

    static cudaStream_t s1 = 0;
    static cudaEvent_t  e0 = 0, e1 = 0;
    if (!s1) {
        cudaStreamCreateWithFlags(&s1, cudaStreamNonBlocking);
        cudaEventCreateWithFlags(&e0, cudaEventDisableTiming);
        cudaEventCreateWithFlags(&e1, cudaEventDisableTiming);
        cudaFuncSetAttribute(k_gemm_mma,   cudaFuncAttributeMaxDynamicSharedMemorySize, MM_SMEM);
        cudaFuncSetAttribute(k_logits_mma, cudaFuncAttributeMaxDynamicSharedMemorySize, LG_SMEM);
        cudaFuncSetAttribute(k_accum_mma,  cudaFuncAttributeMaxDynamicSharedMemorySize, AC_SMEM);
        /* raise smem carveout so 2 CTAs/SM can co-reside */
        cudaFuncSetAttribute(k_gemm_mma,   cudaFuncAttributePreferredSharedMemoryCarveout, 100);
        cudaFuncSetAttribute(k_logits_mma, cudaFuncAttributePreferredSharedMemoryCarveout, 100);
        cudaFuncSetAttribute(k_accum_mma,  cudaFuncAttributePreferredSharedMemoryCarveout, 100);
    }

    /* ---- x -> bf16 hi/lo ---- */
    k_x2bf<<<NB*DIMX/512, 256>>>(x, xhi, xlo);
    cudaEventRecord(e0, 0);
    cudaStreamWaitEvent(s1, e0, 0);

    /* ---- branch A (stream 0): wq_a -> rms -> wq_b -> rope/split ---- */
    k_gemm_mma<<<dim3(12, 8, 1), 256, MM_SMEM>>>(
        xhi, xlo, DIMX, 0, wqa, DIMX, 0,
        part + PART_QA_OFF, QLRK, 0, (long long)NB*QLRK, 512, QLRK);
    k_fuse_qa<<<NB, 256>>>(part + PART_QA_OFF, qnw, qahi, qalo);
    k_gemm_mma<<<dim3(48, 3, 1), 256, MM_SMEM>>>(
        qahi, qalo, QLRK, 0, wqb, QLRK, 0,
        part + PART_QB_OFF, QDIM, 0, (long long)NB*QDIM, 512, QDIM);
    k_fuse_q<<<NB, 256>>>(part + PART_QB_OFF, ctxl, qhi, qlo);

    /* ---- branch B (stream s1): wkv -> rms+rope ---- */
    k_gemm_mma<<<dim3(2, 16, 1), 256, MM_SMEM, s1>>>(
        xhi, xlo, DIMX, 0, wkv, DIMX, 0,
        part + PART_KV_OFF, HDIM, 0, (long long)NB*HDIM, 256, HDIM);
    k_fuse_kv<<<NB, 64, 0, s1>>>(part + PART_KV_OFF, kvnw, ctxl, kv);
    cudaEventRecord(e1, s1);
    cudaStreamWaitEvent(0, e1, 0);

    /* ---- attention ---- */
    k_logits_mma<<<dim3(16, NB), 256, LG_SMEM>>>(kvc, bt, ctxl, qhi, qlo, kv, lg);
    k_select<<<NB*HEADS, 256>>>(lg, sink, ctxl, tau, mr, iv);
    k_accum_mma<<<dim3(8, NB), 256, AC_SMEM>>>(kvc, bt, ctxl, kv, lg, tau, mr, iv, op);
    k_reduce_o<<<NB*QDIM/512, 256>>>(op, oohi, oolo);

    /* ---- lat = grouped wo_a : split 4 (sequential; reuse offset 0) ---- */
    k_gemm_mma<<<dim3(4, 4, GRP), 256, MM_SMEM>>>(
        oohi, oolo, QDIM, 768, woa, 768, (long long)OLRK*768,
        part, GRP*OLRK, OLRK, (long long)NB*GRP*OLRK, 192, OLRK);
    k_reduce_bf<<<(NB*GRP*OLRK/2+255)/256, 256>>>(part, lathi, latlo,
                                                  NB*GRP*OLRK/2, NB*GRP*OLRK, 4);

    /* ---- out = lat @ wo_b^T : split 8 ---- */
    k_gemm_mma<<<dim3(32, 8, 1), 256, MM_SMEM>>>(
        lathi, latlo, GRP*OLRK, 0, wob, DIMX, 0,
        part, DIMX, 0, (long long)NB*DIMX, 512, DIMX);
    k_reduce<<<(NB*DIMX+255)/256, 256>>>(part, out, NB*DIMX, 8);
}

// round 11
// speedup vs baseline: 4.5668x; 1.1650x over previous
#include <cuda_runtime.h>
#include <cuda_bf16.h>
#include <math.h>
#include <stdint.h>

#define NB    64
#define DIMX  4096
#define HEADS 32
#define HDIM  192
#define RDIM  64
#define QLRK  1536
#define OLRK  512
#define GRP   8
#define BS    64
#define MAXB  64
#define LMAX  4096
#define TOPKK 1024
#define EPSI  1e-6f
#define NEGF  -1e30f
#define QDIM  (HEADS*HDIM)   /* 6144 */
#define SCALE_F 0.07216878364870323f  /* 192^-0.5 */

/* disjoint split-K partial regions (floats) */
#define PART_QA_OFF 0                         /* 16*98304  = 1572864 */
#define PART_KV_OFF 1572864                   /* 32*12288  = 393216  */
#define PART_QB_OFF 1966080                   /* 6*393216  = 2359296 */
#define PART_TOTAL  4325376                   /* 16.5 MB */

/* ------------------------------------------------------------------ */
/* scratch                                                            */
/* ------------------------------------------------------------------ */
__device__ __nv_bfloat16 g_xhi[NB*DIMX];
__device__ __nv_bfloat16 g_xlo[NB*DIMX];
__device__ __nv_bfloat16 g_qahi[NB*QLRK];
__device__ __nv_bfloat16 g_qalo[NB*QLRK];
__device__ float g_kv[NB*HDIM];
__device__ __nv_bfloat16 g_qhi[NB*QDIM];
__device__ __nv_bfloat16 g_qlo[NB*QDIM];
__device__ float g_logits[(size_t)NB*HEADS*LMAX];       /* 32 MB */
__device__ float g_tau[NB*HEADS];
__device__ float g_mrow[NB*HEADS];
__device__ float g_invden[NB*HEADS];
__device__ float g_opart[(size_t)8*NB*HEADS*HDIM];      /* 12.6 MB */
__device__ __nv_bfloat16 g_oohi[NB*QDIM];
__device__ __nv_bfloat16 g_oolo[NB*QDIM];
__device__ __nv_bfloat16 g_lathi[NB*GRP*OLRK];
__device__ __nv_bfloat16 g_latlo[NB*GRP*OLRK];
__device__ float g_part[PART_TOTAL];

/* ------------------------------------------------------------------ */
/* helpers                                                            */
/* ------------------------------------------------------------------ */
__device__ __forceinline__ uint32_t smem_u32(const void* p){
    uint32_t a;
    asm("{ .reg .u64 t; cvta.to.shared.u64 t, %1; cvt.u32.u64 %0, t; }"
        : "=r"(a) : "l"(p));
    return a;
}
__device__ __forceinline__ uint32_t sw128(uint32_t b){ return b ^ ((b >> 3) & 0x70); }

/* fast exact split: hi = truncate-to-bf16 (bit prefix), lo = rn(v-hi). */
__device__ __forceinline__ void split2(float x, float y, uint32_t& hp, uint32_t& lp){
    uint32_t bx = __float_as_uint(x), by = __float_as_uint(y);
    uint32_t h;
    asm("prmt.b32 %0, %1, %2, 0x7632;" : "=r"(h) : "r"(bx), "r"(by));
    float fx = __uint_as_float(h << 16);
    float fy = __uint_as_float(h & 0xFFFF0000u);
    float lx = x - fx, ly = y - fy;
    uint32_t l;
    asm("cvt.rn.bf16x2.f32 %0, %1, %2;" : "=r"(l) : "f"(ly), "f"(lx));
    hp = h; lp = l;
}
__device__ __forceinline__ void mma16816(float* c, const uint32_t* a, const uint32_t* b){
    asm volatile("mma.sync.aligned.m16n8k16.row.col.f32.bf16.bf16.f32 "
        "{%0,%1,%2,%3}, {%4,%5,%6,%7}, {%8,%9}, {%0,%1,%2,%3};"
        : "+f"(c[0]), "+f"(c[1]), "+f"(c[2]), "+f"(c[3])
        : "r"(a[0]), "r"(a[1]), "r"(a[2]), "r"(a[3]), "r"(b[0]), "r"(b[1]));
}
__device__ __forceinline__ void ldm_x4(uint32_t* r, uint32_t addr){
    asm volatile("ldmatrix.sync.aligned.m8n8.x4.shared.b16 {%0,%1,%2,%3}, [%4];"
        : "=r"(r[0]), "=r"(r[1]), "=r"(r[2]), "=r"(r[3]) : "r"(addr));
}
__device__ __forceinline__ void ldm_x4t(uint32_t* r, uint32_t addr){
    asm volatile("ldmatrix.sync.aligned.m8n8.x4.trans.shared.b16 {%0,%1,%2,%3}, [%4];"
        : "=r"(r[0]), "=r"(r[1]), "=r"(r[2]), "=r"(r[3]) : "r"(addr));
}
__device__ __forceinline__ void cvt_store(char* hiB, char* loB, uint32_t off, float4 v){
    uint2 hh, ll;
    split2(v.x, v.y, hh.x, ll.x);
    split2(v.z, v.w, hh.y, ll.y);
    *(uint2*)(hiB + off) = hh;
    *(uint2*)(loB + off) = ll;
}

/* ------------------------------------------------------------------ */
/* HMMA GEMM: X pre-converted bf16 hi/lo in gmem; W fp32 (fast split) */
/* ------------------------------------------------------------------ */
#define MM_SMEM 49152
__global__ void __launch_bounds__(256,2) k_gemm_mma(
    const __nv_bfloat16* __restrict__ Xhi, const __nv_bfloat16* __restrict__ Xlo,
    int ldx, long long xGrp,
    const float* __restrict__ W, int ldw, long long wGrp,
    float* __restrict__ C, int ldc, long long cGrp, long long cSplit,
    int Kloc, int Nw)
{
    extern __shared__ char sm[];
    char* sXhi = sm;
    char* sXlo = sm + 8192;
    char* sWhi = sm + 16384;
    char* sWlo = sm + 32768;
    uint32_t smb = smem_u32(sm);

    int tid = threadIdx.x, wid = tid >> 5, lane = tid & 31;
    int n0 = blockIdx.x * 128;
    int s  = blockIdx.y;
    int g  = blockIdx.z;
    Xhi += (size_t)g * xGrp + (size_t)s * Kloc;
    Xlo += (size_t)g * xGrp + (size_t)s * Kloc;
    W   += (size_t)g * wGrp + (size_t)s * Kloc;
    C   += (size_t)g * cGrp + (size_t)s * cSplit;

    int wm = (wid & 3) * 16;
    int wn = (wid >> 2) * 64;

    float acc[8][4];
#pragma unroll
    for (int i = 0; i < 8; i++)
#pragma unroll
        for (int j = 0; j < 4; j++) acc[i][j] = 0.f;

    int xr0 = tid >> 3, xr1 = (tid + 256) >> 3;
    int xc16 = tid & 7;
    int wrow = tid >> 1;
    int wc   = tid & 1;
    int wrg  = n0 + wrow; if (wrg >= Nw) wrg = Nw - 1;

    const int NC = Kloc / 64;
    uint4 xh[2], xl[2];
    float4 wv[8];
    xh[0] = *(const uint4*)(Xhi + (size_t)xr0 * ldx + xc16 * 8);
    xh[1] = *(const uint4*)(Xhi + (size_t)xr1 * ldx + xc16 * 8);
    xl[0] = *(const uint4*)(Xlo + (size_t)xr0 * ldx + xc16 * 8);
    xl[1] = *(const uint4*)(Xlo + (size_t)xr1 * ldx + xc16 * 8);
#pragma unroll
    for (int j = 0; j < 8; j++)
        wv[j] = *(const float4*)(W + (size_t)wrg * ldw + (wc + 2*j) * 4);

    for (int ch = 0; ch < NC; ch++) {
        if (ch) __syncthreads();
        {
            uint32_t o0 = sw128((uint32_t)(xr0 * 128 + xc16 * 16));
            uint32_t o1 = sw128((uint32_t)(xr1 * 128 + xc16 * 16));
            *(uint4*)(sXhi + o0) = xh[0];
            *(uint4*)(sXhi + o1) = xh[1];
            *(uint4*)(sXlo + o0) = xl[0];
            *(uint4*)(sXlo + o1) = xl[1];
        }
#pragma unroll
        for (int j = 0; j < 8; j++) {
            uint32_t off = sw128((uint32_t)(wrow * 128 + (wc + 2*j) * 8));
            cvt_store(sWhi, sWlo, off, wv[j]);
        }
        __syncthreads();
        if (ch + 1 < NC) {
            int kb = (ch + 1) * 64;
            xh[0] = *(const uint4*)(Xhi + (size_t)xr0 * ldx + kb + xc16 * 8);
            xh[1] = *(const uint4*)(Xhi + (size_t)xr1 * ldx + kb + xc16 * 8);
            xl[0] = *(const uint4*)(Xlo + (size_t)xr0 * ldx + kb + xc16 * 8);
            xl[1] = *(const uint4*)(Xlo + (size_t)xr1 * ldx + kb + xc16 * 8);
#pragma unroll
            for (int j = 0; j < 8; j++)
                wv[j] = *(const float4*)(W + (size_t)wrg * ldw + kb + (wc + 2*j) * 4);
        }
#pragma unroll
        for (int ks = 0; ks < 4; ks++) {
            uint32_t ah[4], al[4];
            {
                int arow = wm + (lane & 15);
                uint32_t aoff = sw128((uint32_t)(arow * 128 + (ks*2 + (lane >> 4)) * 16));
                ldm_x4(ah, smb + aoff);
                ldm_x4(al, smb + 8192 + aoff);
            }
#pragma unroll
            for (int t = 0; t < 4; t++) {
                int brow = wn + 16*t + ((lane >> 4) & 1) * 8 + (lane & 7);
                uint32_t boff = sw128((uint32_t)(brow * 128 + (ks*2 + ((lane >> 3) & 1)) * 16));
                uint32_t bh[4], bl[4];
                ldm_x4(bh, smb + 16384 + boff);
                ldm_x4(bl, smb + 32768 + boff);
                mma16816(acc[2*t],   ah, bh);
                mma16816(acc[2*t],   ah, bl);
                mma16816(acc[2*t],   al, bh);
                mma16816(acc[2*t+1], ah, bh + 2);
                mma16816(acc[2*t+1], ah, bl + 2);
                mma16816(acc[2*t+1], al, bh + 2);
            }
        }
    }

    int mr = wm + (lane >> 2);
#pragma unroll
    for (int sub = 0; sub < 8; sub++) {
        int nc = n0 + wn + sub * 8 + (lane & 3) * 2;
        if (nc < Nw) {
            C[(size_t)mr * ldc + nc]       = acc[sub][0];
            C[(size_t)(mr + 8) * ldc + nc] = acc[sub][2];
        }
        if (nc + 1 < Nw) {
            C[(size_t)mr * ldc + nc + 1]       = acc[sub][1];
            C[(size_t)(mr + 8) * ldc + nc + 1] = acc[sub][3];
        }
    }
}

/* generic split-K reduce -> fp32 */
__global__ void k_reduce(const float* __restrict__ part, float* __restrict__ out,
                         int E, int S)
{
    int i = blockIdx.x * 256 + threadIdx.x;
    if (i >= E) return;
    float s = 0.f;
    for (int p = 0; p < S; p++) s += part[(size_t)p * E + i];
    out[i] = s;
}

/* split-K reduce -> bf16 hi/lo pairs */
__global__ void k_reduce_bf(const float* __restrict__ part,
                            __nv_bfloat16* __restrict__ ohi,
                            __nv_bfloat16* __restrict__ olo,
                            int Epairs, int E, int S)
{
    int p = blockIdx.x * 256 + threadIdx.x;
    if (p >= Epairs) return;
    int e0 = 2 * p;
    float v0 = 0.f, v1 = 0.f;
    for (int q = 0; q < S; q++) {
        v0 += part[(size_t)q * E + e0];
        v1 += part[(size_t)q * E + e0 + 1];
    }
    uint32_t hp, lp;
    split2(v0, v1, hp, lp);
    ((uint32_t*)ohi)[p] = hp;
    ((uint32_t*)olo)[p] = lp;
}

/* x fp32 -> bf16 hi/lo */
__global__ void __launch_bounds__(256) k_x2bf(const float* __restrict__ x,
                                              __nv_bfloat16* __restrict__ xhi,
                                              __nv_bfloat16* __restrict__ xlo)
{
    int p = blockIdx.x * 256 + threadIdx.x;
    float2 v = ((const float2*)x)[p];
    uint32_t hp, lp;
    split2(v.x, v.y, hp, lp);
    ((uint32_t*)xhi)[p] = hp;
    ((uint32_t*)xlo)[p] = lp;
}

/* ------------------------------------------------------------------ */
/* fused: reduce 16 partials + RMS(q_norm) -> bf16 hi/lo              */
/* ------------------------------------------------------------------ */
__global__ void __launch_bounds__(256) k_fuse_qa(const float* __restrict__ part,
                                                 const float* __restrict__ wt,
                                                 __nv_bfloat16* __restrict__ qahi,
                                                 __nv_bfloat16* __restrict__ qalo)
{
    __shared__ float red[256];
    int n = blockIdx.x, tid = threadIdx.x;
    float v0[3], v1[3]; float s = 0.f;
#pragma unroll
    for (int i = 0; i < 3; i++) {
        int e0 = 2 * (tid + i*256);
        float a = 0.f, b = 0.f;
#pragma unroll
        for (int p = 0; p < 16; p++) {
            a += part[(size_t)p*NB*QLRK + (size_t)n*QLRK + e0];
            b += part[(size_t)p*NB*QLRK + (size_t)n*QLRK + e0 + 1];
        }
        v0[i] = a; v1[i] = b; s += a*a + b*b;
    }
    red[tid] = s; __syncthreads();
    for (int k = 128; k > 0; k >>= 1) { if (tid < k) red[tid] += red[tid+k]; __syncthreads(); }
    float scale = rsqrtf(red[0] / (float)QLRK + EPSI);
#pragma unroll
    for (int i = 0; i < 3; i++) {
        int p = tid + i*256;
        int e0 = 2 * p;
        float f0 = v0[i] * scale * wt[e0];
        float f1 = v1[i] * scale * wt[e0 + 1];
        uint32_t hp, lp;
        split2(f0, f1, hp, lp);
        ((uint32_t*)qahi)[(size_t)n*(QLRK/2) + p] = hp;
        ((uint32_t*)qalo)[(size_t)n*(QLRK/2) + p] = lp;
    }
}

__device__ __forceinline__ void rope_cs(int i, float pos, float& c, float& s)
{
    float inv = (float)exp(-(double)i * 0.28782313662425574); /* ln(1e4)/32 */
    float ang = pos * inv;
    double ad = (double)ang;
    c = (float)cos(ad); s = (float)sin(ad);
}

/* fused: reduce 32 partials + RMS + rope -> g_kv (fp32)              */
__global__ void k_fuse_kv(const float* __restrict__ part,
                          const float* __restrict__ wt,
                          const int* __restrict__ ctxl,
                          float* __restrict__ kv)
{
    __shared__ float srow[HDIM];
    __shared__ float rs[64];
    int n = blockIdx.x, tid = threadIdx.x;
    float s = 0.f;
#pragma unroll
    for (int j = 0; j < 3; j++) {
        int c = tid + j*64;
        float t = 0.f;
#pragma unroll
        for (int p = 0; p < 32; p++) t += part[(size_t)p*NB*HDIM + (size_t)n*HDIM + c];
        srow[c] = t; s += t*t;
    }
    rs[tid] = s; __syncthreads();
    for (int k = 32; k > 0; k >>= 1) { if (tid < k) rs[tid] += rs[tid+k]; __syncthreads(); }
    float scale = rsqrtf(rs[0] / (float)HDIM + EPSI);
#pragma unroll
    for (int j = 0; j < 3; j++) { int i = tid + j*64; srow[i] = srow[i]*scale*wt[i]; }
    __syncthreads();
    float pos = (float)(ctxl[n] - 1);
    if (tid < 32) {
        int i = tid;
        float x0 = srow[HDIM-RDIM + 2*i], x1 = srow[HDIM-RDIM + 2*i + 1];
        float c, sn; rope_cs(i, pos, c, sn);
        srow[HDIM-RDIM + 2*i]     = x0*c - x1*sn;
        srow[HDIM-RDIM + 2*i + 1] = x0*sn + x1*c;
    }
    __syncthreads();
#pragma unroll
    for (int j = 0; j < 3; j++) { int i = tid + j*64; kv[(size_t)n*HDIM + i] = srow[i]; }
}

/* fused: reduce 6 partials + rope + bf16 split -> g_qhi/g_qlo        */
__global__ void __launch_bounds__(256) k_fuse_q(const float* __restrict__ part,
                                                const int* __restrict__ ctxl,
                                                __nv_bfloat16* __restrict__ qhi,
                                                __nv_bfloat16* __restrict__ qlo)
{
    int n = blockIdx.x, tid = threadIdx.x;
    float pos = (float)(ctxl[n] - 1);
#pragma unroll
    for (int i = 0; i < 12; i++) {
        int p = tid + i*256;
        int e0 = 2*p;
        float v0 = 0.f, v1 = 0.f;
#pragma unroll
        for (int q = 0; q < 6; q++) {
            v0 += part[(size_t)q*NB*QDIM + (size_t)n*QDIM + e0];
            v1 += part[(size_t)q*NB*QDIM + (size_t)n*QDIM + e0 + 1];
        }
        int dd = e0 % HDIM;
        if (dd >= HDIM - RDIM) {
            int ir = (dd - (HDIM - RDIM)) >> 1;
            float c, s; rope_cs(ir, pos, c, s);
            float x0 = v0, x1 = v1;
            v0 = x0*c - x1*s;
            v1 = x0*s + x1*c;
        }
        uint32_t hp, lp;
        split2(v0, v1, hp, lp);
        ((uint32_t*)qhi)[(size_t)n*(QDIM/2) + p] = hp;
        ((uint32_t*)qlo)[(size_t)n*(QDIM/2) + p] = lp;
    }
}

/* ------------------------------------------------------------------ */
/* logits via HMMA: CTA bx handles blocks bx, bx+16, bx+32, bx+48     */
/* ------------------------------------------------------------------ */
#define LG_SMEM 76800
__global__ void __launch_bounds__(256,2) k_logits_mma(
    const float* __restrict__ kvc, const int* __restrict__ bt,
    const int* __restrict__ ctxl,
    const __nv_bfloat16* __restrict__ qhi, const __nv_bfloat16* __restrict__ qlo,
    const float* __restrict__ kvnew, float* __restrict__ logits)
{
    extern __shared__ char sm[];
    uint32_t smb = smem_u32(sm);
    int n = blockIdx.y;
    int ctx = ctxl[n];
    int bx = blockIdx.x;               /* 0..15 */
    if (bx * BS >= ctx) return;
    int tid = threadIdx.x, wid = tid >> 5, lane = tid & 31;

    {
        const char* gh = (const char*)(qhi + (size_t)n * QDIM);
        const char* gl = (const char*)(qlo + (size_t)n * QDIM);
#pragma unroll
        for (int i = 0; i < 3; i++) {
            int c = tid + i * 256;
            int r = c / 24, k16 = c % 24;
            *(uint4*)(sm + r * 400 + k16 * 16) = *(const uint4*)(gh + r * 384 + k16 * 16);
            *(uint4*)(sm + 12800 + r * 400 + k16 * 16) = *(const uint4*)(gl + r * 384 + k16 * 16);
        }
    }

    int mt = wid & 3;
    int nt = wid >> 2;
    int kvrow = tid >> 2, kvqp = tid & 3;

    for (int bi = 0; bi < 4; bi++) {
        int b = bx + 16 * bi;          /* strided */
        int base = b * BS;
        if (base >= ctx) break;
        if (bi) __syncthreads();

        int blk = bt[n * MAXB + b];
        {
            int lg = base + kvrow;
            const float* src = (lg == ctx - 1) ? (kvnew + (size_t)n * HDIM)
                                               : (kvc + ((size_t)blk * BS + kvrow) * HDIM);
#pragma unroll
            for (int j = 0; j < 12; j++) {
                int d4 = kvqp * 12 + j;
                float4 v = ((const float4*)src)[d4];
                cvt_store(sm + 25600, sm + 51200, (uint32_t)(kvrow * 400 + d4 * 8), v);
            }
        }
        __syncthreads();

        float acc[2][4];
#pragma unroll
        for (int i = 0; i < 2; i++)
#pragma unroll
            for (int j = 0; j < 4; j++) acc[i][j] = 0.f;

#pragma unroll
        for (int ks = 0; ks < 12; ks++) {
            uint32_t ah[4], al[4];
            int arow = mt * 16 + (lane & 15);
            uint32_t aoff = (uint32_t)(arow * 400 + ks * 32 + (lane >> 4) * 16);
            ldm_x4(ah, smb + 25600 + aoff);
            ldm_x4(al, smb + 51200 + aoff);
            int brow = nt * 16 + ((lane >> 4) & 1) * 8 + (lane & 7);
            uint32_t boff = (uint32_t)(brow * 400 + ks * 32 + ((lane >> 3) & 1) * 16);
            uint32_t bh[4], bl[4];
            ldm_x4(bh, smb + boff);
            ldm_x4(bl, smb + 12800 + boff);
            mma16816(acc[0], ah, bh);
            mma16816(acc[0], ah, bl);
            mma16816(acc[0], al, bh);
            mma16816(acc[1], ah, bh + 2);
            mma16816(acc[1], ah, bl + 2);
            mma16816(acc[1], al, bh + 2);
        }
        __syncthreads();

        float* D = (float*)(sm + 25600);
#pragma unroll
        for (int n8 = 0; n8 < 2; n8++) {
            int h = nt * 16 + n8 * 8 + (lane & 3) * 2;
            int l = mt * 16 + (lane >> 2);
            D[h * 64 + l]           = acc[n8][0];
            D[(h + 1) * 64 + l]     = acc[n8][1];
            D[h * 64 + l + 8]       = acc[n8][2];
            D[(h + 1) * 64 + l + 8] = acc[n8][3];
        }
        __syncthreads();
        int h = tid >> 3, l0 = (tid & 7) * 8;
        float* dst = logits + ((size_t)(n * HEADS + h)) * LMAX + base + l0;
#pragma unroll
        for (int j = 0; j < 8; j++) {
            int l = l0 + j;
            float v = D[h * 64 + l];
            dst[j] = (base + l < ctx) ? v * SCALE_F : NEGF;
        }
    }
}

/* ------------------------------------------------------------------ */
/* top-k radix select (variable length, parallel suffix-sum scan)     */
/* ------------------------------------------------------------------ */
__device__ __forceinline__ unsigned f2ord(float f) {
    unsigned b = __float_as_uint(f);
    return (b & 0x80000000u) ? ~b : (b | 0x80000000u);
}
__device__ __forceinline__ float ord2f(unsigned u) {
    return (u & 0x80000000u) ? __uint_as_float(u ^ 0x80000000u)
                             : __uint_as_float(~u);
}

__global__ void __launch_bounds__(256) k_select(
    const float* __restrict__ logits, const float* __restrict__ sink,
    const int* __restrict__ ctxl,
    float* __restrict__ tau_o, float* __restrict__ m_o, float* __restrict__ iv_o)
{
    __shared__ unsigned keys[LMAX];
    __shared__ unsigned hist[256];
    __shared__ unsigned sfx[256];
    __shared__ unsigned rmax[256];
    __shared__ float    red[256];
    __shared__ unsigned s_prefix;
    __shared__ int      s_k;

    int rowid = blockIdx.x;
    int n = rowid >> 5;
    int h = rowid & 31;
    int tid = threadIdx.x;
    int ctx = ctxl[n];
    int nb = ((ctx + 63) >> 6) << 6;
    const float* src = logits + (size_t)rowid * LMAX;

    unsigned um = 0u;
    for (int idx = tid; idx < nb; idx += 256) {
        unsigned u = f2ord(src[idx]);
        keys[idx] = u;
        um = max(um, u);
    }
    rmax[tid] = um; __syncthreads();
    for (int k = 128; k > 0; k >>= 1) { if (tid < k) rmax[tid] = max(rmax[tid], rmax[tid+k]); __syncthreads(); }

    float maxf = ord2f(rmax[0]);
    float snk  = sink[h];
    float m    = fmaxf(maxf, snk);

    if (nb <= TOPKK) {
        float local = 0.f;
        for (int idx = tid; idx < nb; idx += 256)
            local += expf(ord2f(keys[idx]) - m);
        red[tid] = local; __syncthreads();
        for (int k = 128; k > 0; k >>= 1) { if (tid < k) red[tid] += red[tid+k]; __syncthreads(); }
        if (tid == 0) {
            float denom = red[0] + expf(snk - m);
            tau_o[rowid] = -__builtin_huge_valf(); m_o[rowid] = m; iv_o[rowid] = 1.f / denom;
        }
        return;
    }

    if (tid == 0) { s_prefix = 0u; s_k = TOPKK; }
    __syncthreads();

    for (int shift = 24; shift >= 0; shift -= 8) {
        hist[tid] = 0u;
        __syncthreads();
        unsigned pref = s_prefix;
        int kk = s_k;
        unsigned himask = (shift == 24) ? 0u : (0xFFFFFFFFu << (shift + 8));
        for (int idx = tid; idx < nb; idx += 256) {
            unsigned u = keys[idx];
            if ((u & himask) == pref) atomicAdd(&hist[(u >> shift) & 255u], 1u);
        }
        __syncthreads();
        /* inclusive suffix sum of hist into sfx */
        sfx[tid] = hist[tid];
        __syncthreads();
#pragma unroll
        for (int st = 1; st < 256; st <<= 1) {
            unsigned v = (tid + st < 256) ? sfx[tid + st] : 0u;
            __syncthreads();
            sfx[tid] += v;
            __syncthreads();
        }
        unsigned Sb  = sfx[tid];
        unsigned Sn  = (tid == 255) ? 0u : sfx[tid + 1];
        if (Sb >= (unsigned)kk && Sn < (unsigned)kk) {
            s_prefix = pref | ((unsigned)tid << shift);
            s_k = kk - (int)Sn;
        }
        __syncthreads();
    }
    unsigned tu = s_prefix;

    float local = 0.f;
    for (int idx = tid; idx < nb; idx += 256) {
        unsigned u = keys[idx];
        if (u >= tu) local += expf(ord2f(u) - m);
    }
    red[tid] = local; __syncthreads();
    for (int k = 128; k > 0; k >>= 1) { if (tid < k) red[tid] += red[tid+k]; __syncthreads(); }
    if (tid == 0) {
        float denom = red[0] + expf(snk - m);
        tau_o[rowid] = ord2f(tu); m_o[rowid] = m; iv_o[rowid] = 1.f / denom;
    }
}

/* ------------------------------------------------------------------ */
/* o accumulation via HMMA; chunk c handles blocks c, c+8, ..., c+56  */
/* ------------------------------------------------------------------ */
#define AC_SMEM 60416
__global__ void __launch_bounds__(256,2) k_accum_mma(
    const float* __restrict__ kvc, const int* __restrict__ bt,
    const int* __restrict__ ctxl, const float* __restrict__ kvnew,
    const float* __restrict__ logits, const float* __restrict__ tau_i,
    const float* __restrict__ m_i, const float* __restrict__ iv_i,
    float* __restrict__ opart)
{
    extern __shared__ char sm[];
    uint32_t smb = smem_u32(sm);
    int chunk = blockIdx.x, n = blockIdx.y;
    int ctx = ctxl[n];
    int tid = threadIdx.x, wid = tid >> 5, lane = tid & 31;

    int mt = wid & 1;
    int ng = wid >> 1;
    float acc[6][4];
#pragma unroll
    for (int i = 0; i < 6; i++)
#pragma unroll
        for (int j = 0; j < 4; j++) acc[i][j] = 0.f;

    int ph = tid >> 3, pl0 = (tid & 7) * 8;
    float ptau = tau_i[n*HEADS + ph];
    float pm   = m_i[n*HEADS + ph];
    float piv  = iv_i[n*HEADS + ph];
    int kvrow = tid >> 2, kvqp = tid & 3;

    for (int b8 = 0; b8 < 8; b8++) {
        int b = chunk + 8 * b8;        /* strided */
        int base = b * BS;
        if (base >= ctx) break;
        int blk = bt[n*MAXB + b];
        if (b8) __syncthreads();

        const float* lsrc = logits + ((size_t)(n*HEADS + ph))*LMAX + base + pl0;
#pragma unroll
        for (int j = 0; j < 8; j += 2) {
            float lg0 = lsrc[j], lg1 = lsrc[j+1];
            float p0 = (lg0 >= ptau) ? (expf(lg0 - pm) * piv) : 0.f;
            float p1 = (lg1 >= ptau) ? (expf(lg1 - pm) * piv) : 0.f;
            uint32_t hp, lp;
            split2(p0, p1, hp, lp);
            uint32_t off = (uint32_t)(ph * 144 + (pl0 + j) * 2);
            *(uint32_t*)(sm + off)        = hp;
            *(uint32_t*)(sm + 4608 + off) = lp;
        }
        {
            int lg = base + kvrow;
            const float* src = (lg == ctx - 1) ? (kvnew + (size_t)n*HDIM)
                                               : (kvc + ((size_t)blk*BS + kvrow)*HDIM);
#pragma unroll
            for (int j = 0; j < 12; j++) {
                int d4 = kvqp * 12 + j;
                float4 v = ((const float4*)src)[d4];
                cvt_store(sm + 9216, sm + 34816, (uint32_t)(kvrow * 400 + d4 * 8), v);
            }
        }
        __syncthreads();

#pragma unroll
        for (int ks = 0; ks < 4; ks++) {
            uint32_t ah[4], al[4];
            int arow = mt * 16 + (lane & 15);
            uint32_t aoff = (uint32_t)(arow * 144 + ks * 32 + (lane >> 4) * 16);
            ldm_x4(ah, smb + aoff);
            ldm_x4(al, smb + 4608 + aoff);
            int l_in = ks * 16 + ((lane >> 3) & 1) * 8 + (lane & 7);
#pragma unroll
            for (int t = 0; t < 3; t++) {
                uint32_t dByte = (uint32_t)((ng * 48 + t * 16) * 2 + ((lane >> 4) & 1) * 16);
                uint32_t boff = (uint32_t)(l_in * 400) + dByte;
                uint32_t bh[4], bl[4];
                ldm_x4t(bh, smb + 9216 + boff);
                ldm_x4t(bl, smb + 34816 + boff);
                mma16816(acc[2*t],   ah, bh);
                mma16816(acc[2*t],   ah, bl);
                mma16816(acc[2*t],   al, bh);
                mma16816(acc[2*t+1], ah, bh + 2);
                mma16816(acc[2*t+1], ah, bl + 2);
                mma16816(acc[2*t+1], al, bh + 2);
            }
        }
    }

    float* dst = opart + ((size_t)(chunk * NB + n)) * HEADS * HDIM;
#pragma unroll
    for (int t6 = 0; t6 < 6; t6++) {
        int d = ng * 48 + t6 * 8 + (lane & 3) * 2;
        int h = mt * 16 + (lane >> 2);
        dst[(size_t)h * HDIM + d]           = acc[t6][0];
        dst[(size_t)h * HDIM + d + 1]       = acc[t6][1];
        dst[(size_t)(h + 8) * HDIM + d]     = acc[t6][2];
        dst[(size_t)(h + 8) * HDIM + d + 1] = acc[t6][3];
    }
}

/* reduce 8 o-partials -> bf16 hi/lo pairs */
__global__ void k_reduce_o(const float* __restrict__ opart,
                           __nv_bfloat16* __restrict__ ohi,
                           __nv_bfloat16* __restrict__ olo)
{
    int p = blockIdx.x*256 + threadIdx.x;
    int e0 = 2 * p;
    float v0 = 0.f, v1 = 0.f;
#pragma unroll
    for (int c = 0; c < 8; c++) {
        v0 += opart[(size_t)c*NB*QDIM + e0];
        v1 += opart[(size_t)c*NB*QDIM + e0 + 1];
    }
    uint32_t hp, lp;
    split2(v0, v1, hp, lp);
    ((uint32_t*)ohi)[p] = hp;
    ((uint32_t*)olo)[p] = lp;
}

/* ------------------------------------------------------------------ */
/* host launcher (stream fork/join during graph capture)              */
/* ------------------------------------------------------------------ */
extern "C" void kernel_launch(void* const* d_in, const int* in_sizes, int n_in,
                              void* d_out, int out_size)
{
    const float* x    = (const float*)d_in[0];
    const float* kvc  = (const float*)d_in[1];
    const int*   bt   = (const int*)  d_in[2];
    const int*   ctxl = (const int*)  d_in[3];
    const float* wqa  = (const float*)d_in[5];
    const float* qnw  = (const float*)d_in[6];
    const float* wqb  = (const float*)d_in[7];
    const float* wkv  = (const float*)d_in[8];
    const float* kvnw = (const float*)d_in[9];
    const float* woa  = (const float*)d_in[10];
    const float* wob  = (const float*)d_in[11];
    const float* sink = (const float*)d_in[12];
    float* out = (float*)d_out;

    float *kv, *lg, *tau, *mr, *iv, *op, *part;
    __nv_bfloat16 *xhi, *xlo, *qahi, *qalo, *qhi, *qlo, *oohi, *oolo, *lathi, *latlo;
    cudaGetSymbolAddress((void**)&xhi,  g_xhi);
    cudaGetSymbolAddress((void**)&xlo,  g_xlo);
    cudaGetSymbolAddress((void**)&qahi, g_qahi);
    cudaGetSymbolAddress((void**)&qalo, g_qalo);
    cudaGetSymbolAddress((void**)&kv,   g_kv);
    cudaGetSymbolAddress((void**)&qhi,  g_qhi);
    cudaGetSymbolAddress((void**)&qlo,  g_qlo);
    cudaGetSymbolAddress((void**)&lg,   g_logits);
    cudaGetSymbolAddress((void**)&tau,  g_tau);
    cudaGetSymbolAddress((void**)&mr,   g_mrow);
    cudaGetSymbolAddress((void**)&iv,   g_invden);
    cudaGetSymbolAddress((void**)&op,   g_opart);
    cudaGetSymbolAddress((void**)&oohi, g_oohi);
    cudaGetSymbolAddress((void**)&oolo, g_oolo);
    cudaGetSymbolAddress((void**)&lathi,g_lathi);
    cudaGetSymbolAddress((void**)&latlo,g_latlo);
    cudaGetSymbolAddress((void**)&part, g_part);

    static cudaStream_t s1 = 0;
    static cudaEvent_t  e0 = 0, e1 = 0;
    if (!s1) {
        cudaStreamCreateWithFlags(&s1, cudaStreamNonBlocking);
        cudaEventCreateWithFlags(&e0, cudaEventDisableTiming);
        cudaEventCreateWithFlags(&e1, cudaEventDisableTiming);
        cudaFuncSetAttribute(k_gemm_mma,   cudaFuncAttributeMaxDynamicSharedMemorySize, MM_SMEM);
        cudaFuncSetAttribute(k_logits_mma, cudaFuncAttributeMaxDynamicSharedMemorySize, LG_SMEM);
        cudaFuncSetAttribute(k_accum_mma,  cudaFuncAttributeMaxDynamicSharedMemorySize, AC_SMEM);
        /* carveout tuned: enough shared for 2 CTAs, keep L1 */
        cudaFuncSetAttribute(k_gemm_mma,   cudaFuncAttributePreferredSharedMemoryCarveout, 50);
        cudaFuncSetAttribute(k_logits_mma, cudaFuncAttributePreferredSharedMemoryCarveout, 70);
        cudaFuncSetAttribute(k_accum_mma,  cudaFuncAttributePreferredSharedMemoryCarveout, 55);
    }

    /* ---- x -> bf16 hi/lo ---- */
    k_x2bf<<<NB*DIMX/512, 256>>>(x, xhi, xlo);
    cudaEventRecord(e0, 0);
    cudaStreamWaitEvent(s1, e0, 0);

    /* ---- branch A (stream 0): wq_a -> rms -> wq_b -> rope/split ---- */
    k_gemm_mma<<<dim3(12, 16, 1), 256, MM_SMEM>>>(
        xhi, xlo, DIMX, 0, wqa, DIMX, 0,
        part + PART_QA_OFF, QLRK, 0, (long long)NB*QLRK, 256, QLRK);
    k_fuse_qa<<<NB, 256>>>(part + PART_QA_OFF, qnw, qahi, qalo);
    k_gemm_mma<<<dim3(48, 6, 1), 256, MM_SMEM>>>(
        qahi, qalo, QLRK, 0, wqb, QLRK, 0,
        part + PART_QB_OFF, QDIM, 0, (long long)NB*QDIM, 256, QDIM);
    k_fuse_q<<<NB, 256>>>(part + PART_QB_OFF, ctxl, qhi, qlo);

    /* ---- branch B (stream s1): wkv -> rms+rope ---- */
    k_gemm_mma<<<dim3(2, 32, 1), 256, MM_SMEM, s1>>>(
        xhi, xlo, DIMX, 0, wkv, DIMX, 0,
        part + PART_KV_OFF, HDIM, 0, (long long)NB*HDIM, 128, HDIM);
    k_fuse_kv<<<NB, 64, 0, s1>>>(part + PART_KV_OFF, kvnw, ctxl, kv);
    cudaEventRecord(e1, s1);
    cudaStreamWaitEvent(0, e1, 0);

    /* ---- attention ---- */
    k_logits_mma<<<dim3(16, NB), 256, LG_SMEM>>>(kvc, bt, ctxl, qhi, qlo, kv, lg);
    k_select<<<NB*HEADS, 256>>>(lg, sink, ctxl, tau, mr, iv);
    k_accum_mma<<<dim3(8, NB), 256, AC_SMEM>>>(kvc, bt, ctxl, kv, lg, tau, mr, iv, op);
    k_reduce_o<<<NB*QDIM/512, 256>>>(op, oohi, oolo);

    /* ---- lat = grouped wo_a : split 12 (sequential; reuse offset 0) ---- */
    k_gemm_mma<<<dim3(4, 12, GRP), 256, MM_SMEM>>>(
        oohi, oolo, QDIM, 768, woa, 768, (long long)OLRK*768,
        part, GRP*OLRK, OLRK, (long long)NB*GRP*OLRK, 64, OLRK);
    k_reduce_bf<<<(NB*GRP*OLRK/2+255)/256, 256>>>(part, lathi, latlo,
                                                  NB*GRP*OLRK/2, NB*GRP*OLRK, 12);

    /* ---- out = lat @ wo_b^T : split 16 ---- */
    k_gemm_mma<<<dim3(32, 16, 1), 256, MM_SMEM>>>(
        lathi, latlo, GRP*OLRK, 0, wob, DIMX, 0,
        part, DIMX, 0, (long long)NB*DIMX, 256, DIMX);
    k_reduce<<<(NB*DIMX+255)/256, 256>>>(part, out, NB*DIMX, 16);
}